// round 1
// baseline (speedup 1.0000x reference)
#include <cuda_runtime.h>

#define NB 4
#define CIN 64
#define HH 128
#define WW 128
#define COUT 128
#define NTAP 10            // 9 deform taps + 1 center-correction tap
#define KDIM (CIN * NTAP)  // 640
#define NOFF 18

// ---- scratch (no allocations allowed) ----
__device__ float g_x_nhwc[NB * HH * WW * CIN];        // 16.8 MB
__device__ float g_toff[NB * NOFF * HH * WW];         // 4.7 MB, NCHW
__device__ float g_At[KDIM * COUT];                   // A^T: [k][o], 327 KB
__device__ float g_wmod[NOFF * CIN * 9];              // folded offset-conv weights

// ============================================================
// Precompute folded weights: w_mod (center-tap fold) and A^T
// ============================================================
__global__ void prep_kernel(const float* __restrict__ w_off,
                            const float* __restrict__ w_deform,
                            const float* __restrict__ w_pw) {
    int tid = blockIdx.x * blockDim.x + threadIdx.x;

    // w_mod[o][c][t] = w_off[o][c][t] - (t==4) * sum_t w_off[o][c][t]
    if (tid < NOFF * CIN * 9) {
        int t = tid % 9;
        int c = (tid / 9) % CIN;
        int o = tid / (9 * CIN);
        const float* wp = w_off + (o * CIN + c) * 9;
        float s = 0.f;
        #pragma unroll
        for (int tt = 0; tt < 9; ++tt) s += wp[tt];
        float v = wp[t];
        if (t == 4) v -= s;
        g_wmod[(o * CIN + c) * 9 + t] = v;
    }

    // A^T[k][o], k = c*10 + p.
    // p<9 : sum_d w_pw[o, 4c+d] * w_deform[(4c+d)*9 + p]
    // p==9: -sum_d w_pw[o, 4c+d] * sum_p w_deform[(4c+d)*9 + p]   (center correction)
    for (int i = tid; i < KDIM * COUT; i += gridDim.x * blockDim.x) {
        int o = i % COUT;
        int k = i / COUT;
        int p = k % NTAP;
        int c = k / NTAP;
        float acc = 0.f;
        if (p < 9) {
            #pragma unroll
            for (int d = 0; d < 4; ++d)
                acc += w_pw[o * 256 + c * 4 + d] * w_deform[(c * 4 + d) * 9 + p];
        } else {
            #pragma unroll
            for (int d = 0; d < 4; ++d) {
                float ws = 0.f;
                #pragma unroll
                for (int pp = 0; pp < 9; ++pp) ws += w_deform[(c * 4 + d) * 9 + pp];
                acc -= w_pw[o * 256 + c * 4 + d] * ws;
            }
        }
        g_At[k * COUT + o] = acc;
    }
}

// ============================================================
// NCHW -> NHWC transpose of x (tiled through smem)
// ============================================================
__global__ void transpose_kernel(const float* __restrict__ x) {
    __shared__ float tile[CIN][33];
    int b = blockIdx.x;                 // 2048 blocks: n * 128h * 4wt
    int wt = b & 3;
    int h  = (b >> 2) & 127;
    int n  = b >> 9;
    int w0 = wt * 32;

    for (int i = threadIdx.x; i < CIN * 32; i += 256) {
        int c = i >> 5, w = i & 31;
        tile[c][w] = x[((n * CIN + c) * HH + h) * WW + w0 + w];
    }
    __syncthreads();
    for (int i = threadIdx.x; i < CIN * 32; i += 256) {
        int w = i >> 6, c = i & 63;
        g_x_nhwc[((n * HH + h) * WW + w0 + w) * CIN + c] = tile[c][w];
    }
}

// ============================================================
// Offset conv: t = conv3x3(x, w_mod) + b_off  (center fold already applied)
// one thread per pixel, 18 accumulators
// ============================================================
__global__ void off_conv_kernel(const float* __restrict__ x,
                                const float* __restrict__ b_off) {
    __shared__ float sw[NOFF * CIN * 9];   // 41472 B
    for (int i = threadIdx.x; i < NOFF * CIN * 9; i += 256)
        sw[i] = g_wmod[i];
    __syncthreads();

    int pid = blockIdx.x * 256 + threadIdx.x;   // 65536 pixels
    int w = pid & 127;
    int h = (pid >> 7) & 127;
    int n = pid >> 14;

    float acc[NOFF];
    #pragma unroll
    for (int o = 0; o < NOFF; ++o) acc[o] = __ldg(&b_off[o]);

    for (int c = 0; c < CIN; ++c) {
        const float* xc = x + ((n * CIN + c) * HH) * WW;
        float v[9];
        #pragma unroll
        for (int ky = 0; ky < 3; ++ky) {
            #pragma unroll
            for (int kx = 0; kx < 3; ++kx) {
                int yy = h - 1 + ky, xx = w - 1 + kx;
                bool ok = (unsigned)yy < (unsigned)HH && (unsigned)xx < (unsigned)WW;
                v[ky * 3 + kx] = ok ? xc[yy * WW + xx] : 0.f;
            }
        }
        #pragma unroll
        for (int o = 0; o < NOFF; ++o) {
            #pragma unroll
            for (int t = 0; t < 9; ++t)
                acc[o] += v[t] * sw[(o * CIN + c) * 9 + t];
        }
    }
    #pragma unroll
    for (int o = 0; o < NOFF; ++o)
        g_toff[((n * NOFF + o) * HH + h) * WW + w] = acc[o];
}

// ============================================================
// Fused deform-sample + GEMM.
// Block = 256 threads, 32 consecutive pixels of one row.
//   Phase 1: bilinear params (288), gather samp[32][640] into smem.
//   Phase 2: out[128, 32] = A^T(640x128)^T @ samp, register-tiled 4o x 4pix.
// ============================================================
#define SMEM_BYTES ((32 * 640 + 288 * 4) * 4)

__global__ void __launch_bounds__(256, 2) fused_kernel(float* __restrict__ out) {
    extern __shared__ float sm[];
    float* samp = sm;                     // [32][640]
    float* pfy  = sm + 32 * 640;          // 288
    float* pfx  = pfy + 288;              // 288
    int*   py0  = (int*)(pfx + 288);      // 288
    int*   px0  = py0 + 288;              // 288

    int b  = blockIdx.x;                  // 2048 blocks
    int wt = b & 3;
    int h  = (b >> 2) & 127;
    int n  = b >> 9;
    int w0 = wt * 32;
    int tid = threadIdx.x;

    // ---- Phase 1a: bilinear parameters per (tap, pixel) ----
    for (int i = tid; i < 9 * 32; i += 256) {
        int p = i >> 5;
        int pix = i & 31;
        int w = w0 + pix;
        float dy = g_toff[((n * NOFF + 2 * p    ) * HH + h) * WW + w];
        float dx = g_toff[((n * NOFF + 2 * p + 1) * HH + h) * WW + w];
        float py = dy + (float)(h - 1 + p / 3);
        float px = dx + (float)(w - 1 + p % 3);
        float y0 = floorf(py), x0 = floorf(px);
        pfy[i] = py - y0;
        pfx[i] = px - x0;
        py0[i] = (int)y0;
        px0[i] = (int)x0;
    }
    __syncthreads();

    // ---- Phase 1b: gather samp; k = c*10 + p (p==9 is center tap) ----
    const float* xb = g_x_nhwc + (size_t)n * (HH * WW * CIN);
    for (int e = tid; e < 32 * NTAP * CIN; e += 256) {
        int c   = e & 63;
        int rem = e >> 6;
        int p   = rem % NTAP;
        int pix = rem / NTAP;
        float val;
        if (p == 9) {
            val = xb[(h * WW + (w0 + pix)) * CIN + c];
        } else {
            int i = p * 32 + pix;
            int y0 = py0[i], x0 = px0[i];
            float fy = pfy[i], fx = pfx[i];
            int y1 = y0 + 1, x1 = x0 + 1;
            bool vy0 = (unsigned)y0 < (unsigned)HH;
            bool vy1 = (unsigned)y1 < (unsigned)HH;
            bool vx0 = (unsigned)x0 < (unsigned)WW;
            bool vx1 = (unsigned)x1 < (unsigned)WW;
            float v00 = (vy0 && vx0) ? xb[(y0 * WW + x0) * CIN + c] : 0.f;
            float v01 = (vy0 && vx1) ? xb[(y0 * WW + x1) * CIN + c] : 0.f;
            float v10 = (vy1 && vx0) ? xb[(y1 * WW + x0) * CIN + c] : 0.f;
            float v11 = (vy1 && vx1) ? xb[(y1 * WW + x1) * CIN + c] : 0.f;
            val = v00 * (1.f - fy) * (1.f - fx) + v01 * (1.f - fy) * fx
                + v10 * fy * (1.f - fx)         + v11 * fy * fx;
        }
        samp[pix * 640 + c * NTAP + p] = val;
    }
    __syncthreads();

    // ---- Phase 2: GEMM. thread -> outputs [4*oq, 4*oq+3], pixels [4*pq, 4*pq+3]
    int oq = tid & 31;
    int pq = tid >> 5;
    float acc[4][4];
    #pragma unroll
    for (int i = 0; i < 4; ++i)
        #pragma unroll
        for (int j = 0; j < 4; ++j) acc[i][j] = 0.f;

    const float4* A4 = (const float4*)g_At;   // [k][32 x float4]
    const float* s0p = samp + (pq * 4 + 0) * 640;
    const float* s1p = samp + (pq * 4 + 1) * 640;
    const float* s2p = samp + (pq * 4 + 2) * 640;
    const float* s3p = samp + (pq * 4 + 3) * 640;

    #pragma unroll 8
    for (int k = 0; k < 640; ++k) {
        float4 a = __ldg(&A4[k * 32 + oq]);
        float s0 = s0p[k], s1 = s1p[k], s2 = s2p[k], s3 = s3p[k];
        acc[0][0] += a.x * s0; acc[0][1] += a.y * s0; acc[0][2] += a.z * s0; acc[0][3] += a.w * s0;
        acc[1][0] += a.x * s1; acc[1][1] += a.y * s1; acc[1][2] += a.z * s1; acc[1][3] += a.w * s1;
        acc[2][0] += a.x * s2; acc[2][1] += a.y * s2; acc[2][2] += a.z * s2; acc[2][3] += a.w * s2;
        acc[3][0] += a.x * s3; acc[3][1] += a.y * s3; acc[3][2] += a.z * s3; acc[3][3] += a.w * s3;
    }

    // ---- write out: NCHW, float4 over 4 consecutive w per output row ----
    #pragma unroll
    for (int j = 0; j < 4; ++j) {
        int o = oq * 4 + j;
        float4 v = make_float4(acc[0][j], acc[1][j], acc[2][j], acc[3][j]);
        *(float4*)&out[((size_t)(n * COUT + o) * HH + h) * WW + w0 + pq * 4] = v;
    }
}

// ============================================================
extern "C" void kernel_launch(void* const* d_in, const int* in_sizes, int n_in,
                              void* d_out, int out_size) {
    const float* x        = (const float*)d_in[0];
    const float* w_off    = (const float*)d_in[1];
    const float* b_off    = (const float*)d_in[2];
    const float* w_deform = (const float*)d_in[3];
    const float* w_pw     = (const float*)d_in[4];
    float* out = (float*)d_out;

    cudaFuncSetAttribute(fused_kernel,
                         cudaFuncAttributeMaxDynamicSharedMemorySize, SMEM_BYTES);

    prep_kernel<<<320, 256>>>(w_off, w_deform, w_pw);
    transpose_kernel<<<2048, 256>>>(x);
    off_conv_kernel<<<256, 256>>>(x, b_off);
    fused_kernel<<<2048, 256, SMEM_BYTES>>>(out);
}

// round 3
// speedup vs baseline: 1.9867x; 1.9867x over previous
#include <cuda_runtime.h>
#include <cuda_bf16.h>
#include <cstdint>

#define NB 4
#define CIN 64
#define HH 128
#define WW 128
#define COUT 128
#define NTAP 10            // 9 deform taps + 1 center-correction tap
#define NOFF 18

// ---- scratch (no allocations allowed) ----
__device__ float g_x_nhwc[NB * HH * WW * CIN];          // 16.8 MB
__device__ float g_toff[NB * NOFF * HH * WW];           // 4.7 MB, NCHW
__device__ __nv_bfloat16 g_A[NTAP * 2 * COUT * 64];     // [tap][hi/lo][o][c] unswizzled
__device__ float g_wmod[NOFF * CIN * 9];                // folded offset-conv weights

// ============================================================
// warp mma helper: m16n8k16 bf16 -> f32
// ============================================================
__device__ __forceinline__ void mma_bf16(float* c, const uint32_t* a, const uint32_t* b) {
    asm volatile(
        "mma.sync.aligned.m16n8k16.row.col.f32.bf16.bf16.f32 "
        "{%0,%1,%2,%3}, {%4,%5,%6,%7}, {%8,%9}, {%0,%1,%2,%3};"
        : "+f"(c[0]), "+f"(c[1]), "+f"(c[2]), "+f"(c[3])
        : "r"(a[0]), "r"(a[1]), "r"(a[2]), "r"(a[3]), "r"(b[0]), "r"(b[1]));
}

// ============================================================
// Precompute: w_mod fold + A split (bf16 hi/lo), k = tap*64 + c
// ============================================================
__global__ void prep_kernel(const float* __restrict__ w_off,
                            const float* __restrict__ w_deform,
                            const float* __restrict__ w_pw) {
    int tid = blockIdx.x * blockDim.x + threadIdx.x;

    if (tid < NOFF * CIN * 9) {
        int t = tid % 9;
        int c = (tid / 9) % CIN;
        int o = tid / (9 * CIN);
        const float* wp = w_off + (o * CIN + c) * 9;
        float s = 0.f;
        #pragma unroll
        for (int tt = 0; tt < 9; ++tt) s += wp[tt];
        float v = wp[t];
        if (t == 4) v -= s;
        g_wmod[(o * CIN + c) * 9 + t] = v;
    }

    for (int i = tid; i < NTAP * CIN * COUT; i += gridDim.x * blockDim.x) {
        int o = i & 127;
        int k = i >> 7;
        int p = k >> 6;     // tap 0..9
        int c = k & 63;
        float acc = 0.f;
        if (p < 9) {
            #pragma unroll
            for (int d = 0; d < 4; ++d)
                acc += w_pw[o * 256 + c * 4 + d] * w_deform[(c * 4 + d) * 9 + p];
        } else {
            #pragma unroll
            for (int d = 0; d < 4; ++d) {
                float ws = 0.f;
                #pragma unroll
                for (int pp = 0; pp < 9; ++pp) ws += w_deform[(c * 4 + d) * 9 + pp];
                acc -= w_pw[o * 256 + c * 4 + d] * ws;
            }
        }
        __nv_bfloat16 hi = __float2bfloat16(acc);
        __nv_bfloat16 lo = __float2bfloat16(acc - __bfloat162float(hi));
        g_A[(p * 2 + 0) * 8192 + o * 64 + c] = hi;
        g_A[(p * 2 + 1) * 8192 + o * 64 + c] = lo;
    }
}

// ============================================================
// NCHW -> NHWC transpose of x
// ============================================================
__global__ void transpose_kernel(const float* __restrict__ x) {
    __shared__ float tile[CIN][33];
    int b = blockIdx.x;
    int wt = b & 3;
    int h  = (b >> 2) & 127;
    int n  = b >> 9;
    int w0 = wt * 32;

    for (int i = threadIdx.x; i < CIN * 32; i += 256) {
        int c = i >> 5, w = i & 31;
        tile[c][w] = x[((n * CIN + c) * HH + h) * WW + w0 + w];
    }
    __syncthreads();
    for (int i = threadIdx.x; i < CIN * 32; i += 256) {
        int w = i >> 6, c = i & 63;
        g_x_nhwc[((n * HH + h) * WW + w0 + w) * CIN + c] = tile[c][w];
    }
}

// ============================================================
// Offset conv: t = conv3x3(x, w_mod) + b_off
// ============================================================
__global__ void off_conv_kernel(const float* __restrict__ x,
                                const float* __restrict__ b_off) {
    __shared__ float sw[NOFF * CIN * 9];
    for (int i = threadIdx.x; i < NOFF * CIN * 9; i += 256)
        sw[i] = g_wmod[i];
    __syncthreads();

    int pid = blockIdx.x * 256 + threadIdx.x;
    int w = pid & 127;
    int h = (pid >> 7) & 127;
    int n = pid >> 14;

    float acc[NOFF];
    #pragma unroll
    for (int o = 0; o < NOFF; ++o) acc[o] = __ldg(&b_off[o]);

    for (int c = 0; c < CIN; ++c) {
        const float* xc = x + ((n * CIN + c) * HH) * WW;
        float v[9];
        #pragma unroll
        for (int ky = 0; ky < 3; ++ky) {
            #pragma unroll
            for (int kx = 0; kx < 3; ++kx) {
                int yy = h - 1 + ky, xx = w - 1 + kx;
                bool ok = (unsigned)yy < (unsigned)HH && (unsigned)xx < (unsigned)WW;
                v[ky * 3 + kx] = ok ? xc[yy * WW + xx] : 0.f;
            }
        }
        #pragma unroll
        for (int o = 0; o < NOFF; ++o) {
            #pragma unroll
            for (int t = 0; t < 9; ++t)
                acc[o] += v[t] * sw[(o * CIN + c) * 9 + t];
        }
    }
    #pragma unroll
    for (int o = 0; o < NOFF; ++o)
        g_toff[((n * NOFF + o) * HH + h) * WW + w] = acc[o];
}

// ============================================================
// Fused deform-sample + mma.sync bf16x3 GEMM.
// Block = one image row (n,h): M=128 outs, N=128 pixels, K=640 (tap-tiled 64).
// 16 warps, each computes a 32(m) x 32(n) output tile.
// Smem tiles padded to 72 bf16/row -> conflict-free LDS.32 fragment loads.
// ============================================================
#define PADK 72
#define SM_PAR 0                       // 8 * 1152 * 4 = 36864 B
#define SM_A 36864                     // 2 planes * 128 * 72 * 2B = 36864 B
#define SM_B (36864 + 36864)           // same
#define SM_TOTAL (SM_B + 36864)        // 110592 B

__global__ void __launch_bounds__(512, 1) fused_mma(float* __restrict__ out) {
    extern __shared__ char sm[];
    float* sW = (float*)(sm + SM_PAR);
    int*   sO = (int*)(sm + SM_PAR + 4 * 1152 * 4);
    __nv_bfloat16* As = (__nv_bfloat16*)(sm + SM_A);   // [plane][128][72]
    __nv_bfloat16* Bs = (__nv_bfloat16*)(sm + SM_B);   // [plane][128][72]

    int tid = threadIdx.x, wid = tid >> 5, lid = tid & 31;
    int n = blockIdx.x >> 7, h = blockIdx.x & 127;
    int g = lid >> 2, tq = lid & 3;
    int m0 = (wid & 3) * 32;
    int n0 = (wid >> 2) * 32;

    // ---- bilinear params per (tap, pixel) ----
    for (int i = tid; i < 9 * 128; i += 512) {
        int p = i >> 7, pix = i & 127;
        float dy = g_toff[((n * NOFF + 2 * p    ) * HH + h) * WW + pix];
        float dx = g_toff[((n * NOFF + 2 * p + 1) * HH + h) * WW + pix];
        float py = dy + (float)(h - 1 + p / 3);
        float px = dx + (float)(pix - 1 + p % 3);
        float y0f = floorf(py), x0f = floorf(px);
        int y0 = (int)y0f, x0 = (int)x0f;
        float wy1 = py - y0f, wx1 = px - x0f;
        float wy0 = 1.f - wy1, wx0 = 1.f - wx1;
        bool vy0 = (unsigned)y0 < (unsigned)HH, vy1 = (unsigned)(y0 + 1) < (unsigned)HH;
        bool vx0 = (unsigned)x0 < (unsigned)WW, vx1 = (unsigned)(x0 + 1) < (unsigned)WW;
        int cy0 = min(max(y0, 0), HH - 1), cy1 = min(max(y0 + 1, 0), HH - 1);
        int cx0 = min(max(x0, 0), WW - 1), cx1 = min(max(x0 + 1, 0), WW - 1);
        sW[0 * 1152 + i] = (vy0 && vx0) ? wy0 * wx0 : 0.f;
        sW[1 * 1152 + i] = (vy0 && vx1) ? wy0 * wx1 : 0.f;
        sW[2 * 1152 + i] = (vy1 && vx0) ? wy1 * wx0 : 0.f;
        sW[3 * 1152 + i] = (vy1 && vx1) ? wy1 * wx1 : 0.f;
        sO[0 * 1152 + i] = (cy0 * WW + cx0) * CIN;
        sO[1 * 1152 + i] = (cy0 * WW + cx1) * CIN;
        sO[2 * 1152 + i] = (cy1 * WW + cx0) * CIN;
        sO[3 * 1152 + i] = (cy1 * WW + cx1) * CIN;
    }
    __syncthreads();

    const float* xb = g_x_nhwc + (size_t)n * (HH * WW * CIN);

    float acc[2][4][4];
    #pragma unroll
    for (int mi = 0; mi < 2; ++mi)
        #pragma unroll
        for (int nj = 0; nj < 4; ++nj)
            #pragma unroll
            for (int r = 0; r < 4; ++r) acc[mi][nj][r] = 0.f;

    for (int t = 0; t < NTAP; ++t) {
        // ---- stage A tile (hi+lo) with row padding ----
        {
            const uint4* asrc = (const uint4*)g_A + t * 2048;
            #pragma unroll
            for (int i = tid; i < 2048; i += 512) {
                int plane = i >> 10, row = (i >> 3) & 127, seg = i & 7;
                *(uint4*)&As[plane * 9216 + row * PADK + seg * 8] = asrc[i];
            }
        }
        // ---- gather B tile + bf16 hi/lo split ----
        for (int e = tid; e < 2048; e += 512) {
            int pix = e >> 4;
            int c0 = (e & 15) * 4;
            float4 v;
            if (t == 9) {
                v = *(const float4*)&xb[(h * WW + pix) * CIN + c0];
            } else {
                int i = t * 128 + pix;
                float w00 = sW[i], w01 = sW[1152 + i], w10 = sW[2 * 1152 + i], w11 = sW[3 * 1152 + i];
                float4 v00 = *(const float4*)&xb[sO[i] + c0];
                float4 v01 = *(const float4*)&xb[sO[1152 + i] + c0];
                float4 v10 = *(const float4*)&xb[sO[2 * 1152 + i] + c0];
                float4 v11 = *(const float4*)&xb[sO[3 * 1152 + i] + c0];
                v.x = w00 * v00.x + w01 * v01.x + w10 * v10.x + w11 * v11.x;
                v.y = w00 * v00.y + w01 * v01.y + w10 * v10.y + w11 * v11.y;
                v.z = w00 * v00.z + w01 * v01.z + w10 * v10.z + w11 * v11.z;
                v.w = w00 * v00.w + w01 * v01.w + w10 * v10.w + w11 * v11.w;
            }
            __nv_bfloat16 b0 = __float2bfloat16(v.x);
            __nv_bfloat16 b1 = __float2bfloat16(v.y);
            __nv_bfloat16 b2 = __float2bfloat16(v.z);
            __nv_bfloat16 b3 = __float2bfloat16(v.w);
            __nv_bfloat162 hA = __halves2bfloat162(b0, b1);
            __nv_bfloat162 hB = __halves2bfloat162(b2, b3);
            __nv_bfloat162 lA = __halves2bfloat162(
                __float2bfloat16(v.x - __bfloat162float(b0)),
                __float2bfloat16(v.y - __bfloat162float(b1)));
            __nv_bfloat162 lB = __halves2bfloat162(
                __float2bfloat16(v.z - __bfloat162float(b2)),
                __float2bfloat16(v.w - __bfloat162float(b3)));
            *(uint2*)&Bs[pix * PADK + c0]        = make_uint2(*(uint32_t*)&hA, *(uint32_t*)&hB);
            *(uint2*)&Bs[9216 + pix * PADK + c0] = make_uint2(*(uint32_t*)&lA, *(uint32_t*)&lB);
        }
        __syncthreads();

        // ---- mma over this tap's K=64 window, 3 split passes ----
        #pragma unroll
        for (int ks = 0; ks < 4; ++ks) {
            int k0 = ks * 16;
            uint32_t a[2][2][4];   // [plane][mi][reg]
            uint32_t b[2][4][2];   // [plane][nj][reg]
            #pragma unroll
            for (int pl = 0; pl < 2; ++pl) {
                #pragma unroll
                for (int mi = 0; mi < 2; ++mi) {
                    const __nv_bfloat16* ap = As + pl * 9216 + (m0 + mi * 16 + g) * PADK + k0 + 2 * tq;
                    a[pl][mi][0] = *(const uint32_t*)(ap);
                    a[pl][mi][1] = *(const uint32_t*)(ap + 8 * PADK);
                    a[pl][mi][2] = *(const uint32_t*)(ap + 8);
                    a[pl][mi][3] = *(const uint32_t*)(ap + 8 * PADK + 8);
                }
                #pragma unroll
                for (int nj = 0; nj < 4; ++nj) {
                    const __nv_bfloat16* bp = Bs + pl * 9216 + (n0 + nj * 8 + g) * PADK + k0 + 2 * tq;
                    b[pl][nj][0] = *(const uint32_t*)(bp);
                    b[pl][nj][1] = *(const uint32_t*)(bp + 8);
                }
            }
            #pragma unroll
            for (int mi = 0; mi < 2; ++mi)
                #pragma unroll
                for (int nj = 0; nj < 4; ++nj) {
                    mma_bf16(acc[mi][nj], a[0][mi], b[0][nj]);  // hi*hi
                    mma_bf16(acc[mi][nj], a[0][mi], b[1][nj]);  // hi*lo
                    mma_bf16(acc[mi][nj], a[1][mi], b[0][nj]);  // lo*hi
                }
        }
        __syncthreads();
    }

    // ---- epilogue: direct stores, NCHW ----
    #pragma unroll
    for (int mi = 0; mi < 2; ++mi) {
        #pragma unroll
        for (int nj = 0; nj < 4; ++nj) {
            int o = m0 + mi * 16 + g;
            int pix = n0 + nj * 8 + 2 * tq;
            float* op = out + (((size_t)n * COUT + o) * HH + h) * WW + pix;
            *(float2*)op = make_float2(acc[mi][nj][0], acc[mi][nj][1]);
            *(float2*)(op + 8 * HH * WW) = make_float2(acc[mi][nj][2], acc[mi][nj][3]);
        }
    }
}

// ============================================================
extern "C" void kernel_launch(void* const* d_in, const int* in_sizes, int n_in,
                              void* d_out, int out_size) {
    const float* x        = (const float*)d_in[0];
    const float* w_off    = (const float*)d_in[1];
    const float* b_off    = (const float*)d_in[2];
    const float* w_deform = (const float*)d_in[3];
    const float* w_pw     = (const float*)d_in[4];
    float* out = (float*)d_out;

    cudaFuncSetAttribute(fused_mma,
                         cudaFuncAttributeMaxDynamicSharedMemorySize, SM_TOTAL);

    prep_kernel<<<320, 256>>>(w_off, w_deform, w_pw);
    transpose_kernel<<<2048, 256>>>(x);
    off_conv_kernel<<<256, 256>>>(x, b_off);
    fused_mma<<<NB * HH, 512, SM_TOTAL>>>(out);
}

// round 6
// speedup vs baseline: 2.5709x; 1.2940x over previous
#include <cuda_runtime.h>
#include <cuda_bf16.h>
#include <cstdint>

#define NB 4
#define CIN 64
#define HH 128
#define WW 128
#define COUT 128
#define NTAP 10            // 9 deform taps + 1 center-correction tap
#define NOFF 18

// ---- scratch (no allocations allowed) ----
__device__ float g_x_nhwc[NB * HH * WW * CIN];          // 16.8 MB
__device__ float g_toff[NB * NOFF * HH * WW];           // 4.7 MB, NCHW
__device__ __nv_bfloat16 g_A[NTAP * 2 * COUT * 64];     // fused GEMM A: [tap][hi/lo][o][c]
__device__ __nv_bfloat16 g_Aoff[2 * 32 * 576];          // offset-conv A: [hi/lo][o(32)][k=t*64+c]

// ============================================================
// helpers
// ============================================================
__device__ __forceinline__ void mma_bf16(float* c, const uint32_t* a, const uint32_t* b) {
    asm volatile(
        "mma.sync.aligned.m16n8k16.row.col.f32.bf16.bf16.f32 "
        "{%0,%1,%2,%3}, {%4,%5,%6,%7}, {%8,%9}, {%0,%1,%2,%3};"
        : "+f"(c[0]), "+f"(c[1]), "+f"(c[2]), "+f"(c[3])
        : "r"(a[0]), "r"(a[1]), "r"(a[2]), "r"(a[3]), "r"(b[0]), "r"(b[1]));
}
__device__ __forceinline__ uint32_t smem_u32(const void* p) {
    uint32_t a;
    asm("{ .reg .u64 t; cvta.to.shared.u64 t, %1; cvt.u32.u64 %0, t; }" : "=r"(a) : "l"(p));
    return a;
}
__device__ __forceinline__ void cp_async16(uint32_t dst, const void* src) {
    asm volatile("cp.async.cg.shared.global [%0], [%1], 16;" :: "r"(dst), "l"(src) : "memory");
}
__device__ __forceinline__ void cp_commit() {
    asm volatile("cp.async.commit_group;" ::: "memory");
}
__device__ __forceinline__ void cp_wait0() {
    asm volatile("cp.async.wait_group 0;" ::: "memory");
}
__device__ __forceinline__ void split_store(__nv_bfloat16* hi_p, __nv_bfloat16* lo_p, float4 v) {
    __nv_bfloat16 b0 = __float2bfloat16(v.x);
    __nv_bfloat16 b1 = __float2bfloat16(v.y);
    __nv_bfloat16 b2 = __float2bfloat16(v.z);
    __nv_bfloat16 b3 = __float2bfloat16(v.w);
    __nv_bfloat162 hA = __halves2bfloat162(b0, b1);
    __nv_bfloat162 hB = __halves2bfloat162(b2, b3);
    __nv_bfloat162 lA = __halves2bfloat162(
        __float2bfloat16(v.x - __bfloat162float(b0)),
        __float2bfloat16(v.y - __bfloat162float(b1)));
    __nv_bfloat162 lB = __halves2bfloat162(
        __float2bfloat16(v.z - __bfloat162float(b2)),
        __float2bfloat16(v.w - __bfloat162float(b3)));
    *(uint2*)hi_p = make_uint2(*(uint32_t*)&hA, *(uint32_t*)&hB);
    *(uint2*)lo_p = make_uint2(*(uint32_t*)&lA, *(uint32_t*)&lB);
}

// ============================================================
// Precompute: A tiles for both GEMMs (bf16 hi/lo split)
// ============================================================
__global__ void prep_kernel(const float* __restrict__ w_off,
                            const float* __restrict__ w_deform,
                            const float* __restrict__ w_pw) {
    int tid = blockIdx.x * blockDim.x + threadIdx.x;
    int stride = gridDim.x * blockDim.x;

    // fused-GEMM A: [tap p][pl][o][c], k = p*64 + c
    for (int i = tid; i < NTAP * CIN * COUT; i += stride) {
        int o = i & 127;
        int k = i >> 7;
        int p = k >> 6;
        int c = k & 63;
        float acc = 0.f;
        if (p < 9) {
            #pragma unroll
            for (int d = 0; d < 4; ++d)
                acc += w_pw[o * 256 + c * 4 + d] * w_deform[(c * 4 + d) * 9 + p];
        } else {
            #pragma unroll
            for (int d = 0; d < 4; ++d) {
                float ws = 0.f;
                #pragma unroll
                for (int pp = 0; pp < 9; ++pp) ws += w_deform[(c * 4 + d) * 9 + pp];
                acc -= w_pw[o * 256 + c * 4 + d] * ws;
            }
        }
        __nv_bfloat16 hi = __float2bfloat16(acc);
        __nv_bfloat16 lo = __float2bfloat16(acc - __bfloat162float(hi));
        g_A[(p * 2 + 0) * 8192 + o * 64 + c] = hi;
        g_A[(p * 2 + 1) * 8192 + o * 64 + c] = lo;
    }

    // offset-conv A: [pl][o 0..31][k = t*64 + c], folded center tap, zero o>=18
    for (int i = tid; i < 32 * 576; i += stride) {
        int k = i % 576;
        int o = i / 576;
        int t = k >> 6;
        int c = k & 63;
        float v = 0.f;
        if (o < NOFF) {
            const float* wp = w_off + (o * CIN + c) * 9;
            v = wp[t];
            if (t == 4) {
                float s = 0.f;
                #pragma unroll
                for (int tt = 0; tt < 9; ++tt) s += wp[tt];
                v -= s;
            }
        }
        __nv_bfloat16 hi = __float2bfloat16(v);
        __nv_bfloat16 lo = __float2bfloat16(v - __bfloat162float(hi));
        g_Aoff[0 * 18432 + o * 576 + k] = hi;
        g_Aoff[1 * 18432 + o * 576 + k] = lo;
    }
}

// ============================================================
// NCHW -> NHWC transpose of x
// ============================================================
__global__ void transpose_kernel(const float* __restrict__ x) {
    __shared__ float tile[CIN][33];
    int b = blockIdx.x;
    int wt = b & 3;
    int h  = (b >> 2) & 127;
    int n  = b >> 9;
    int w0 = wt * 32;

    for (int i = threadIdx.x; i < CIN * 32; i += 256) {
        int c = i >> 5, w = i & 31;
        tile[c][w] = x[((n * CIN + c) * HH + h) * WW + w0 + w];
    }
    __syncthreads();
    for (int i = threadIdx.x; i < CIN * 32; i += 256) {
        int w = i >> 6, c = i & 63;
        g_x_nhwc[((n * HH + h) * WW + w0 + w) * CIN + c] = tile[c][w];
    }
}

// ============================================================
// Offset conv as tensor-core GEMM. Block = (n,h) row.
// M=32 (18 used), N=128 pixels, K=576. Taps are shifted views of 3
// staged x rows (h-1,h,h+1), 130 pixels wide (zero-padded), bf16 hi/lo.
// Writes g_toff DIRECTLY via device symbol (host-passed device-symbol
// pointers are invalid -- that was the R4/R5 bug).
// ============================================================
#define XROW 72           // padded channel pitch (bf16) per pixel
#define XPIX 130
#define XPLANE (3 * XPIX * XROW)          // 28080 els
#define AOP 584           // padded K pitch for A rows
#define APLANE (32 * AOP)                 // 18688 els
#define OFF_SM_X 0
#define OFF_SM_A (2 * XPLANE * 2)         // 112320 B
#define OFF_SM_TOTAL (OFF_SM_A + 2 * APLANE * 2)   // 187072 B

__global__ void __launch_bounds__(512, 1) off_mma(const float* __restrict__ b_off) {
    extern __shared__ char sm[];
    __nv_bfloat16* Xs = (__nv_bfloat16*)(sm + OFF_SM_X);   // [pl][r][pix130][72]
    __nv_bfloat16* Aw = (__nv_bfloat16*)(sm + OFF_SM_A);   // [pl][o32][584]

    int tid = threadIdx.x, wid = tid >> 5, lid = tid & 31;
    int g = lid >> 2, tq = lid & 3;
    int n = blockIdx.x >> 7, h = blockIdx.x & 127;
    int nw = wid * 8;

    // stage A with padding
    for (int j = tid; j < 4608; j += 512) {
        int pl = j / 2304, rem = j % 2304;
        int o = rem / 72, seg = rem % 72;
        *(uint4*)&Aw[pl * APLANE + o * AOP + seg * 8] =
            *(const uint4*)&g_Aoff[pl * 18432 + o * 576 + seg * 8];
    }

    // stage 3 x rows, zero-padded, split hi/lo
    const float* xb = g_x_nhwc + (size_t)n * (HH * WW * CIN);
    for (int e = tid; e < 6240; e += 512) {
        int r = e / 2080, rem = e % 2080;
        int p = rem >> 4, c0 = (rem & 15) * 4;
        int row = h - 1 + r, w = p - 1;
        float4 v = make_float4(0.f, 0.f, 0.f, 0.f);
        if ((unsigned)row < (unsigned)HH && (unsigned)w < (unsigned)WW)
            v = *(const float4*)&xb[(row * WW + w) * CIN + c0];
        int off = r * (XPIX * XROW) + p * XROW + c0;
        split_store(&Xs[off], &Xs[XPLANE + off], v);
    }
    __syncthreads();

    float acc[2][4];
    #pragma unroll
    for (int mi = 0; mi < 2; ++mi)
        #pragma unroll
        for (int r = 0; r < 4; ++r) acc[mi][r] = 0.f;

    #pragma unroll
    for (int t = 0; t < 9; ++t) {
        int ky = t / 3, kx = t % 3;
        #pragma unroll
        for (int ks = 0; ks < 4; ++ks) {
            int k0 = ks * 16;
            uint32_t a[2][2][4], b[2][2];
            #pragma unroll
            for (int pl = 0; pl < 2; ++pl) {
                #pragma unroll
                for (int mi = 0; mi < 2; ++mi) {
                    const __nv_bfloat16* ap =
                        Aw + pl * APLANE + (mi * 16 + g) * AOP + t * 64 + k0 + 2 * tq;
                    a[pl][mi][0] = *(const uint32_t*)(ap);
                    a[pl][mi][1] = *(const uint32_t*)(ap + 8 * AOP);
                    a[pl][mi][2] = *(const uint32_t*)(ap + 8);
                    a[pl][mi][3] = *(const uint32_t*)(ap + 8 * AOP + 8);
                }
                const __nv_bfloat16* bp =
                    Xs + pl * XPLANE + ky * (XPIX * XROW) + (nw + g + kx) * XROW + k0 + 2 * tq;
                b[pl][0] = *(const uint32_t*)(bp);
                b[pl][1] = *(const uint32_t*)(bp + 8);
            }
            #pragma unroll
            for (int mi = 0; mi < 2; ++mi) {
                mma_bf16(acc[mi], a[0][mi], b[0]);
                mma_bf16(acc[mi], a[0][mi], b[1]);
                mma_bf16(acc[mi], a[1][mi], b[0]);
            }
        }
    }

    // store t offsets (+ bias) into g_toff (device symbol), only o < 18
    int pix = nw + 2 * tq;
    #pragma unroll
    for (int mi = 0; mi < 2; ++mi) {
        int oa = mi * 16 + g;
        int ob = oa + 8;
        if (oa < NOFF) {
            float bb = __ldg(&b_off[oa]);
            *(float2*)&g_toff[((n * NOFF + oa) * HH + h) * WW + pix] =
                make_float2(acc[mi][0] + bb, acc[mi][1] + bb);
        }
        if (ob < NOFF) {
            float bb = __ldg(&b_off[ob]);
            *(float2*)&g_toff[((n * NOFF + ob) * HH + h) * WW + pix] =
                make_float2(acc[mi][2] + bb, acc[mi][3] + bb);
        }
    }
}

// ============================================================
// Fused deform-sample + mma.sync bf16x3 GEMM, software-pipelined.
// Block = (n,h): M=128, N=128, K=640. Double-buffered A (cp.async) and B
// (inline gather interleaved with MMA k-steps).
// ============================================================
#define PADK 72
#define TILE_ELS 9216                       // 128*72
#define BUF_ELS (2 * TILE_ELS)              // hi+lo plane
#define SM_PAR 0                            // 36864 B
#define SM_A 36864                          // 2 bufs x 36864 B
#define SM_B (36864 + 73728)
#define SM_TOTAL (SM_B + 73728)             // 184320 B

__global__ void __launch_bounds__(512, 1) fused_mma(float* __restrict__ out) {
    extern __shared__ char sm[];
    float* sW = (float*)(sm + SM_PAR);
    int*   sO = (int*)(sm + SM_PAR + 4 * 1152 * 4);
    __nv_bfloat16* As = (__nv_bfloat16*)(sm + SM_A);
    __nv_bfloat16* Bs = (__nv_bfloat16*)(sm + SM_B);
    uint32_t smbA = smem_u32(sm + SM_A);

    int tid = threadIdx.x, wid = tid >> 5, lid = tid & 31;
    int n = blockIdx.x >> 7, h = blockIdx.x & 127;
    int g = lid >> 2, tq = lid & 3;
    int m0 = (wid & 3) * 32;
    int n0 = (wid >> 2) * 32;

    // ---- bilinear params per (tap, pixel) ----
    for (int i = tid; i < 9 * 128; i += 512) {
        int p = i >> 7, pix = i & 127;
        float dy = g_toff[((n * NOFF + 2 * p    ) * HH + h) * WW + pix];
        float dx = g_toff[((n * NOFF + 2 * p + 1) * HH + h) * WW + pix];
        float py = dy + (float)(h - 1 + p / 3);
        float px = dx + (float)(pix - 1 + p % 3);
        float y0f = floorf(py), x0f = floorf(px);
        int y0 = (int)y0f, x0 = (int)x0f;
        float wy1 = py - y0f, wx1 = px - x0f;
        float wy0 = 1.f - wy1, wx0 = 1.f - wx1;
        bool vy0 = (unsigned)y0 < (unsigned)HH, vy1 = (unsigned)(y0 + 1) < (unsigned)HH;
        bool vx0 = (unsigned)x0 < (unsigned)WW, vx1 = (unsigned)(x0 + 1) < (unsigned)WW;
        int cy0 = min(max(y0, 0), HH - 1), cy1 = min(max(y0 + 1, 0), HH - 1);
        int cx0 = min(max(x0, 0), WW - 1), cx1 = min(max(x0 + 1, 0), WW - 1);
        sW[0 * 1152 + i] = (vy0 && vx0) ? wy0 * wx0 : 0.f;
        sW[1 * 1152 + i] = (vy0 && vx1) ? wy0 * wx1 : 0.f;
        sW[2 * 1152 + i] = (vy1 && vx0) ? wy1 * wx0 : 0.f;
        sW[3 * 1152 + i] = (vy1 && vx1) ? wy1 * wx1 : 0.f;
        sO[0 * 1152 + i] = (cy0 * WW + cx0) * CIN;
        sO[1 * 1152 + i] = (cy0 * WW + cx1) * CIN;
        sO[2 * 1152 + i] = (cy1 * WW + cx0) * CIN;
        sO[3 * 1152 + i] = (cy1 * WW + cx1) * CIN;
    }
    __syncthreads();

    const float* xb = g_x_nhwc + (size_t)n * (HH * WW * CIN);

    // ---- prologue: A(0) via cp.async, B(0) gathered inline ----
    {
        #pragma unroll
        for (int m = 0; m < 4; ++m) {
            int j = tid + 512 * m;
            int plane = j >> 10, row = (j >> 3) & 127, seg = j & 7;
            cp_async16(smbA + (uint32_t)(plane * 18432 + row * 144 + seg * 16),
                       g_A + j * 8);
        }
        cp_commit();
        #pragma unroll
        for (int sub = 0; sub < 4; ++sub) {
            int e = tid + 512 * sub;
            int pix = e >> 4, c0 = (e & 15) * 4;
            int i = pix;   // tap 0
            float w00 = sW[i], w01 = sW[1152 + i], w10 = sW[2 * 1152 + i], w11 = sW[3 * 1152 + i];
            float4 v00 = *(const float4*)&xb[sO[i] + c0];
            float4 v01 = *(const float4*)&xb[sO[1152 + i] + c0];
            float4 v10 = *(const float4*)&xb[sO[2 * 1152 + i] + c0];
            float4 v11 = *(const float4*)&xb[sO[3 * 1152 + i] + c0];
            float4 v;
            v.x = w00 * v00.x + w01 * v01.x + w10 * v10.x + w11 * v11.x;
            v.y = w00 * v00.y + w01 * v01.y + w10 * v10.y + w11 * v11.y;
            v.z = w00 * v00.z + w01 * v01.z + w10 * v10.z + w11 * v11.z;
            v.w = w00 * v00.w + w01 * v01.w + w10 * v10.w + w11 * v11.w;
            int off = pix * PADK + c0;
            split_store(&Bs[off], &Bs[TILE_ELS + off], v);
        }
    }

    float acc[2][4][4];
    #pragma unroll
    for (int mi = 0; mi < 2; ++mi)
        #pragma unroll
        for (int nj = 0; nj < 4; ++nj)
            #pragma unroll
            for (int r = 0; r < 4; ++r) acc[mi][nj][r] = 0.f;

    for (int t = 0; t < NTAP; ++t) {
        cp_wait0();
        __syncthreads();
        bool pf = (t < 9);

        if (pf) {
            const __nv_bfloat16* asrc = g_A + (t + 1) * 16384;
            uint32_t adst = smbA + (uint32_t)(((t + 1) & 1) * 36864);
            #pragma unroll
            for (int m = 0; m < 4; ++m) {
                int j = tid + 512 * m;
                int plane = j >> 10, row = (j >> 3) & 127, seg = j & 7;
                cp_async16(adst + (uint32_t)(plane * 18432 + row * 144 + seg * 16),
                           asrc + j * 8);
            }
            cp_commit();
        }

        const __nv_bfloat16* At = As + (t & 1) * BUF_ELS;
        const __nv_bfloat16* Bt = Bs + (t & 1) * BUF_ELS;
        __nv_bfloat16* Bnx = (__nv_bfloat16*)Bs + ((t + 1) & 1) * BUF_ELS;

        #pragma unroll
        for (int sub = 0; sub < 4; ++sub) {
            // -- issue gather loads for tap t+1, sub-block 'sub' --
            float4 v00, v01, v10, v11;
            float w00, w01, w10, w11;
            int pix = 0, c0 = 0;
            bool center = (t + 1 == 9);
            if (pf) {
                int e = tid + 512 * sub;
                pix = e >> 4; c0 = (e & 15) * 4;
                if (center) {
                    v00 = *(const float4*)&xb[(h * WW + pix) * CIN + c0];
                } else {
                    int i = (t + 1) * 128 + pix;
                    w00 = sW[i]; w01 = sW[1152 + i]; w10 = sW[2 * 1152 + i]; w11 = sW[3 * 1152 + i];
                    v00 = *(const float4*)&xb[sO[i] + c0];
                    v01 = *(const float4*)&xb[sO[1152 + i] + c0];
                    v10 = *(const float4*)&xb[sO[2 * 1152 + i] + c0];
                    v11 = *(const float4*)&xb[sO[3 * 1152 + i] + c0];
                }
            }

            // -- MMA k-step 'sub' of tap t (hides gather latency) --
            {
                int k0 = sub * 16;
                uint32_t a[2][2][4], b[2][4][2];
                #pragma unroll
                for (int pl = 0; pl < 2; ++pl) {
                    #pragma unroll
                    for (int mi = 0; mi < 2; ++mi) {
                        const __nv_bfloat16* ap =
                            At + pl * TILE_ELS + (m0 + mi * 16 + g) * PADK + k0 + 2 * tq;
                        a[pl][mi][0] = *(const uint32_t*)(ap);
                        a[pl][mi][1] = *(const uint32_t*)(ap + 8 * PADK);
                        a[pl][mi][2] = *(const uint32_t*)(ap + 8);
                        a[pl][mi][3] = *(const uint32_t*)(ap + 8 * PADK + 8);
                    }
                    #pragma unroll
                    for (int nj = 0; nj < 4; ++nj) {
                        const __nv_bfloat16* bp =
                            Bt + pl * TILE_ELS + (n0 + nj * 8 + g) * PADK + k0 + 2 * tq;
                        b[pl][nj][0] = *(const uint32_t*)(bp);
                        b[pl][nj][1] = *(const uint32_t*)(bp + 8);
                    }
                }
                #pragma unroll
                for (int mi = 0; mi < 2; ++mi)
                    #pragma unroll
                    for (int nj = 0; nj < 4; ++nj) {
                        mma_bf16(acc[mi][nj], a[0][mi], b[0][nj]);
                        mma_bf16(acc[mi][nj], a[0][mi], b[1][nj]);
                        mma_bf16(acc[mi][nj], a[1][mi], b[0][nj]);
                    }
            }

            // -- finish gather: combine, split, STS into next buffer --
            if (pf) {
                float4 v;
                if (center) {
                    v = v00;
                } else {
                    v.x = w00 * v00.x + w01 * v01.x + w10 * v10.x + w11 * v11.x;
                    v.y = w00 * v00.y + w01 * v01.y + w10 * v10.y + w11 * v11.y;
                    v.z = w00 * v00.z + w01 * v01.z + w10 * v10.z + w11 * v11.z;
                    v.w = w00 * v00.w + w01 * v01.w + w10 * v10.w + w11 * v11.w;
                }
                int off = pix * PADK + c0;
                split_store(&Bnx[off], &Bnx[TILE_ELS + off], v);
            }
        }
    }

    // ---- epilogue: direct stores, NCHW ----
    #pragma unroll
    for (int mi = 0; mi < 2; ++mi) {
        #pragma unroll
        for (int nj = 0; nj < 4; ++nj) {
            int o = m0 + mi * 16 + g;
            int pix = n0 + nj * 8 + 2 * tq;
            float* op = out + (((size_t)n * COUT + o) * HH + h) * WW + pix;
            *(float2*)op = make_float2(acc[mi][nj][0], acc[mi][nj][1]);
            *(float2*)(op + 8 * HH * WW) = make_float2(acc[mi][nj][2], acc[mi][nj][3]);
        }
    }
}

// ============================================================
extern "C" void kernel_launch(void* const* d_in, const int* in_sizes, int n_in,
                              void* d_out, int out_size) {
    const float* x        = (const float*)d_in[0];
    const float* w_off    = (const float*)d_in[1];
    const float* b_off    = (const float*)d_in[2];
    const float* w_deform = (const float*)d_in[3];
    const float* w_pw     = (const float*)d_in[4];
    float* out = (float*)d_out;

    cudaFuncSetAttribute(off_mma,
                         cudaFuncAttributeMaxDynamicSharedMemorySize, OFF_SM_TOTAL);
    cudaFuncSetAttribute(fused_mma,
                         cudaFuncAttributeMaxDynamicSharedMemorySize, SM_TOTAL);

    prep_kernel<<<320, 256>>>(w_off, w_deform, w_pw);
    transpose_kernel<<<2048, 256>>>(x);
    off_mma<<<NB * HH, 512, OFF_SM_TOTAL>>>(b_off);
    fused_mma<<<NB * HH, 512, SM_TOTAL>>>(out);
}

// round 7
// speedup vs baseline: 2.7588x; 1.0731x over previous
#include <cuda_runtime.h>
#include <cuda_bf16.h>
#include <cstdint>

#define NB 4
#define CIN 64
#define HH 128
#define WW 128
#define COUT 128
#define NTAP 10            // 9 deform taps + 1 center-correction tap
#define NOFF 18

// ---- scratch (no allocations allowed) ----
__device__ float g_x_nhwc[NB * HH * WW * CIN];          // 16.8 MB
__device__ float g_toff[NB * NOFF * HH * WW];           // 4.7 MB, NCHW
__device__ __nv_bfloat16 g_A[NTAP * 2 * COUT * 64];     // fused GEMM A: [tap][hi/lo][o][c]
__device__ __nv_bfloat16 g_Aoff[2 * 32 * 576];          // offset-conv A: [hi/lo][o(32)][k=t*64+c]

// ============================================================
// helpers
// ============================================================
__device__ __forceinline__ void mma_bf16(float* c, const uint32_t* a, const uint32_t* b) {
    asm volatile(
        "mma.sync.aligned.m16n8k16.row.col.f32.bf16.bf16.f32 "
        "{%0,%1,%2,%3}, {%4,%5,%6,%7}, {%8,%9}, {%0,%1,%2,%3};"
        : "+f"(c[0]), "+f"(c[1]), "+f"(c[2]), "+f"(c[3])
        : "r"(a[0]), "r"(a[1]), "r"(a[2]), "r"(a[3]), "r"(b[0]), "r"(b[1]));
}
__device__ __forceinline__ void ldsm_x4(uint32_t addr, uint32_t* r) {
    asm volatile("ldmatrix.sync.aligned.m8n8.x4.shared.b16 {%0,%1,%2,%3}, [%4];"
                 : "=r"(r[0]), "=r"(r[1]), "=r"(r[2]), "=r"(r[3]) : "r"(addr));
}
__device__ __forceinline__ uint32_t smem_u32(const void* p) {
    uint32_t a;
    asm("{ .reg .u64 t; cvta.to.shared.u64 t, %1; cvt.u32.u64 %0, t; }" : "=r"(a) : "l"(p));
    return a;
}
__device__ __forceinline__ void cp_async16(uint32_t dst, const void* src) {
    asm volatile("cp.async.cg.shared.global [%0], [%1], 16;" :: "r"(dst), "l"(src) : "memory");
}
__device__ __forceinline__ void cp_commit() {
    asm volatile("cp.async.commit_group;" ::: "memory");
}
__device__ __forceinline__ void cp_wait0() {
    asm volatile("cp.async.wait_group 0;" ::: "memory");
}
__device__ __forceinline__ void split_store(__nv_bfloat16* hi_p, __nv_bfloat16* lo_p, float4 v) {
    __nv_bfloat16 b0 = __float2bfloat16(v.x);
    __nv_bfloat16 b1 = __float2bfloat16(v.y);
    __nv_bfloat16 b2 = __float2bfloat16(v.z);
    __nv_bfloat16 b3 = __float2bfloat16(v.w);
    __nv_bfloat162 hA = __halves2bfloat162(b0, b1);
    __nv_bfloat162 hB = __halves2bfloat162(b2, b3);
    __nv_bfloat162 lA = __halves2bfloat162(
        __float2bfloat16(v.x - __bfloat162float(b0)),
        __float2bfloat16(v.y - __bfloat162float(b1)));
    __nv_bfloat162 lB = __halves2bfloat162(
        __float2bfloat16(v.z - __bfloat162float(b2)),
        __float2bfloat16(v.w - __bfloat162float(b3)));
    *(uint2*)hi_p = make_uint2(*(uint32_t*)&hA, *(uint32_t*)&hB);
    *(uint2*)lo_p = make_uint2(*(uint32_t*)&lA, *(uint32_t*)&lB);
}

// ============================================================
// Precompute: A tiles for both GEMMs (bf16 hi/lo split)
// ============================================================
__global__ void prep_kernel(const float* __restrict__ w_off,
                            const float* __restrict__ w_deform,
                            const float* __restrict__ w_pw) {
    int tid = blockIdx.x * blockDim.x + threadIdx.x;
    int stride = gridDim.x * blockDim.x;

    // fused-GEMM A: [tap p][pl][o][c], k = p*64 + c
    for (int i = tid; i < NTAP * CIN * COUT; i += stride) {
        int o = i & 127;
        int k = i >> 7;
        int p = k >> 6;
        int c = k & 63;
        float acc = 0.f;
        if (p < 9) {
            #pragma unroll
            for (int d = 0; d < 4; ++d)
                acc += w_pw[o * 256 + c * 4 + d] * w_deform[(c * 4 + d) * 9 + p];
        } else {
            #pragma unroll
            for (int d = 0; d < 4; ++d) {
                float ws = 0.f;
                #pragma unroll
                for (int pp = 0; pp < 9; ++pp) ws += w_deform[(c * 4 + d) * 9 + pp];
                acc -= w_pw[o * 256 + c * 4 + d] * ws;
            }
        }
        __nv_bfloat16 hi = __float2bfloat16(acc);
        __nv_bfloat16 lo = __float2bfloat16(acc - __bfloat162float(hi));
        g_A[(p * 2 + 0) * 8192 + o * 64 + c] = hi;
        g_A[(p * 2 + 1) * 8192 + o * 64 + c] = lo;
    }

    // offset-conv A: [pl][o 0..31][k = t*64 + c], folded center tap, zero o>=18
    for (int i = tid; i < 32 * 576; i += stride) {
        int k = i % 576;
        int o = i / 576;
        int t = k >> 6;
        int c = k & 63;
        float v = 0.f;
        if (o < NOFF) {
            const float* wp = w_off + (o * CIN + c) * 9;
            v = wp[t];
            if (t == 4) {
                float s = 0.f;
                #pragma unroll
                for (int tt = 0; tt < 9; ++tt) s += wp[tt];
                v -= s;
            }
        }
        __nv_bfloat16 hi = __float2bfloat16(v);
        __nv_bfloat16 lo = __float2bfloat16(v - __bfloat162float(hi));
        g_Aoff[0 * 18432 + o * 576 + k] = hi;
        g_Aoff[1 * 18432 + o * 576 + k] = lo;
    }
}

// ============================================================
// NCHW -> NHWC transpose of x
// ============================================================
__global__ void transpose_kernel(const float* __restrict__ x) {
    __shared__ float tile[CIN][33];
    int b = blockIdx.x;
    int wt = b & 3;
    int h  = (b >> 2) & 127;
    int n  = b >> 9;
    int w0 = wt * 32;

    for (int i = threadIdx.x; i < CIN * 32; i += 256) {
        int c = i >> 5, w = i & 31;
        tile[c][w] = x[((n * CIN + c) * HH + h) * WW + w0 + w];
    }
    __syncthreads();
    for (int i = threadIdx.x; i < CIN * 32; i += 256) {
        int w = i >> 6, c = i & 63;
        g_x_nhwc[((n * HH + h) * WW + w0 + w) * CIN + c] = tile[c][w];
    }
}

// ============================================================
// Offset conv as tensor-core GEMM (unchanged from R6, proven).
// ============================================================
#define XROW 72
#define XPIX 130
#define XPLANE (3 * XPIX * XROW)
#define AOP 584
#define APLANE (32 * AOP)
#define OFF_SM_X 0
#define OFF_SM_A (2 * XPLANE * 2)
#define OFF_SM_TOTAL (OFF_SM_A + 2 * APLANE * 2)

__global__ void __launch_bounds__(512, 1) off_mma(const float* __restrict__ b_off) {
    extern __shared__ char sm[];
    __nv_bfloat16* Xs = (__nv_bfloat16*)(sm + OFF_SM_X);
    __nv_bfloat16* Aw = (__nv_bfloat16*)(sm + OFF_SM_A);

    int tid = threadIdx.x, wid = tid >> 5, lid = tid & 31;
    int g = lid >> 2, tq = lid & 3;
    int n = blockIdx.x >> 7, h = blockIdx.x & 127;
    int nw = wid * 8;

    for (int j = tid; j < 4608; j += 512) {
        int pl = j / 2304, rem = j % 2304;
        int o = rem / 72, seg = rem % 72;
        *(uint4*)&Aw[pl * APLANE + o * AOP + seg * 8] =
            *(const uint4*)&g_Aoff[pl * 18432 + o * 576 + seg * 8];
    }

    const float* xb = g_x_nhwc + (size_t)n * (HH * WW * CIN);
    for (int e = tid; e < 6240; e += 512) {
        int r = e / 2080, rem = e % 2080;
        int p = rem >> 4, c0 = (rem & 15) * 4;
        int row = h - 1 + r, w = p - 1;
        float4 v = make_float4(0.f, 0.f, 0.f, 0.f);
        if ((unsigned)row < (unsigned)HH && (unsigned)w < (unsigned)WW)
            v = *(const float4*)&xb[(row * WW + w) * CIN + c0];
        int off = r * (XPIX * XROW) + p * XROW + c0;
        split_store(&Xs[off], &Xs[XPLANE + off], v);
    }
    __syncthreads();

    float acc[2][4];
    #pragma unroll
    for (int mi = 0; mi < 2; ++mi)
        #pragma unroll
        for (int r = 0; r < 4; ++r) acc[mi][r] = 0.f;

    #pragma unroll
    for (int t = 0; t < 9; ++t) {
        int ky = t / 3, kx = t % 3;
        #pragma unroll
        for (int ks = 0; ks < 4; ++ks) {
            int k0 = ks * 16;
            uint32_t a[2][2][4], b[2][2];
            #pragma unroll
            for (int pl = 0; pl < 2; ++pl) {
                #pragma unroll
                for (int mi = 0; mi < 2; ++mi) {
                    const __nv_bfloat16* ap =
                        Aw + pl * APLANE + (mi * 16 + g) * AOP + t * 64 + k0 + 2 * tq;
                    a[pl][mi][0] = *(const uint32_t*)(ap);
                    a[pl][mi][1] = *(const uint32_t*)(ap + 8 * AOP);
                    a[pl][mi][2] = *(const uint32_t*)(ap + 8);
                    a[pl][mi][3] = *(const uint32_t*)(ap + 8 * AOP + 8);
                }
                const __nv_bfloat16* bp =
                    Xs + pl * XPLANE + ky * (XPIX * XROW) + (nw + g + kx) * XROW + k0 + 2 * tq;
                b[pl][0] = *(const uint32_t*)(bp);
                b[pl][1] = *(const uint32_t*)(bp + 8);
            }
            #pragma unroll
            for (int mi = 0; mi < 2; ++mi) {
                mma_bf16(acc[mi], a[0][mi], b[0]);
                mma_bf16(acc[mi], a[0][mi], b[1]);
                mma_bf16(acc[mi], a[1][mi], b[0]);
            }
        }
    }

    int pix = nw + 2 * tq;
    #pragma unroll
    for (int mi = 0; mi < 2; ++mi) {
        int oa = mi * 16 + g;
        int ob = oa + 8;
        if (oa < NOFF) {
            float bb = __ldg(&b_off[oa]);
            *(float2*)&g_toff[((n * NOFF + oa) * HH + h) * WW + pix] =
                make_float2(acc[mi][0] + bb, acc[mi][1] + bb);
        }
        if (ob < NOFF) {
            float bb = __ldg(&b_off[ob]);
            *(float2*)&g_toff[((n * NOFF + ob) * HH + h) * WW + pix] =
                make_float2(acc[mi][2] + bb, acc[mi][3] + bb);
        }
    }
}

// ============================================================
// Fused deform-sample + mma.sync bf16x3 GEMM, software-pipelined,
// fragment loads via ldmatrix.x4 (R7 change).
// ============================================================
#define PADK 72
#define TILE_ELS 9216                       // 128*72
#define BUF_ELS (2 * TILE_ELS)
#define SM_PAR 0
#define SM_A 36864
#define SM_B (36864 + 73728)
#define SM_TOTAL (SM_B + 73728)             // 184320 B

__global__ void __launch_bounds__(512, 1) fused_mma(float* __restrict__ out) {
    extern __shared__ char sm[];
    float* sW = (float*)(sm + SM_PAR);
    int*   sO = (int*)(sm + SM_PAR + 4 * 1152 * 4);
    __nv_bfloat16* Bs = (__nv_bfloat16*)(sm + SM_B);
    uint32_t smbA = smem_u32(sm + SM_A);
    uint32_t smbB = smem_u32(sm + SM_B);

    int tid = threadIdx.x, wid = tid >> 5, lid = tid & 31;
    int n = blockIdx.x >> 7, h = blockIdx.x & 127;
    int g = lid >> 2, tq = lid & 3;
    int m0 = (wid & 3) * 32;
    int n0 = (wid >> 2) * 32;

    // ldmatrix per-lane base byte offsets (within a plane)
    // A x4: lanes 0-15 -> rows m..m+15 @ k0, lanes 16-31 -> same rows @ k0+8
    uint32_t aBase = (uint32_t)(((m0 + (lid & 15)) * PADK + ((lid >> 4) << 3)) * 2);
    // B x4: lanes 0-7: rows n..n+7 @k0; 8-15: same rows @k0+8; 16-23: rows n+8.. @k0; 24-31: @k0+8
    uint32_t bBase = (uint32_t)(((n0 + (lid & 7) + ((lid >> 4) << 3)) * PADK
                                 + (((lid >> 3) & 1) << 3)) * 2);

    // ---- bilinear params per (tap, pixel) ----
    for (int i = tid; i < 9 * 128; i += 512) {
        int p = i >> 7, pix = i & 127;
        float dy = g_toff[((n * NOFF + 2 * p    ) * HH + h) * WW + pix];
        float dx = g_toff[((n * NOFF + 2 * p + 1) * HH + h) * WW + pix];
        float py = dy + (float)(h - 1 + p / 3);
        float px = dx + (float)(pix - 1 + p % 3);
        float y0f = floorf(py), x0f = floorf(px);
        int y0 = (int)y0f, x0 = (int)x0f;
        float wy1 = py - y0f, wx1 = px - x0f;
        float wy0 = 1.f - wy1, wx0 = 1.f - wx1;
        bool vy0 = (unsigned)y0 < (unsigned)HH, vy1 = (unsigned)(y0 + 1) < (unsigned)HH;
        bool vx0 = (unsigned)x0 < (unsigned)WW, vx1 = (unsigned)(x0 + 1) < (unsigned)WW;
        int cy0 = min(max(y0, 0), HH - 1), cy1 = min(max(y0 + 1, 0), HH - 1);
        int cx0 = min(max(x0, 0), WW - 1), cx1 = min(max(x0 + 1, 0), WW - 1);
        sW[0 * 1152 + i] = (vy0 && vx0) ? wy0 * wx0 : 0.f;
        sW[1 * 1152 + i] = (vy0 && vx1) ? wy0 * wx1 : 0.f;
        sW[2 * 1152 + i] = (vy1 && vx0) ? wy1 * wx0 : 0.f;
        sW[3 * 1152 + i] = (vy1 && vx1) ? wy1 * wx1 : 0.f;
        sO[0 * 1152 + i] = (cy0 * WW + cx0) * CIN;
        sO[1 * 1152 + i] = (cy0 * WW + cx1) * CIN;
        sO[2 * 1152 + i] = (cy1 * WW + cx0) * CIN;
        sO[3 * 1152 + i] = (cy1 * WW + cx1) * CIN;
    }
    __syncthreads();

    const float* xb = g_x_nhwc + (size_t)n * (HH * WW * CIN);

    // ---- prologue: A(0) via cp.async, B(0) gathered inline ----
    {
        #pragma unroll
        for (int m = 0; m < 4; ++m) {
            int j = tid + 512 * m;
            int plane = j >> 10, row = (j >> 3) & 127, seg = j & 7;
            cp_async16(smbA + (uint32_t)(plane * 18432 + row * 144 + seg * 16),
                       g_A + j * 8);
        }
        cp_commit();
        __nv_bfloat16* B0 = Bs;
        #pragma unroll
        for (int sub = 0; sub < 4; ++sub) {
            int e = tid + 512 * sub;
            int pix = e >> 4, c0 = (e & 15) * 4;
            int i = pix;   // tap 0
            float w00 = sW[i], w01 = sW[1152 + i], w10 = sW[2 * 1152 + i], w11 = sW[3 * 1152 + i];
            float4 v00 = *(const float4*)&xb[sO[i] + c0];
            float4 v01 = *(const float4*)&xb[sO[1152 + i] + c0];
            float4 v10 = *(const float4*)&xb[sO[2 * 1152 + i] + c0];
            float4 v11 = *(const float4*)&xb[sO[3 * 1152 + i] + c0];
            float4 v;
            v.x = w00 * v00.x + w01 * v01.x + w10 * v10.x + w11 * v11.x;
            v.y = w00 * v00.y + w01 * v01.y + w10 * v10.y + w11 * v11.y;
            v.z = w00 * v00.z + w01 * v01.z + w10 * v10.z + w11 * v11.z;
            v.w = w00 * v00.w + w01 * v01.w + w10 * v10.w + w11 * v11.w;
            int off = pix * PADK + c0;
            split_store(&B0[off], &B0[TILE_ELS + off], v);
        }
    }

    float acc[2][4][4];
    #pragma unroll
    for (int mi = 0; mi < 2; ++mi)
        #pragma unroll
        for (int nj = 0; nj < 4; ++nj)
            #pragma unroll
            for (int r = 0; r < 4; ++r) acc[mi][nj][r] = 0.f;

    for (int t = 0; t < NTAP; ++t) {
        cp_wait0();
        __syncthreads();
        bool pf = (t < 9);

        if (pf) {
            const __nv_bfloat16* asrc = g_A + (t + 1) * 16384;
            uint32_t adst = smbA + (uint32_t)(((t + 1) & 1) * 36864);
            #pragma unroll
            for (int m = 0; m < 4; ++m) {
                int j = tid + 512 * m;
                int plane = j >> 10, row = (j >> 3) & 127, seg = j & 7;
                cp_async16(adst + (uint32_t)(plane * 18432 + row * 144 + seg * 16),
                           asrc + j * 8);
            }
            cp_commit();
        }

        uint32_t aBuf = smbA + (uint32_t)((t & 1) * 36864) + aBase;
        uint32_t bBuf = smbB + (uint32_t)((t & 1) * 36864) + bBase;
        __nv_bfloat16* Bnx = Bs + ((t + 1) & 1) * BUF_ELS;

        #pragma unroll
        for (int sub = 0; sub < 4; ++sub) {
            // -- issue gather loads for tap t+1, sub-block 'sub' --
            float4 v00, v01, v10, v11;
            float w00, w01, w10, w11;
            int pix = 0, c0 = 0;
            bool center = (t + 1 == 9);
            if (pf) {
                int e = tid + 512 * sub;
                pix = e >> 4; c0 = (e & 15) * 4;
                if (center) {
                    v00 = *(const float4*)&xb[(h * WW + pix) * CIN + c0];
                } else {
                    int i = (t + 1) * 128 + pix;
                    w00 = sW[i]; w01 = sW[1152 + i]; w10 = sW[2 * 1152 + i]; w11 = sW[3 * 1152 + i];
                    v00 = *(const float4*)&xb[sO[i] + c0];
                    v01 = *(const float4*)&xb[sO[1152 + i] + c0];
                    v10 = *(const float4*)&xb[sO[2 * 1152 + i] + c0];
                    v11 = *(const float4*)&xb[sO[3 * 1152 + i] + c0];
                }
            }

            // -- MMA k-step 'sub' of tap t: ldmatrix fragments + 24 MMA --
            {
                uint32_t kOff = (uint32_t)(sub * 16 * 2);
                uint32_t a[2][2][4], bfr[2][2][4];
                #pragma unroll
                for (int pl = 0; pl < 2; ++pl) {
                    #pragma unroll
                    for (int mi = 0; mi < 2; ++mi)
                        ldsm_x4(aBuf + (uint32_t)(pl * 18432 + mi * 16 * PADK * 2) + kOff,
                                a[pl][mi]);
                    #pragma unroll
                    for (int njp = 0; njp < 2; ++njp)
                        ldsm_x4(bBuf + (uint32_t)(pl * 18432 + njp * 16 * PADK * 2) + kOff,
                                bfr[pl][njp]);
                }
                #pragma unroll
                for (int mi = 0; mi < 2; ++mi)
                    #pragma unroll
                    for (int nj = 0; nj < 4; ++nj) {
                        const uint32_t* b0 = bfr[0][nj >> 1] + (nj & 1) * 2;
                        const uint32_t* b1 = bfr[1][nj >> 1] + (nj & 1) * 2;
                        mma_bf16(acc[mi][nj], a[0][mi], b0);  // hi*hi
                        mma_bf16(acc[mi][nj], a[0][mi], b1);  // hi*lo
                        mma_bf16(acc[mi][nj], a[1][mi], b0);  // lo*hi
                    }
            }

            // -- finish gather: combine, split, STS into next buffer --
            if (pf) {
                float4 v;
                if (center) {
                    v = v00;
                } else {
                    v.x = w00 * v00.x + w01 * v01.x + w10 * v10.x + w11 * v11.x;
                    v.y = w00 * v00.y + w01 * v01.y + w10 * v10.y + w11 * v11.y;
                    v.z = w00 * v00.z + w01 * v01.z + w10 * v10.z + w11 * v11.z;
                    v.w = w00 * v00.w + w01 * v01.w + w10 * v10.w + w11 * v11.w;
                }
                int off = pix * PADK + c0;
                split_store(&Bnx[off], &Bnx[TILE_ELS + off], v);
            }
        }
    }

    // ---- epilogue: direct stores, NCHW ----
    #pragma unroll
    for (int mi = 0; mi < 2; ++mi) {
        #pragma unroll
        for (int nj = 0; nj < 4; ++nj) {
            int o = m0 + mi * 16 + g;
            int pix = n0 + nj * 8 + 2 * tq;
            float* op = out + (((size_t)n * COUT + o) * HH + h) * WW + pix;
            *(float2*)op = make_float2(acc[mi][nj][0], acc[mi][nj][1]);
            *(float2*)(op + 8 * HH * WW) = make_float2(acc[mi][nj][2], acc[mi][nj][3]);
        }
    }
}

// ============================================================
extern "C" void kernel_launch(void* const* d_in, const int* in_sizes, int n_in,
                              void* d_out, int out_size) {
    const float* x        = (const float*)d_in[0];
    const float* w_off    = (const float*)d_in[1];
    const float* b_off    = (const float*)d_in[2];
    const float* w_deform = (const float*)d_in[3];
    const float* w_pw     = (const float*)d_in[4];
    float* out = (float*)d_out;

    cudaFuncSetAttribute(off_mma,
                         cudaFuncAttributeMaxDynamicSharedMemorySize, OFF_SM_TOTAL);
    cudaFuncSetAttribute(fused_mma,
                         cudaFuncAttributeMaxDynamicSharedMemorySize, SM_TOTAL);

    prep_kernel<<<320, 256>>>(w_off, w_deform, w_pw);
    transpose_kernel<<<2048, 256>>>(x);
    off_mma<<<NB * HH, 512, OFF_SM_TOTAL>>>(b_off);
    fused_mma<<<NB * HH, 512, SM_TOTAL>>>(out);
}

// round 8
// speedup vs baseline: 2.8579x; 1.0359x over previous
#include <cuda_runtime.h>
#include <cuda_bf16.h>
#include <cstdint>

#define NB 4
#define CIN 64
#define HH 128
#define WW 128
#define COUT 128
#define NTAP 10            // 9 deform taps + 1 center-correction tap
#define NOFF 18

// ---- scratch (no allocations allowed) ----
__device__ float g_x_nhwc[NB * HH * WW * CIN];          // 16.8 MB
__device__ float g_toff[NB * NOFF * HH * WW];           // 4.7 MB, NCHW
__device__ __nv_bfloat16 g_A[NTAP * 2 * COUT * 64];     // fused GEMM A: [tap][hi/lo][o][c]
__device__ __nv_bfloat16 g_Aoff[2 * 32 * 576];          // offset-conv A: [hi/lo][o(32)][k=t*64+c]

// ============================================================
// helpers
// ============================================================
__device__ __forceinline__ void mma_bf16(float* c, const uint32_t* a, const uint32_t* b) {
    asm volatile(
        "mma.sync.aligned.m16n8k16.row.col.f32.bf16.bf16.f32 "
        "{%0,%1,%2,%3}, {%4,%5,%6,%7}, {%8,%9}, {%0,%1,%2,%3};"
        : "+f"(c[0]), "+f"(c[1]), "+f"(c[2]), "+f"(c[3])
        : "r"(a[0]), "r"(a[1]), "r"(a[2]), "r"(a[3]), "r"(b[0]), "r"(b[1]));
}
__device__ __forceinline__ void ldsm_x4(uint32_t addr, uint32_t* r) {
    asm volatile("ldmatrix.sync.aligned.m8n8.x4.shared.b16 {%0,%1,%2,%3}, [%4];"
                 : "=r"(r[0]), "=r"(r[1]), "=r"(r[2]), "=r"(r[3]) : "r"(addr));
}
__device__ __forceinline__ uint32_t smem_u32(const void* p) {
    uint32_t a;
    asm("{ .reg .u64 t; cvta.to.shared.u64 t, %1; cvt.u32.u64 %0, t; }" : "=r"(a) : "l"(p));
    return a;
}
__device__ __forceinline__ void cp_async16(uint32_t dst, const void* src) {
    asm volatile("cp.async.cg.shared.global [%0], [%1], 16;" :: "r"(dst), "l"(src) : "memory");
}
__device__ __forceinline__ void cp_commit() {
    asm volatile("cp.async.commit_group;" ::: "memory");
}
__device__ __forceinline__ void cp_wait0() {
    asm volatile("cp.async.wait_group 0;" ::: "memory");
}
__device__ __forceinline__ void split_store(__nv_bfloat16* hi_p, __nv_bfloat16* lo_p, float4 v) {
    __nv_bfloat16 b0 = __float2bfloat16(v.x);
    __nv_bfloat16 b1 = __float2bfloat16(v.y);
    __nv_bfloat16 b2 = __float2bfloat16(v.z);
    __nv_bfloat16 b3 = __float2bfloat16(v.w);
    __nv_bfloat162 hA = __halves2bfloat162(b0, b1);
    __nv_bfloat162 hB = __halves2bfloat162(b2, b3);
    __nv_bfloat162 lA = __halves2bfloat162(
        __float2bfloat16(v.x - __bfloat162float(b0)),
        __float2bfloat16(v.y - __bfloat162float(b1)));
    __nv_bfloat162 lB = __halves2bfloat162(
        __float2bfloat16(v.z - __bfloat162float(b2)),
        __float2bfloat16(v.w - __bfloat162float(b3)));
    *(uint2*)hi_p = make_uint2(*(uint32_t*)&hA, *(uint32_t*)&hB);
    *(uint2*)lo_p = make_uint2(*(uint32_t*)&lA, *(uint32_t*)&lB);
}

// ============================================================
// Precompute: A tiles for both GEMMs (bf16 hi/lo split)
// ============================================================
__global__ void prep_kernel(const float* __restrict__ w_off,
                            const float* __restrict__ w_deform,
                            const float* __restrict__ w_pw) {
    int tid = blockIdx.x * blockDim.x + threadIdx.x;
    int stride = gridDim.x * blockDim.x;

    for (int i = tid; i < NTAP * CIN * COUT; i += stride) {
        int o = i & 127;
        int k = i >> 7;
        int p = k >> 6;
        int c = k & 63;
        float acc = 0.f;
        if (p < 9) {
            #pragma unroll
            for (int d = 0; d < 4; ++d)
                acc += w_pw[o * 256 + c * 4 + d] * w_deform[(c * 4 + d) * 9 + p];
        } else {
            #pragma unroll
            for (int d = 0; d < 4; ++d) {
                float ws = 0.f;
                #pragma unroll
                for (int pp = 0; pp < 9; ++pp) ws += w_deform[(c * 4 + d) * 9 + pp];
                acc -= w_pw[o * 256 + c * 4 + d] * ws;
            }
        }
        __nv_bfloat16 hi = __float2bfloat16(acc);
        __nv_bfloat16 lo = __float2bfloat16(acc - __bfloat162float(hi));
        g_A[(p * 2 + 0) * 8192 + o * 64 + c] = hi;
        g_A[(p * 2 + 1) * 8192 + o * 64 + c] = lo;
    }

    for (int i = tid; i < 32 * 576; i += stride) {
        int k = i % 576;
        int o = i / 576;
        int t = k >> 6;
        int c = k & 63;
        float v = 0.f;
        if (o < NOFF) {
            const float* wp = w_off + (o * CIN + c) * 9;
            v = wp[t];
            if (t == 4) {
                float s = 0.f;
                #pragma unroll
                for (int tt = 0; tt < 9; ++tt) s += wp[tt];
                v -= s;
            }
        }
        __nv_bfloat16 hi = __float2bfloat16(v);
        __nv_bfloat16 lo = __float2bfloat16(v - __bfloat162float(hi));
        g_Aoff[0 * 18432 + o * 576 + k] = hi;
        g_Aoff[1 * 18432 + o * 576 + k] = lo;
    }
}

// ============================================================
// NCHW -> NHWC transpose of x
// ============================================================
__global__ void transpose_kernel(const float* __restrict__ x) {
    __shared__ float tile[CIN][33];
    int b = blockIdx.x;
    int wt = b & 3;
    int h  = (b >> 2) & 127;
    int n  = b >> 9;
    int w0 = wt * 32;

    for (int i = threadIdx.x; i < CIN * 32; i += 256) {
        int c = i >> 5, w = i & 31;
        tile[c][w] = x[((n * CIN + c) * HH + h) * WW + w0 + w];
    }
    __syncthreads();
    for (int i = threadIdx.x; i < CIN * 32; i += 256) {
        int w = i >> 6, c = i & 63;
        g_x_nhwc[((n * HH + h) * WW + w0 + w) * CIN + c] = tile[c][w];
    }
}

// ============================================================
// Offset conv as tensor-core GEMM (unchanged, proven).
// ============================================================
#define XROW 72
#define XPIX 130
#define XPLANE (3 * XPIX * XROW)
#define AOP 584
#define APLANE (32 * AOP)
#define OFF_SM_X 0
#define OFF_SM_A (2 * XPLANE * 2)
#define OFF_SM_TOTAL (OFF_SM_A + 2 * APLANE * 2)

__global__ void __launch_bounds__(512, 1) off_mma(const float* __restrict__ b_off) {
    extern __shared__ char sm[];
    __nv_bfloat16* Xs = (__nv_bfloat16*)(sm + OFF_SM_X);
    __nv_bfloat16* Aw = (__nv_bfloat16*)(sm + OFF_SM_A);

    int tid = threadIdx.x, wid = tid >> 5, lid = tid & 31;
    int g = lid >> 2, tq = lid & 3;
    int n = blockIdx.x >> 7, h = blockIdx.x & 127;
    int nw = wid * 8;

    for (int j = tid; j < 4608; j += 512) {
        int pl = j / 2304, rem = j % 2304;
        int o = rem / 72, seg = rem % 72;
        *(uint4*)&Aw[pl * APLANE + o * AOP + seg * 8] =
            *(const uint4*)&g_Aoff[pl * 18432 + o * 576 + seg * 8];
    }

    const float* xb = g_x_nhwc + (size_t)n * (HH * WW * CIN);
    for (int e = tid; e < 6240; e += 512) {
        int r = e / 2080, rem = e % 2080;
        int p = rem >> 4, c0 = (rem & 15) * 4;
        int row = h - 1 + r, w = p - 1;
        float4 v = make_float4(0.f, 0.f, 0.f, 0.f);
        if ((unsigned)row < (unsigned)HH && (unsigned)w < (unsigned)WW)
            v = *(const float4*)&xb[(row * WW + w) * CIN + c0];
        int off = r * (XPIX * XROW) + p * XROW + c0;
        split_store(&Xs[off], &Xs[XPLANE + off], v);
    }
    __syncthreads();

    float acc[2][4];
    #pragma unroll
    for (int mi = 0; mi < 2; ++mi)
        #pragma unroll
        for (int r = 0; r < 4; ++r) acc[mi][r] = 0.f;

    #pragma unroll
    for (int t = 0; t < 9; ++t) {
        int ky = t / 3, kx = t % 3;
        #pragma unroll
        for (int ks = 0; ks < 4; ++ks) {
            int k0 = ks * 16;
            uint32_t a[2][2][4], b[2][2];
            #pragma unroll
            for (int pl = 0; pl < 2; ++pl) {
                #pragma unroll
                for (int mi = 0; mi < 2; ++mi) {
                    const __nv_bfloat16* ap =
                        Aw + pl * APLANE + (mi * 16 + g) * AOP + t * 64 + k0 + 2 * tq;
                    a[pl][mi][0] = *(const uint32_t*)(ap);
                    a[pl][mi][1] = *(const uint32_t*)(ap + 8 * AOP);
                    a[pl][mi][2] = *(const uint32_t*)(ap + 8);
                    a[pl][mi][3] = *(const uint32_t*)(ap + 8 * AOP + 8);
                }
                const __nv_bfloat16* bp =
                    Xs + pl * XPLANE + ky * (XPIX * XROW) + (nw + g + kx) * XROW + k0 + 2 * tq;
                b[pl][0] = *(const uint32_t*)(bp);
                b[pl][1] = *(const uint32_t*)(bp + 8);
            }
            #pragma unroll
            for (int mi = 0; mi < 2; ++mi) {
                mma_bf16(acc[mi], a[0][mi], b[0]);
                mma_bf16(acc[mi], a[0][mi], b[1]);
                mma_bf16(acc[mi], a[1][mi], b[0]);
            }
        }
    }

    int pix = nw + 2 * tq;
    #pragma unroll
    for (int mi = 0; mi < 2; ++mi) {
        int oa = mi * 16 + g;
        int ob = oa + 8;
        if (oa < NOFF) {
            float bb = __ldg(&b_off[oa]);
            *(float2*)&g_toff[((n * NOFF + oa) * HH + h) * WW + pix] =
                make_float2(acc[mi][0] + bb, acc[mi][1] + bb);
        }
        if (ob < NOFF) {
            float bb = __ldg(&b_off[ob]);
            *(float2*)&g_toff[((n * NOFF + ob) * HH + h) * WW + pix] =
                make_float2(acc[mi][2] + bb, acc[mi][3] + bb);
        }
    }
}

// ============================================================
// Fused deform-sample + mma.sync bf16x3 GEMM.
// R8: 256-thread CTAs, M=128 x N=64, 92KB smem -> 2 CTAs/SM.
// A single-buffered (reload bubble covered by co-resident CTA),
// B double-buffered with gather interleaved into MMA k-steps.
// ============================================================
#define PADK 72
#define NPIX 64                              // pixels per block
#define BTILE (NPIX * PADK)                  // 4608 els per plane
#define BBUF (2 * BTILE)                     // hi+lo = 9216 els
#define SM_PAR 0                             // 8 * 576 * 4 = 18432 B
#define SM_A 18432                           // 2 planes * 128*72*2B = 36864 B
#define SM_B (18432 + 36864)                 // 2 bufs * 18432 B = 36864 B
#define SM_TOTAL (SM_B + 36864)              // 92160 B

__global__ void __launch_bounds__(256, 2) fused_mma(float* __restrict__ out) {
    extern __shared__ char sm[];
    float* sW = (float*)(sm + SM_PAR);                  // 4 x [576]
    int*   sO = (int*)(sm + SM_PAR + 4 * 576 * 4);      // 4 x [576]
    __nv_bfloat16* Bs = (__nv_bfloat16*)(sm + SM_B);
    uint32_t smbA = smem_u32(sm + SM_A);
    uint32_t smbB = smem_u32(sm + SM_B);

    int tid = threadIdx.x, wid = tid >> 5, lid = tid & 31;
    int n  = blockIdx.x >> 8;
    int h  = (blockIdx.x >> 1) & 127;
    int w0 = (blockIdx.x & 1) * NPIX;
    int g = lid >> 2, tq = lid & 3;
    int m0 = (wid & 3) * 32;
    int n0 = (wid >> 2) * 32;                // 0 or 32 within the 64-pixel tile

    // ldmatrix per-lane base byte offsets
    uint32_t aBase = (uint32_t)(((m0 + (lid & 15)) * PADK + ((lid >> 4) << 3)) * 2);
    uint32_t bBase = (uint32_t)(((n0 + (lid & 7) + ((lid >> 4) << 3)) * PADK
                                 + (((lid >> 3) & 1) << 3)) * 2);

    // ---- bilinear params per (tap, pixel): 9*64 = 576 entries ----
    for (int i = tid; i < 9 * NPIX; i += 256) {
        int p = i >> 6, pix = i & 63;
        int w = w0 + pix;
        float dy = g_toff[((n * NOFF + 2 * p    ) * HH + h) * WW + w];
        float dx = g_toff[((n * NOFF + 2 * p + 1) * HH + h) * WW + w];
        float py = dy + (float)(h - 1 + p / 3);
        float px = dx + (float)(w - 1 + p % 3);
        float y0f = floorf(py), x0f = floorf(px);
        int y0 = (int)y0f, x0 = (int)x0f;
        float wy1 = py - y0f, wx1 = px - x0f;
        float wy0 = 1.f - wy1, wx0 = 1.f - wx1;
        bool vy0 = (unsigned)y0 < (unsigned)HH, vy1 = (unsigned)(y0 + 1) < (unsigned)HH;
        bool vx0 = (unsigned)x0 < (unsigned)WW, vx1 = (unsigned)(x0 + 1) < (unsigned)WW;
        int cy0 = min(max(y0, 0), HH - 1), cy1 = min(max(y0 + 1, 0), HH - 1);
        int cx0 = min(max(x0, 0), WW - 1), cx1 = min(max(x0 + 1, 0), WW - 1);
        sW[0 * 576 + i] = (vy0 && vx0) ? wy0 * wx0 : 0.f;
        sW[1 * 576 + i] = (vy0 && vx1) ? wy0 * wx1 : 0.f;
        sW[2 * 576 + i] = (vy1 && vx0) ? wy1 * wx0 : 0.f;
        sW[3 * 576 + i] = (vy1 && vx1) ? wy1 * wx1 : 0.f;
        sO[0 * 576 + i] = (cy0 * WW + cx0) * CIN;
        sO[1 * 576 + i] = (cy0 * WW + cx1) * CIN;
        sO[2 * 576 + i] = (cy1 * WW + cx0) * CIN;
        sO[3 * 576 + i] = (cy1 * WW + cx1) * CIN;
    }

    const float* xb = g_x_nhwc + (size_t)n * (HH * WW * CIN);

    // ---- prologue: A(0) via cp.async (single buffer) ----
    #pragma unroll
    for (int m = 0; m < 8; ++m) {
        int j = tid + 256 * m;
        int plane = j >> 10, row = (j >> 3) & 127, seg = j & 7;
        cp_async16(smbA + (uint32_t)(plane * 18432 + row * 144 + seg * 16),
                   g_A + j * 8);
    }
    cp_commit();
    __syncthreads();   // params visible

    // ---- prologue: B(0) gathered inline into buf 0 ----
    #pragma unroll
    for (int sub = 0; sub < 4; ++sub) {
        int e = tid + 256 * sub;
        int pix = e >> 4, c0 = (e & 15) * 4;
        int i = pix;   // tap 0
        float w00 = sW[i], w01 = sW[576 + i], w10 = sW[2 * 576 + i], w11 = sW[3 * 576 + i];
        float4 v00 = *(const float4*)&xb[sO[i] + c0];
        float4 v01 = *(const float4*)&xb[sO[576 + i] + c0];
        float4 v10 = *(const float4*)&xb[sO[2 * 576 + i] + c0];
        float4 v11 = *(const float4*)&xb[sO[3 * 576 + i] + c0];
        float4 v;
        v.x = w00 * v00.x + w01 * v01.x + w10 * v10.x + w11 * v11.x;
        v.y = w00 * v00.y + w01 * v01.y + w10 * v10.y + w11 * v11.y;
        v.z = w00 * v00.z + w01 * v01.z + w10 * v10.z + w11 * v11.z;
        v.w = w00 * v00.w + w01 * v01.w + w10 * v10.w + w11 * v11.w;
        int off = pix * PADK + c0;
        split_store(&Bs[off], &Bs[BTILE + off], v);
    }

    float acc[2][4][4];
    #pragma unroll
    for (int mi = 0; mi < 2; ++mi)
        #pragma unroll
        for (int nj = 0; nj < 4; ++nj)
            #pragma unroll
            for (int r = 0; r < 4; ++r) acc[mi][nj][r] = 0.f;

    for (int t = 0; t < NTAP; ++t) {
        cp_wait0();
        __syncthreads();   // A(t) + B(t) ready
        bool pf = (t < 9);

        uint32_t bBuf = smbB + (uint32_t)((t & 1) * 18432) + bBase;
        __nv_bfloat16* Bnx = Bs + ((t + 1) & 1) * BBUF;

        #pragma unroll
        for (int sub = 0; sub < 4; ++sub) {
            // -- issue gather loads for tap t+1 --
            float4 v00, v01, v10, v11;
            float w00, w01, w10, w11;
            int pix = 0, c0 = 0;
            bool center = (t + 1 == 9);
            if (pf) {
                int e = tid + 256 * sub;
                pix = e >> 4; c0 = (e & 15) * 4;
                if (center) {
                    v00 = *(const float4*)&xb[(h * WW + w0 + pix) * CIN + c0];
                } else {
                    int i = (t + 1) * NPIX + pix;
                    w00 = sW[i]; w01 = sW[576 + i]; w10 = sW[2 * 576 + i]; w11 = sW[3 * 576 + i];
                    v00 = *(const float4*)&xb[sO[i] + c0];
                    v01 = *(const float4*)&xb[sO[576 + i] + c0];
                    v10 = *(const float4*)&xb[sO[2 * 576 + i] + c0];
                    v11 = *(const float4*)&xb[sO[3 * 576 + i] + c0];
                }
            }

            // -- MMA k-step 'sub' of tap t --
            {
                uint32_t kOff = (uint32_t)(sub * 16 * 2);
                uint32_t a[2][2][4], bfr[2][2][4];
                #pragma unroll
                for (int pl = 0; pl < 2; ++pl) {
                    #pragma unroll
                    for (int mi = 0; mi < 2; ++mi)
                        ldsm_x4(smbA + aBase + (uint32_t)(pl * 18432 + mi * 16 * PADK * 2) + kOff,
                                a[pl][mi]);
                    #pragma unroll
                    for (int njp = 0; njp < 2; ++njp)
                        ldsm_x4(bBuf + (uint32_t)(pl * 9216 + njp * 16 * PADK * 2) + kOff,
                                bfr[pl][njp]);
                }
                #pragma unroll
                for (int mi = 0; mi < 2; ++mi)
                    #pragma unroll
                    for (int nj = 0; nj < 4; ++nj) {
                        const uint32_t* b0 = bfr[0][nj >> 1] + (nj & 1) * 2;
                        const uint32_t* b1 = bfr[1][nj >> 1] + (nj & 1) * 2;
                        mma_bf16(acc[mi][nj], a[0][mi], b0);  // hi*hi
                        mma_bf16(acc[mi][nj], a[0][mi], b1);  // hi*lo
                        mma_bf16(acc[mi][nj], a[1][mi], b0);  // lo*hi
                    }
            }

            // -- finish gather: combine, split, STS into next buffer --
            if (pf) {
                float4 v;
                if (center) {
                    v = v00;
                } else {
                    v.x = w00 * v00.x + w01 * v01.x + w10 * v10.x + w11 * v11.x;
                    v.y = w00 * v00.y + w01 * v01.y + w10 * v10.y + w11 * v11.y;
                    v.z = w00 * v00.z + w01 * v01.z + w10 * v10.z + w11 * v11.z;
                    v.w = w00 * v00.w + w01 * v01.w + w10 * v10.w + w11 * v11.w;
                }
                int off = pix * PADK + c0;
                split_store(&Bnx[off], &Bnx[BTILE + off], v);
            }
        }

        __syncthreads();   // all reads of single-buffered A(t) done
        if (pf) {
            const __nv_bfloat16* asrc = g_A + (t + 1) * 16384;
            #pragma unroll
            for (int m = 0; m < 8; ++m) {
                int j = tid + 256 * m;
                int plane = j >> 10, row = (j >> 3) & 127, seg = j & 7;
                cp_async16(smbA + (uint32_t)(plane * 18432 + row * 144 + seg * 16),
                           asrc + j * 8);
            }
            cp_commit();
        }
    }

    // ---- epilogue: direct stores, NCHW ----
    #pragma unroll
    for (int mi = 0; mi < 2; ++mi) {
        #pragma unroll
        for (int nj = 0; nj < 4; ++nj) {
            int o = m0 + mi * 16 + g;
            int pix = w0 + n0 + nj * 8 + 2 * tq;
            float* op = out + (((size_t)n * COUT + o) * HH + h) * WW + pix;
            *(float2*)op = make_float2(acc[mi][nj][0], acc[mi][nj][1]);
            *(float2*)(op + 8 * HH * WW) = make_float2(acc[mi][nj][2], acc[mi][nj][3]);
        }
    }
}

// ============================================================
extern "C" void kernel_launch(void* const* d_in, const int* in_sizes, int n_in,
                              void* d_out, int out_size) {
    const float* x        = (const float*)d_in[0];
    const float* w_off    = (const float*)d_in[1];
    const float* b_off    = (const float*)d_in[2];
    const float* w_deform = (const float*)d_in[3];
    const float* w_pw     = (const float*)d_in[4];
    float* out = (float*)d_out;

    cudaFuncSetAttribute(off_mma,
                         cudaFuncAttributeMaxDynamicSharedMemorySize, OFF_SM_TOTAL);
    cudaFuncSetAttribute(fused_mma,
                         cudaFuncAttributeMaxDynamicSharedMemorySize, SM_TOTAL);

    prep_kernel<<<320, 256>>>(w_off, w_deform, w_pw);
    transpose_kernel<<<2048, 256>>>(x);
    off_mma<<<NB * HH, 512, OFF_SM_TOTAL>>>(b_off);
    fused_mma<<<NB * HH * 2, 256, SM_TOTAL>>>(out);
}

// round 9
// speedup vs baseline: 3.3811x; 1.1831x over previous
#include <cuda_runtime.h>
#include <cuda_bf16.h>
#include <cuda_fp16.h>
#include <cstdint>

#define NB 4
#define CIN 64
#define HH 128
#define WW 128
#define COUT 128
#define NTAP 10            // 9 deform taps + 1 center-correction tap
#define NOFF 18

// ---- scratch (no allocations allowed) ----
__device__ float g_x_nhwc[NB * HH * WW * CIN];          // 16.8 MB
__device__ float g_toff[NB * NOFF * HH * WW];           // 4.7 MB, NCHW
__device__ __half g_Ah[NTAP * COUT * 64];               // fused GEMM A (fp16): [tap][o][c]
__device__ __nv_bfloat16 g_Aoff[2 * 32 * 576];          // offset-conv A: [hi/lo][o(32)][k=t*64+c]

// ============================================================
// helpers
// ============================================================
__device__ __forceinline__ void mma_bf16(float* c, const uint32_t* a, const uint32_t* b) {
    asm volatile(
        "mma.sync.aligned.m16n8k16.row.col.f32.bf16.bf16.f32 "
        "{%0,%1,%2,%3}, {%4,%5,%6,%7}, {%8,%9}, {%0,%1,%2,%3};"
        : "+f"(c[0]), "+f"(c[1]), "+f"(c[2]), "+f"(c[3])
        : "r"(a[0]), "r"(a[1]), "r"(a[2]), "r"(a[3]), "r"(b[0]), "r"(b[1]));
}
__device__ __forceinline__ void mma_fp16(float* c, const uint32_t* a, const uint32_t* b) {
    asm volatile(
        "mma.sync.aligned.m16n8k16.row.col.f32.f16.f16.f32 "
        "{%0,%1,%2,%3}, {%4,%5,%6,%7}, {%8,%9}, {%0,%1,%2,%3};"
        : "+f"(c[0]), "+f"(c[1]), "+f"(c[2]), "+f"(c[3])
        : "r"(a[0]), "r"(a[1]), "r"(a[2]), "r"(a[3]), "r"(b[0]), "r"(b[1]));
}
__device__ __forceinline__ void ldsm_x4(uint32_t addr, uint32_t* r) {
    asm volatile("ldmatrix.sync.aligned.m8n8.x4.shared.b16 {%0,%1,%2,%3}, [%4];"
                 : "=r"(r[0]), "=r"(r[1]), "=r"(r[2]), "=r"(r[3]) : "r"(addr));
}
__device__ __forceinline__ uint32_t smem_u32(const void* p) {
    uint32_t a;
    asm("{ .reg .u64 t; cvta.to.shared.u64 t, %1; cvt.u32.u64 %0, t; }" : "=r"(a) : "l"(p));
    return a;
}
__device__ __forceinline__ void cp_async16(uint32_t dst, const void* src) {
    asm volatile("cp.async.cg.shared.global [%0], [%1], 16;" :: "r"(dst), "l"(src) : "memory");
}
__device__ __forceinline__ void cp_commit() {
    asm volatile("cp.async.commit_group;" ::: "memory");
}
__device__ __forceinline__ void cp_wait0() {
    asm volatile("cp.async.wait_group 0;" ::: "memory");
}
// bf16 hi/lo split store (off_mma only)
__device__ __forceinline__ void split_store(__nv_bfloat16* hi_p, __nv_bfloat16* lo_p, float4 v) {
    __nv_bfloat16 b0 = __float2bfloat16(v.x);
    __nv_bfloat16 b1 = __float2bfloat16(v.y);
    __nv_bfloat16 b2 = __float2bfloat16(v.z);
    __nv_bfloat16 b3 = __float2bfloat16(v.w);
    __nv_bfloat162 hA = __halves2bfloat162(b0, b1);
    __nv_bfloat162 hB = __halves2bfloat162(b2, b3);
    __nv_bfloat162 lA = __halves2bfloat162(
        __float2bfloat16(v.x - __bfloat162float(b0)),
        __float2bfloat16(v.y - __bfloat162float(b1)));
    __nv_bfloat162 lB = __halves2bfloat162(
        __float2bfloat16(v.z - __bfloat162float(b2)),
        __float2bfloat16(v.w - __bfloat162float(b3)));
    *(uint2*)hi_p = make_uint2(*(uint32_t*)&hA, *(uint32_t*)&hB);
    *(uint2*)lo_p = make_uint2(*(uint32_t*)&lA, *(uint32_t*)&lB);
}
// fp16 plain store (fused_mma)
__device__ __forceinline__ void h4_store(__half* p, float4 v) {
    __half2 h01 = __float22half2_rn(make_float2(v.x, v.y));
    __half2 h23 = __float22half2_rn(make_float2(v.z, v.w));
    *(uint2*)p = make_uint2(*(uint32_t*)&h01, *(uint32_t*)&h23);
}

// ============================================================
// Precompute: fused A (fp16) + offset-conv A (bf16 hi/lo)
// ============================================================
__global__ void prep_kernel(const float* __restrict__ w_off,
                            const float* __restrict__ w_deform,
                            const float* __restrict__ w_pw) {
    int tid = blockIdx.x * blockDim.x + threadIdx.x;
    int stride = gridDim.x * blockDim.x;

    for (int i = tid; i < NTAP * CIN * COUT; i += stride) {
        int o = i & 127;
        int k = i >> 7;
        int p = k >> 6;
        int c = k & 63;
        float acc = 0.f;
        if (p < 9) {
            #pragma unroll
            for (int d = 0; d < 4; ++d)
                acc += w_pw[o * 256 + c * 4 + d] * w_deform[(c * 4 + d) * 9 + p];
        } else {
            #pragma unroll
            for (int d = 0; d < 4; ++d) {
                float ws = 0.f;
                #pragma unroll
                for (int pp = 0; pp < 9; ++pp) ws += w_deform[(c * 4 + d) * 9 + pp];
                acc -= w_pw[o * 256 + c * 4 + d] * ws;
            }
        }
        g_Ah[p * 8192 + o * 64 + c] = __float2half_rn(acc);
    }

    for (int i = tid; i < 32 * 576; i += stride) {
        int k = i % 576;
        int o = i / 576;
        int t = k >> 6;
        int c = k & 63;
        float v = 0.f;
        if (o < NOFF) {
            const float* wp = w_off + (o * CIN + c) * 9;
            v = wp[t];
            if (t == 4) {
                float s = 0.f;
                #pragma unroll
                for (int tt = 0; tt < 9; ++tt) s += wp[tt];
                v -= s;
            }
        }
        __nv_bfloat16 hi = __float2bfloat16(v);
        __nv_bfloat16 lo = __float2bfloat16(v - __bfloat162float(hi));
        g_Aoff[0 * 18432 + o * 576 + k] = hi;
        g_Aoff[1 * 18432 + o * 576 + k] = lo;
    }
}

// ============================================================
// NCHW -> NHWC transpose of x
// ============================================================
__global__ void transpose_kernel(const float* __restrict__ x) {
    __shared__ float tile[CIN][33];
    int b = blockIdx.x;
    int wt = b & 3;
    int h  = (b >> 2) & 127;
    int n  = b >> 9;
    int w0 = wt * 32;

    for (int i = threadIdx.x; i < CIN * 32; i += 256) {
        int c = i >> 5, w = i & 31;
        tile[c][w] = x[((n * CIN + c) * HH + h) * WW + w0 + w];
    }
    __syncthreads();
    for (int i = threadIdx.x; i < CIN * 32; i += 256) {
        int w = i >> 6, c = i & 63;
        g_x_nhwc[((n * HH + h) * WW + w0 + w) * CIN + c] = tile[c][w];
    }
}

// ============================================================
// Offset conv as tensor-core GEMM (unchanged, proven, bf16x3).
// ============================================================
#define XROW 72
#define XPIX 130
#define XPLANE (3 * XPIX * XROW)
#define AOP 584
#define APLANE (32 * AOP)
#define OFF_SM_X 0
#define OFF_SM_A (2 * XPLANE * 2)
#define OFF_SM_TOTAL (OFF_SM_A + 2 * APLANE * 2)

__global__ void __launch_bounds__(512, 1) off_mma(const float* __restrict__ b_off) {
    extern __shared__ char sm[];
    __nv_bfloat16* Xs = (__nv_bfloat16*)(sm + OFF_SM_X);
    __nv_bfloat16* Aw = (__nv_bfloat16*)(sm + OFF_SM_A);

    int tid = threadIdx.x, wid = tid >> 5, lid = tid & 31;
    int g = lid >> 2, tq = lid & 3;
    int n = blockIdx.x >> 7, h = blockIdx.x & 127;
    int nw = wid * 8;

    for (int j = tid; j < 4608; j += 512) {
        int pl = j / 2304, rem = j % 2304;
        int o = rem / 72, seg = rem % 72;
        *(uint4*)&Aw[pl * APLANE + o * AOP + seg * 8] =
            *(const uint4*)&g_Aoff[pl * 18432 + o * 576 + seg * 8];
    }

    const float* xb = g_x_nhwc + (size_t)n * (HH * WW * CIN);
    for (int e = tid; e < 6240; e += 512) {
        int r = e / 2080, rem = e % 2080;
        int p = rem >> 4, c0 = (rem & 15) * 4;
        int row = h - 1 + r, w = p - 1;
        float4 v = make_float4(0.f, 0.f, 0.f, 0.f);
        if ((unsigned)row < (unsigned)HH && (unsigned)w < (unsigned)WW)
            v = *(const float4*)&xb[(row * WW + w) * CIN + c0];
        int off = r * (XPIX * XROW) + p * XROW + c0;
        split_store(&Xs[off], &Xs[XPLANE + off], v);
    }
    __syncthreads();

    float acc[2][4];
    #pragma unroll
    for (int mi = 0; mi < 2; ++mi)
        #pragma unroll
        for (int r = 0; r < 4; ++r) acc[mi][r] = 0.f;

    #pragma unroll
    for (int t = 0; t < 9; ++t) {
        int ky = t / 3, kx = t % 3;
        #pragma unroll
        for (int ks = 0; ks < 4; ++ks) {
            int k0 = ks * 16;
            uint32_t a[2][2][4], b[2][2];
            #pragma unroll
            for (int pl = 0; pl < 2; ++pl) {
                #pragma unroll
                for (int mi = 0; mi < 2; ++mi) {
                    const __nv_bfloat16* ap =
                        Aw + pl * APLANE + (mi * 16 + g) * AOP + t * 64 + k0 + 2 * tq;
                    a[pl][mi][0] = *(const uint32_t*)(ap);
                    a[pl][mi][1] = *(const uint32_t*)(ap + 8 * AOP);
                    a[pl][mi][2] = *(const uint32_t*)(ap + 8);
                    a[pl][mi][3] = *(const uint32_t*)(ap + 8 * AOP + 8);
                }
                const __nv_bfloat16* bp =
                    Xs + pl * XPLANE + ky * (XPIX * XROW) + (nw + g + kx) * XROW + k0 + 2 * tq;
                b[pl][0] = *(const uint32_t*)(bp);
                b[pl][1] = *(const uint32_t*)(bp + 8);
            }
            #pragma unroll
            for (int mi = 0; mi < 2; ++mi) {
                mma_bf16(acc[mi], a[0][mi], b[0]);
                mma_bf16(acc[mi], a[0][mi], b[1]);
                mma_bf16(acc[mi], a[1][mi], b[0]);
            }
        }
    }

    int pix = nw + 2 * tq;
    #pragma unroll
    for (int mi = 0; mi < 2; ++mi) {
        int oa = mi * 16 + g;
        int ob = oa + 8;
        if (oa < NOFF) {
            float bb = __ldg(&b_off[oa]);
            *(float2*)&g_toff[((n * NOFF + oa) * HH + h) * WW + pix] =
                make_float2(acc[mi][0] + bb, acc[mi][1] + bb);
        }
        if (ob < NOFF) {
            float bb = __ldg(&b_off[ob]);
            *(float2*)&g_toff[((n * NOFF + ob) * HH + h) * WW + pix] =
                make_float2(acc[mi][2] + bb, acc[mi][3] + bb);
        }
    }
}

// ============================================================
// Fused deform-sample + single-pass fp16 GEMM.
// R9: 256-thread CTAs, M=128 x N=64, 55KB smem -> 3 CTAs/SM.
// ============================================================
#define PADK 72
#define NPIX 64
#define BTILE (NPIX * PADK)                  // 4608 halfs = 9216 B per buf
#define SM_PAR 0                             // 8 * 576 * 4 = 18432 B
#define SM_A 18432                           // 128*72*2B = 18432 B (single buf)
#define SM_B (18432 + 18432)                 // 2 bufs * 9216 B
#define SM_TOTAL (SM_B + 18432)              // 55296 B

__global__ void __launch_bounds__(256, 3) fused_mma(float* __restrict__ out) {
    extern __shared__ char sm[];
    float* sW = (float*)(sm + SM_PAR);
    int*   sO = (int*)(sm + SM_PAR + 4 * 576 * 4);
    __half* Bs = (__half*)(sm + SM_B);
    uint32_t smbA = smem_u32(sm + SM_A);
    uint32_t smbB = smem_u32(sm + SM_B);

    int tid = threadIdx.x, wid = tid >> 5, lid = tid & 31;
    int n  = blockIdx.x >> 8;
    int h  = (blockIdx.x >> 1) & 127;
    int w0 = (blockIdx.x & 1) * NPIX;
    int g = lid >> 2, tq = lid & 3;
    int m0 = (wid & 3) * 32;
    int n0 = (wid >> 2) * 32;

    uint32_t aBase = (uint32_t)(((m0 + (lid & 15)) * PADK + ((lid >> 4) << 3)) * 2);
    uint32_t bBase = (uint32_t)(((n0 + (lid & 7) + ((lid >> 4) << 3)) * PADK
                                 + (((lid >> 3) & 1) << 3)) * 2);

    // ---- bilinear params per (tap, pixel): 9*64 = 576 entries ----
    for (int i = tid; i < 9 * NPIX; i += 256) {
        int p = i >> 6, pix = i & 63;
        int w = w0 + pix;
        float dy = g_toff[((n * NOFF + 2 * p    ) * HH + h) * WW + w];
        float dx = g_toff[((n * NOFF + 2 * p + 1) * HH + h) * WW + w];
        float py = dy + (float)(h - 1 + p / 3);
        float px = dx + (float)(w - 1 + p % 3);
        float y0f = floorf(py), x0f = floorf(px);
        int y0 = (int)y0f, x0 = (int)x0f;
        float wy1 = py - y0f, wx1 = px - x0f;
        float wy0 = 1.f - wy1, wx0 = 1.f - wx1;
        bool vy0 = (unsigned)y0 < (unsigned)HH, vy1 = (unsigned)(y0 + 1) < (unsigned)HH;
        bool vx0 = (unsigned)x0 < (unsigned)WW, vx1 = (unsigned)(x0 + 1) < (unsigned)WW;
        int cy0 = min(max(y0, 0), HH - 1), cy1 = min(max(y0 + 1, 0), HH - 1);
        int cx0 = min(max(x0, 0), WW - 1), cx1 = min(max(x0 + 1, 0), WW - 1);
        sW[0 * 576 + i] = (vy0 && vx0) ? wy0 * wx0 : 0.f;
        sW[1 * 576 + i] = (vy0 && vx1) ? wy0 * wx1 : 0.f;
        sW[2 * 576 + i] = (vy1 && vx0) ? wy1 * wx0 : 0.f;
        sW[3 * 576 + i] = (vy1 && vx1) ? wy1 * wx1 : 0.f;
        sO[0 * 576 + i] = (cy0 * WW + cx0) * CIN;
        sO[1 * 576 + i] = (cy0 * WW + cx1) * CIN;
        sO[2 * 576 + i] = (cy1 * WW + cx0) * CIN;
        sO[3 * 576 + i] = (cy1 * WW + cx1) * CIN;
    }

    const float* xb = g_x_nhwc + (size_t)n * (HH * WW * CIN);

    // ---- prologue: A(0) via cp.async (single buffer, 16KB) ----
    #pragma unroll
    for (int m = 0; m < 4; ++m) {
        int j = tid + 256 * m;
        int row = j >> 3, seg = j & 7;
        cp_async16(smbA + (uint32_t)(row * 144 + seg * 16), g_Ah + j * 8);
    }
    cp_commit();
    __syncthreads();   // params visible

    // ---- prologue: B(0) gathered inline into buf 0 ----
    #pragma unroll
    for (int sub = 0; sub < 4; ++sub) {
        int e = tid + 256 * sub;
        int pix = e >> 4, c0 = (e & 15) * 4;
        int i = pix;   // tap 0
        float w00 = sW[i], w01 = sW[576 + i], w10 = sW[2 * 576 + i], w11 = sW[3 * 576 + i];
        float4 v00 = *(const float4*)&xb[sO[i] + c0];
        float4 v01 = *(const float4*)&xb[sO[576 + i] + c0];
        float4 v10 = *(const float4*)&xb[sO[2 * 576 + i] + c0];
        float4 v11 = *(const float4*)&xb[sO[3 * 576 + i] + c0];
        float4 v;
        v.x = w00 * v00.x + w01 * v01.x + w10 * v10.x + w11 * v11.x;
        v.y = w00 * v00.y + w01 * v01.y + w10 * v10.y + w11 * v11.y;
        v.z = w00 * v00.z + w01 * v01.z + w10 * v10.z + w11 * v11.z;
        v.w = w00 * v00.w + w01 * v01.w + w10 * v10.w + w11 * v11.w;
        h4_store(&Bs[pix * PADK + c0], v);
    }

    float acc[2][4][4];
    #pragma unroll
    for (int mi = 0; mi < 2; ++mi)
        #pragma unroll
        for (int nj = 0; nj < 4; ++nj)
            #pragma unroll
            for (int r = 0; r < 4; ++r) acc[mi][nj][r] = 0.f;

    for (int t = 0; t < NTAP; ++t) {
        cp_wait0();
        __syncthreads();   // A(t) + B(t) ready
        bool pf = (t < 9);

        uint32_t bBuf = smbB + (uint32_t)((t & 1) * 9216) + bBase;
        __half* Bnx = Bs + ((t + 1) & 1) * BTILE;

        #pragma unroll
        for (int sub = 0; sub < 4; ++sub) {
            // -- issue gather loads for tap t+1 --
            float4 v00, v01, v10, v11;
            float w00, w01, w10, w11;
            int pix = 0, c0 = 0;
            bool center = (t + 1 == 9);
            if (pf) {
                int e = tid + 256 * sub;
                pix = e >> 4; c0 = (e & 15) * 4;
                if (center) {
                    v00 = *(const float4*)&xb[(h * WW + w0 + pix) * CIN + c0];
                } else {
                    int i = (t + 1) * NPIX + pix;
                    w00 = sW[i]; w01 = sW[576 + i]; w10 = sW[2 * 576 + i]; w11 = sW[3 * 576 + i];
                    v00 = *(const float4*)&xb[sO[i] + c0];
                    v01 = *(const float4*)&xb[sO[576 + i] + c0];
                    v10 = *(const float4*)&xb[sO[2 * 576 + i] + c0];
                    v11 = *(const float4*)&xb[sO[3 * 576 + i] + c0];
                }
            }

            // -- MMA k-step 'sub' of tap t: 4 ldsm + 8 HMMA --
            {
                uint32_t kOff = (uint32_t)(sub * 16 * 2);
                uint32_t a[2][4], bfr[2][4];
                #pragma unroll
                for (int mi = 0; mi < 2; ++mi)
                    ldsm_x4(smbA + aBase + (uint32_t)(mi * 16 * PADK * 2) + kOff, a[mi]);
                #pragma unroll
                for (int njp = 0; njp < 2; ++njp)
                    ldsm_x4(bBuf + (uint32_t)(njp * 16 * PADK * 2) + kOff, bfr[njp]);
                #pragma unroll
                for (int mi = 0; mi < 2; ++mi)
                    #pragma unroll
                    for (int nj = 0; nj < 4; ++nj)
                        mma_fp16(acc[mi][nj], a[mi], bfr[nj >> 1] + (nj & 1) * 2);
            }

            // -- finish gather: combine, convert, STS into next buffer --
            if (pf) {
                float4 v;
                if (center) {
                    v = v00;
                } else {
                    v.x = w00 * v00.x + w01 * v01.x + w10 * v10.x + w11 * v11.x;
                    v.y = w00 * v00.y + w01 * v01.y + w10 * v10.y + w11 * v11.y;
                    v.z = w00 * v00.z + w01 * v01.z + w10 * v10.z + w11 * v11.z;
                    v.w = w00 * v00.w + w01 * v01.w + w10 * v10.w + w11 * v11.w;
                }
                h4_store(&Bnx[pix * PADK + c0], v);
            }
        }

        __syncthreads();   // all reads of single-buffered A(t) done
        if (pf) {
            const __half* asrc = g_Ah + (t + 1) * 8192;
            #pragma unroll
            for (int m = 0; m < 4; ++m) {
                int j = tid + 256 * m;
                int row = j >> 3, seg = j & 7;
                cp_async16(smbA + (uint32_t)(row * 144 + seg * 16), asrc + j * 8);
            }
            cp_commit();
        }
    }

    // ---- epilogue: direct stores, NCHW ----
    #pragma unroll
    for (int mi = 0; mi < 2; ++mi) {
        #pragma unroll
        for (int nj = 0; nj < 4; ++nj) {
            int o = m0 + mi * 16 + g;
            int pix = w0 + n0 + nj * 8 + 2 * tq;
            float* op = out + (((size_t)n * COUT + o) * HH + h) * WW + pix;
            *(float2*)op = make_float2(acc[mi][nj][0], acc[mi][nj][1]);
            *(float2*)(op + 8 * HH * WW) = make_float2(acc[mi][nj][2], acc[mi][nj][3]);
        }
    }
}

// ============================================================
extern "C" void kernel_launch(void* const* d_in, const int* in_sizes, int n_in,
                              void* d_out, int out_size) {
    const float* x        = (const float*)d_in[0];
    const float* w_off    = (const float*)d_in[1];
    const float* b_off    = (const float*)d_in[2];
    const float* w_deform = (const float*)d_in[3];
    const float* w_pw     = (const float*)d_in[4];
    float* out = (float*)d_out;

    cudaFuncSetAttribute(off_mma,
                         cudaFuncAttributeMaxDynamicSharedMemorySize, OFF_SM_TOTAL);
    cudaFuncSetAttribute(fused_mma,
                         cudaFuncAttributeMaxDynamicSharedMemorySize, SM_TOTAL);

    prep_kernel<<<320, 256>>>(w_off, w_deform, w_pw);
    transpose_kernel<<<2048, 256>>>(x);
    off_mma<<<NB * HH, 512, OFF_SM_TOTAL>>>(b_off);
    fused_mma<<<NB * HH * 2, 256, SM_TOTAL>>>(out);
}

// round 10
// speedup vs baseline: 4.6445x; 1.3737x over previous
#include <cuda_runtime.h>
#include <cuda_fp16.h>
#include <cstdint>

#define NB 4
#define CIN 64
#define HH 128
#define WW 128
#define COUT 128
#define NTAP 10            // 9 deform taps + 1 center-correction tap
#define NOFF 18

// ---- scratch (no allocations allowed) ----
__device__ __half g_xh[NB * HH * WW * CIN];             // 8.4 MB, NHWC fp16
__device__ float g_toff[NB * NOFF * HH * WW];           // 4.7 MB, NCHW
__device__ __half g_Ah[NTAP * COUT * 64];               // fused GEMM A (fp16): [tap][o][c]
__device__ __half g_Aoffh[32 * 576];                    // offset-conv A (fp16): [o(32)][k]

// ============================================================
// helpers
// ============================================================
__device__ __forceinline__ void mma_fp16(float* c, const uint32_t* a, const uint32_t* b) {
    asm volatile(
        "mma.sync.aligned.m16n8k16.row.col.f32.f16.f16.f32 "
        "{%0,%1,%2,%3}, {%4,%5,%6,%7}, {%8,%9}, {%0,%1,%2,%3};"
        : "+f"(c[0]), "+f"(c[1]), "+f"(c[2]), "+f"(c[3])
        : "r"(a[0]), "r"(a[1]), "r"(a[2]), "r"(a[3]), "r"(b[0]), "r"(b[1]));
}
__device__ __forceinline__ void ldsm_x4(uint32_t addr, uint32_t* r) {
    asm volatile("ldmatrix.sync.aligned.m8n8.x4.shared.b16 {%0,%1,%2,%3}, [%4];"
                 : "=r"(r[0]), "=r"(r[1]), "=r"(r[2]), "=r"(r[3]) : "r"(addr));
}
__device__ __forceinline__ uint32_t smem_u32(const void* p) {
    uint32_t a;
    asm("{ .reg .u64 t; cvta.to.shared.u64 t, %1; cvt.u32.u64 %0, t; }" : "=r"(a) : "l"(p));
    return a;
}
__device__ __forceinline__ void cp_async16(uint32_t dst, const void* src) {
    asm volatile("cp.async.cg.shared.global [%0], [%1], 16;" :: "r"(dst), "l"(src) : "memory");
}
__device__ __forceinline__ void cp_commit() {
    asm volatile("cp.async.commit_group;" ::: "memory");
}
__device__ __forceinline__ void cp_wait0() {
    asm volatile("cp.async.wait_group 0;" ::: "memory");
}
__device__ __forceinline__ void h4_store(__half* p, float4 v) {
    __half2 h01 = __float22half2_rn(make_float2(v.x, v.y));
    __half2 h23 = __float22half2_rn(make_float2(v.z, v.w));
    *(uint2*)p = make_uint2(*(uint32_t*)&h01, *(uint32_t*)&h23);
}
__device__ __forceinline__ float4 h4_load(const __half* p) {
    uint2 u = *(const uint2*)p;
    float2 f0 = __half22float2(*(__half2*)&u.x);
    float2 f1 = __half22float2(*(__half2*)&u.y);
    return make_float4(f0.x, f0.y, f1.x, f1.y);
}

// ============================================================
// Precompute: fused A (fp16) + offset-conv A (fp16)
// ============================================================
__global__ void prep_kernel(const float* __restrict__ w_off,
                            const float* __restrict__ w_deform,
                            const float* __restrict__ w_pw) {
    int tid = blockIdx.x * blockDim.x + threadIdx.x;
    int stride = gridDim.x * blockDim.x;

    for (int i = tid; i < NTAP * CIN * COUT; i += stride) {
        int o = i & 127;
        int k = i >> 7;
        int p = k >> 6;
        int c = k & 63;
        float acc = 0.f;
        if (p < 9) {
            #pragma unroll
            for (int d = 0; d < 4; ++d)
                acc += w_pw[o * 256 + c * 4 + d] * w_deform[(c * 4 + d) * 9 + p];
        } else {
            #pragma unroll
            for (int d = 0; d < 4; ++d) {
                float ws = 0.f;
                #pragma unroll
                for (int pp = 0; pp < 9; ++pp) ws += w_deform[(c * 4 + d) * 9 + pp];
                acc -= w_pw[o * 256 + c * 4 + d] * ws;
            }
        }
        g_Ah[p * 8192 + o * 64 + c] = __float2half_rn(acc);
    }

    for (int i = tid; i < 32 * 576; i += stride) {
        int k = i % 576;
        int o = i / 576;
        int t = k >> 6;
        int c = k & 63;
        float v = 0.f;
        if (o < NOFF) {
            const float* wp = w_off + (o * CIN + c) * 9;
            v = wp[t];
            if (t == 4) {
                float s = 0.f;
                #pragma unroll
                for (int tt = 0; tt < 9; ++tt) s += wp[tt];
                v -= s;
            }
        }
        g_Aoffh[o * 576 + k] = __float2half_rn(v);
    }
}

// ============================================================
// NCHW -> NHWC fp16 transpose of x
// ============================================================
__global__ void transpose_kernel(const float* __restrict__ x) {
    __shared__ float tile[CIN][33];
    int b = blockIdx.x;
    int wt = b & 3;
    int h  = (b >> 2) & 127;
    int n  = b >> 9;
    int w0 = wt * 32;

    for (int i = threadIdx.x; i < CIN * 32; i += 256) {
        int c = i >> 5, w = i & 31;
        tile[c][w] = x[((n * CIN + c) * HH + h) * WW + w0 + w];
    }
    __syncthreads();
    for (int i = threadIdx.x; i < 32 * 32; i += 256) {
        int w = i >> 5, cp = i & 31;
        __half2 hv = __float22half2_rn(make_float2(tile[2 * cp][w], tile[2 * cp + 1][w]));
        *(__half2*)&g_xh[((n * HH + h) * WW + w0 + w) * CIN + 2 * cp] = hv;
    }
}

// ============================================================
// Offset conv as single-pass fp16 tensor-core GEMM. Block = (n,h) row.
// M=32 (18 used), N=128 pixels, K=576. Taps are shifted views of 3
// staged fp16 x rows (h-1,h,h+1), 130 px wide, zero-padded.
// ============================================================
#define XROW 72
#define XPIX 130
#define XPLANE (3 * XPIX * XROW)          // 28080 halfs = 56160 B
#define AOP 584
#define OFF_SM_X 0
#define OFF_SM_A (XPLANE * 2)             // 56160
#define OFF_SM_TOTAL (OFF_SM_A + 32 * AOP * 2)   // 93536 B

__global__ void __launch_bounds__(512, 1) off_mma(const float* __restrict__ b_off) {
    extern __shared__ char sm[];
    __half* Xs = (__half*)(sm + OFF_SM_X);   // [r][pix130][72]
    __half* Aw = (__half*)(sm + OFF_SM_A);   // [o32][584]

    int tid = threadIdx.x, wid = tid >> 5, lid = tid & 31;
    int g = lid >> 2, tq = lid & 3;
    int n = blockIdx.x >> 7, h = blockIdx.x & 127;
    int nw = wid * 8;

    // stage A (fp16, padded pitch)
    for (int j = tid; j < 2304; j += 512) {
        int o = j / 72, seg = j % 72;
        *(uint4*)&Aw[o * AOP + seg * 8] = *(const uint4*)&g_Aoffh[o * 576 + seg * 8];
    }

    // stage 3 fp16 x rows, zero-padded: 3*130*8 = 3120 uint4 chunks
    const __half* xb = g_xh + (size_t)n * (HH * WW * CIN);
    for (int e = tid; e < 3120; e += 512) {
        int r = e / 1040, rem = e % 1040;
        int p = rem >> 3, seg = rem & 7;
        int c0 = seg * 8;
        int row = h - 1 + r, w = p - 1;
        uint4 v = make_uint4(0, 0, 0, 0);
        if ((unsigned)row < (unsigned)HH && (unsigned)w < (unsigned)WW)
            v = *(const uint4*)&xb[(row * WW + w) * CIN + c0];
        *(uint4*)&Xs[r * (XPIX * XROW) + p * XROW + c0] = v;
    }
    __syncthreads();

    float acc[2][4];
    #pragma unroll
    for (int mi = 0; mi < 2; ++mi)
        #pragma unroll
        for (int r = 0; r < 4; ++r) acc[mi][r] = 0.f;

    #pragma unroll
    for (int t = 0; t < 9; ++t) {
        int ky = t / 3, kx = t % 3;
        #pragma unroll
        for (int ks = 0; ks < 4; ++ks) {
            int k0 = ks * 16;
            uint32_t a[2][4], b[2];
            #pragma unroll
            for (int mi = 0; mi < 2; ++mi) {
                const __half* ap = Aw + (mi * 16 + g) * AOP + t * 64 + k0 + 2 * tq;
                a[mi][0] = *(const uint32_t*)(ap);
                a[mi][1] = *(const uint32_t*)(ap + 8 * AOP);
                a[mi][2] = *(const uint32_t*)(ap + 8);
                a[mi][3] = *(const uint32_t*)(ap + 8 * AOP + 8);
            }
            const __half* bp = Xs + ky * (XPIX * XROW) + (nw + g + kx) * XROW + k0 + 2 * tq;
            b[0] = *(const uint32_t*)(bp);
            b[1] = *(const uint32_t*)(bp + 8);
            #pragma unroll
            for (int mi = 0; mi < 2; ++mi)
                mma_fp16(acc[mi], a[mi], b);
        }
    }

    int pix = nw + 2 * tq;
    #pragma unroll
    for (int mi = 0; mi < 2; ++mi) {
        int oa = mi * 16 + g;
        int ob = oa + 8;
        if (oa < NOFF) {
            float bb = __ldg(&b_off[oa]);
            *(float2*)&g_toff[((n * NOFF + oa) * HH + h) * WW + pix] =
                make_float2(acc[mi][0] + bb, acc[mi][1] + bb);
        }
        if (ob < NOFF) {
            float bb = __ldg(&b_off[ob]);
            *(float2*)&g_toff[((n * NOFF + ob) * HH + h) * WW + pix] =
                make_float2(acc[mi][2] + bb, acc[mi][3] + bb);
        }
    }
}

// ============================================================
// Fused deform-sample + single-pass fp16 GEMM, fp16 x source.
// 256-thread CTAs, M=128 x N=64, 55KB smem -> 3 CTAs/SM.
// ============================================================
#define PADK 72
#define NPIX 64
#define BTILE (NPIX * PADK)                  // 4608 halfs = 9216 B per buf
#define SM_PAR 0                             // 8 * 576 * 4 = 18432 B
#define SM_A 18432                           // 128*72*2B = 18432 B (single buf)
#define SM_B (18432 + 18432)                 // 2 bufs * 9216 B
#define SM_TOTAL (SM_B + 18432)              // 55296 B

__global__ void __launch_bounds__(256, 3) fused_mma(float* __restrict__ out) {
    extern __shared__ char sm[];
    float* sW = (float*)(sm + SM_PAR);
    int*   sO = (int*)(sm + SM_PAR + 4 * 576 * 4);
    __half* Bs = (__half*)(sm + SM_B);
    uint32_t smbA = smem_u32(sm + SM_A);
    uint32_t smbB = smem_u32(sm + SM_B);

    int tid = threadIdx.x, wid = tid >> 5, lid = tid & 31;
    int n  = blockIdx.x >> 8;
    int h  = (blockIdx.x >> 1) & 127;
    int w0 = (blockIdx.x & 1) * NPIX;
    int g = lid >> 2, tq = lid & 3;
    int m0 = (wid & 3) * 32;
    int n0 = (wid >> 2) * 32;

    uint32_t aBase = (uint32_t)(((m0 + (lid & 15)) * PADK + ((lid >> 4) << 3)) * 2);
    uint32_t bBase = (uint32_t)(((n0 + (lid & 7) + ((lid >> 4) << 3)) * PADK
                                 + (((lid >> 3) & 1) << 3)) * 2);

    // ---- bilinear params per (tap, pixel): 9*64 = 576 entries ----
    for (int i = tid; i < 9 * NPIX; i += 256) {
        int p = i >> 6, pix = i & 63;
        int w = w0 + pix;
        float dy = g_toff[((n * NOFF + 2 * p    ) * HH + h) * WW + w];
        float dx = g_toff[((n * NOFF + 2 * p + 1) * HH + h) * WW + w];
        float py = dy + (float)(h - 1 + p / 3);
        float px = dx + (float)(w - 1 + p % 3);
        float y0f = floorf(py), x0f = floorf(px);
        int y0 = (int)y0f, x0 = (int)x0f;
        float wy1 = py - y0f, wx1 = px - x0f;
        float wy0 = 1.f - wy1, wx0 = 1.f - wx1;
        bool vy0 = (unsigned)y0 < (unsigned)HH, vy1 = (unsigned)(y0 + 1) < (unsigned)HH;
        bool vx0 = (unsigned)x0 < (unsigned)WW, vx1 = (unsigned)(x0 + 1) < (unsigned)WW;
        int cy0 = min(max(y0, 0), HH - 1), cy1 = min(max(y0 + 1, 0), HH - 1);
        int cx0 = min(max(x0, 0), WW - 1), cx1 = min(max(x0 + 1, 0), WW - 1);
        sW[0 * 576 + i] = (vy0 && vx0) ? wy0 * wx0 : 0.f;
        sW[1 * 576 + i] = (vy0 && vx1) ? wy0 * wx1 : 0.f;
        sW[2 * 576 + i] = (vy1 && vx0) ? wy1 * wx0 : 0.f;
        sW[3 * 576 + i] = (vy1 && vx1) ? wy1 * wx1 : 0.f;
        sO[0 * 576 + i] = (cy0 * WW + cx0) * CIN;
        sO[1 * 576 + i] = (cy0 * WW + cx1) * CIN;
        sO[2 * 576 + i] = (cy1 * WW + cx0) * CIN;
        sO[3 * 576 + i] = (cy1 * WW + cx1) * CIN;
    }

    const __half* xb = g_xh + (size_t)n * (HH * WW * CIN);

    // ---- prologue: A(0) via cp.async (single buffer, 16KB) ----
    #pragma unroll
    for (int m = 0; m < 4; ++m) {
        int j = tid + 256 * m;
        int row = j >> 3, seg = j & 7;
        cp_async16(smbA + (uint32_t)(row * 144 + seg * 16), g_Ah + j * 8);
    }
    cp_commit();
    __syncthreads();   // params visible

    // ---- prologue: B(0) gathered inline into buf 0 ----
    #pragma unroll
    for (int sub = 0; sub < 4; ++sub) {
        int e = tid + 256 * sub;
        int pix = e >> 4, c0 = (e & 15) * 4;
        int i = pix;   // tap 0
        float w00 = sW[i], w01 = sW[576 + i], w10 = sW[2 * 576 + i], w11 = sW[3 * 576 + i];
        float4 v00 = h4_load(&xb[sO[i] + c0]);
        float4 v01 = h4_load(&xb[sO[576 + i] + c0]);
        float4 v10 = h4_load(&xb[sO[2 * 576 + i] + c0]);
        float4 v11 = h4_load(&xb[sO[3 * 576 + i] + c0]);
        float4 v;
        v.x = w00 * v00.x + w01 * v01.x + w10 * v10.x + w11 * v11.x;
        v.y = w00 * v00.y + w01 * v01.y + w10 * v10.y + w11 * v11.y;
        v.z = w00 * v00.z + w01 * v01.z + w10 * v10.z + w11 * v11.z;
        v.w = w00 * v00.w + w01 * v01.w + w10 * v10.w + w11 * v11.w;
        h4_store(&Bs[pix * PADK + c0], v);
    }

    float acc[2][4][4];
    #pragma unroll
    for (int mi = 0; mi < 2; ++mi)
        #pragma unroll
        for (int nj = 0; nj < 4; ++nj)
            #pragma unroll
            for (int r = 0; r < 4; ++r) acc[mi][nj][r] = 0.f;

    for (int t = 0; t < NTAP; ++t) {
        cp_wait0();
        __syncthreads();   // A(t) + B(t) ready
        bool pf = (t < 9);

        uint32_t bBuf = smbB + (uint32_t)((t & 1) * 9216) + bBase;
        __half* Bnx = Bs + ((t + 1) & 1) * BTILE;

        #pragma unroll
        for (int sub = 0; sub < 4; ++sub) {
            // -- issue gather loads for tap t+1 --
            float4 v00, v01, v10, v11;
            float w00, w01, w10, w11;
            int pix = 0, c0 = 0;
            bool center = (t + 1 == 9);
            if (pf) {
                int e = tid + 256 * sub;
                pix = e >> 4; c0 = (e & 15) * 4;
                if (center) {
                    v00 = h4_load(&xb[(h * WW + w0 + pix) * CIN + c0]);
                } else {
                    int i = (t + 1) * NPIX + pix;
                    w00 = sW[i]; w01 = sW[576 + i]; w10 = sW[2 * 576 + i]; w11 = sW[3 * 576 + i];
                    v00 = h4_load(&xb[sO[i] + c0]);
                    v01 = h4_load(&xb[sO[576 + i] + c0]);
                    v10 = h4_load(&xb[sO[2 * 576 + i] + c0]);
                    v11 = h4_load(&xb[sO[3 * 576 + i] + c0]);
                }
            }

            // -- MMA k-step 'sub' of tap t: 4 ldsm + 8 HMMA --
            {
                uint32_t kOff = (uint32_t)(sub * 16 * 2);
                uint32_t a[2][4], bfr[2][4];
                #pragma unroll
                for (int mi = 0; mi < 2; ++mi)
                    ldsm_x4(smbA + aBase + (uint32_t)(mi * 16 * PADK * 2) + kOff, a[mi]);
                #pragma unroll
                for (int njp = 0; njp < 2; ++njp)
                    ldsm_x4(bBuf + (uint32_t)(njp * 16 * PADK * 2) + kOff, bfr[njp]);
                #pragma unroll
                for (int mi = 0; mi < 2; ++mi)
                    #pragma unroll
                    for (int nj = 0; nj < 4; ++nj)
                        mma_fp16(acc[mi][nj], a[mi], bfr[nj >> 1] + (nj & 1) * 2);
            }

            // -- finish gather: combine, convert, STS into next buffer --
            if (pf) {
                float4 v;
                if (center) {
                    v = v00;
                } else {
                    v.x = w00 * v00.x + w01 * v01.x + w10 * v10.x + w11 * v11.x;
                    v.y = w00 * v00.y + w01 * v01.y + w10 * v10.y + w11 * v11.y;
                    v.z = w00 * v00.z + w01 * v01.z + w10 * v10.z + w11 * v11.z;
                    v.w = w00 * v00.w + w01 * v01.w + w10 * v10.w + w11 * v11.w;
                }
                h4_store(&Bnx[pix * PADK + c0], v);
            }
        }

        __syncthreads();   // all reads of single-buffered A(t) done
        if (pf) {
            const __half* asrc = g_Ah + (t + 1) * 8192;
            #pragma unroll
            for (int m = 0; m < 4; ++m) {
                int j = tid + 256 * m;
                int row = j >> 3, seg = j & 7;
                cp_async16(smbA + (uint32_t)(row * 144 + seg * 16), asrc + j * 8);
            }
            cp_commit();
        }
    }

    // ---- epilogue: direct stores, NCHW ----
    #pragma unroll
    for (int mi = 0; mi < 2; ++mi) {
        #pragma unroll
        for (int nj = 0; nj < 4; ++nj) {
            int o = m0 + mi * 16 + g;
            int pix = w0 + n0 + nj * 8 + 2 * tq;
            float* op = out + (((size_t)n * COUT + o) * HH + h) * WW + pix;
            *(float2*)op = make_float2(acc[mi][nj][0], acc[mi][nj][1]);
            *(float2*)(op + 8 * HH * WW) = make_float2(acc[mi][nj][2], acc[mi][nj][3]);
        }
    }
}

// ============================================================
extern "C" void kernel_launch(void* const* d_in, const int* in_sizes, int n_in,
                              void* d_out, int out_size) {
    const float* x        = (const float*)d_in[0];
    const float* w_off    = (const float*)d_in[1];
    const float* b_off    = (const float*)d_in[2];
    const float* w_deform = (const float*)d_in[3];
    const float* w_pw     = (const float*)d_in[4];
    float* out = (float*)d_out;

    cudaFuncSetAttribute(off_mma,
                         cudaFuncAttributeMaxDynamicSharedMemorySize, OFF_SM_TOTAL);
    cudaFuncSetAttribute(fused_mma,
                         cudaFuncAttributeMaxDynamicSharedMemorySize, SM_TOTAL);

    prep_kernel<<<320, 256>>>(w_off, w_deform, w_pw);
    transpose_kernel<<<2048, 256>>>(x);
    off_mma<<<NB * HH, 512, OFF_SM_TOTAL>>>(b_off);
    fused_mma<<<NB * HH * 2, 256, SM_TOTAL>>>(out);
}

// round 11
// speedup vs baseline: 4.7171x; 1.0156x over previous
#include <cuda_runtime.h>
#include <cuda_fp16.h>
#include <cstdint>

#define NB 4
#define CIN 64
#define HH 128
#define WW 128
#define COUT 128
#define NTAP 10            // 9 deform taps + 1 center-correction tap
#define NOFF 18

// ---- scratch (no allocations allowed) ----
__device__ __half g_xh[NB * HH * WW * CIN];             // 8.4 MB, NHWC fp16
__device__ float g_toff[NB * NOFF * HH * WW];           // 4.7 MB, NCHW
__device__ __half g_Ah[NTAP * COUT * 64];               // fused GEMM A (fp16): [tap][o][c]
__device__ __half g_Aoffh[32 * 576];                    // offset-conv A (fp16): [o(32)][k]

// ============================================================
// helpers
// ============================================================
__device__ __forceinline__ void mma_fp16(float* c, const uint32_t* a, const uint32_t* b) {
    asm volatile(
        "mma.sync.aligned.m16n8k16.row.col.f32.f16.f16.f32 "
        "{%0,%1,%2,%3}, {%4,%5,%6,%7}, {%8,%9}, {%0,%1,%2,%3};"
        : "+f"(c[0]), "+f"(c[1]), "+f"(c[2]), "+f"(c[3])
        : "r"(a[0]), "r"(a[1]), "r"(a[2]), "r"(a[3]), "r"(b[0]), "r"(b[1]));
}
__device__ __forceinline__ void ldsm_x4(uint32_t addr, uint32_t* r) {
    asm volatile("ldmatrix.sync.aligned.m8n8.x4.shared.b16 {%0,%1,%2,%3}, [%4];"
                 : "=r"(r[0]), "=r"(r[1]), "=r"(r[2]), "=r"(r[3]) : "r"(addr));
}
__device__ __forceinline__ uint32_t smem_u32(const void* p) {
    uint32_t a;
    asm("{ .reg .u64 t; cvta.to.shared.u64 t, %1; cvt.u32.u64 %0, t; }" : "=r"(a) : "l"(p));
    return a;
}
__device__ __forceinline__ void cp_async16(uint32_t dst, const void* src) {
    asm volatile("cp.async.cg.shared.global [%0], [%1], 16;" :: "r"(dst), "l"(src) : "memory");
}
__device__ __forceinline__ void cp_commit() {
    asm volatile("cp.async.commit_group;" ::: "memory");
}
__device__ __forceinline__ void cp_wait0() {
    asm volatile("cp.async.wait_group 0;" ::: "memory");
}
// fp16x2 bilinear combine of 8 channels (4 half2 lanes)
__device__ __forceinline__ uint4 comb8(uint4 q00, uint4 q01, uint4 q10, uint4 q11,
                                       __half2 w00, __half2 w01, __half2 w10, __half2 w11) {
    const __half2* a = (const __half2*)&q00;
    const __half2* b = (const __half2*)&q01;
    const __half2* c = (const __half2*)&q10;
    const __half2* d = (const __half2*)&q11;
    uint4 r;
    __half2* rr = (__half2*)&r;
    #pragma unroll
    for (int k = 0; k < 4; ++k) {
        __half2 s = __hmul2(a[k], w00);
        s = __hfma2(b[k], w01, s);
        s = __hfma2(c[k], w10, s);
        s = __hfma2(d[k], w11, s);
        rr[k] = s;
    }
    return r;
}

// ============================================================
// Precompute: fused A (fp16) + offset-conv A (fp16)
// ============================================================
__global__ void prep_kernel(const float* __restrict__ w_off,
                            const float* __restrict__ w_deform,
                            const float* __restrict__ w_pw) {
    int tid = blockIdx.x * blockDim.x + threadIdx.x;
    int stride = gridDim.x * blockDim.x;

    for (int i = tid; i < NTAP * CIN * COUT; i += stride) {
        int o = i & 127;
        int k = i >> 7;
        int p = k >> 6;
        int c = k & 63;
        float acc = 0.f;
        if (p < 9) {
            #pragma unroll
            for (int d = 0; d < 4; ++d)
                acc += w_pw[o * 256 + c * 4 + d] * w_deform[(c * 4 + d) * 9 + p];
        } else {
            #pragma unroll
            for (int d = 0; d < 4; ++d) {
                float ws = 0.f;
                #pragma unroll
                for (int pp = 0; pp < 9; ++pp) ws += w_deform[(c * 4 + d) * 9 + pp];
                acc -= w_pw[o * 256 + c * 4 + d] * ws;
            }
        }
        g_Ah[p * 8192 + o * 64 + c] = __float2half_rn(acc);
    }

    for (int i = tid; i < 32 * 576; i += stride) {
        int k = i % 576;
        int o = i / 576;
        int t = k >> 6;
        int c = k & 63;
        float v = 0.f;
        if (o < NOFF) {
            const float* wp = w_off + (o * CIN + c) * 9;
            v = wp[t];
            if (t == 4) {
                float s = 0.f;
                #pragma unroll
                for (int tt = 0; tt < 9; ++tt) s += wp[tt];
                v -= s;
            }
        }
        g_Aoffh[o * 576 + k] = __float2half_rn(v);
    }
}

// ============================================================
// NCHW -> NHWC fp16 transpose of x
// ============================================================
__global__ void transpose_kernel(const float* __restrict__ x) {
    __shared__ float tile[CIN][33];
    int b = blockIdx.x;
    int wt = b & 3;
    int h  = (b >> 2) & 127;
    int n  = b >> 9;
    int w0 = wt * 32;

    for (int i = threadIdx.x; i < CIN * 32; i += 256) {
        int c = i >> 5, w = i & 31;
        tile[c][w] = x[((n * CIN + c) * HH + h) * WW + w0 + w];
    }
    __syncthreads();
    for (int i = threadIdx.x; i < 32 * 32; i += 256) {
        int w = i >> 5, cp = i & 31;
        __half2 hv = __float22half2_rn(make_float2(tile[2 * cp][w], tile[2 * cp + 1][w]));
        *(__half2*)&g_xh[((n * HH + h) * WW + w0 + w) * CIN + 2 * cp] = hv;
    }
}

// ============================================================
// Offset conv as single-pass fp16 tensor-core GEMM (proven).
// ============================================================
#define XROW 72
#define XPIX 130
#define XPLANE (3 * XPIX * XROW)
#define AOP 584
#define OFF_SM_X 0
#define OFF_SM_A (XPLANE * 2)
#define OFF_SM_TOTAL (OFF_SM_A + 32 * AOP * 2)

__global__ void __launch_bounds__(512, 1) off_mma(const float* __restrict__ b_off) {
    extern __shared__ char sm[];
    __half* Xs = (__half*)(sm + OFF_SM_X);
    __half* Aw = (__half*)(sm + OFF_SM_A);

    int tid = threadIdx.x, wid = tid >> 5, lid = tid & 31;
    int g = lid >> 2, tq = lid & 3;
    int n = blockIdx.x >> 7, h = blockIdx.x & 127;
    int nw = wid * 8;

    for (int j = tid; j < 2304; j += 512) {
        int o = j / 72, seg = j % 72;
        *(uint4*)&Aw[o * AOP + seg * 8] = *(const uint4*)&g_Aoffh[o * 576 + seg * 8];
    }

    const __half* xb = g_xh + (size_t)n * (HH * WW * CIN);
    for (int e = tid; e < 3120; e += 512) {
        int r = e / 1040, rem = e % 1040;
        int p = rem >> 3, seg = rem & 7;
        int c0 = seg * 8;
        int row = h - 1 + r, w = p - 1;
        uint4 v = make_uint4(0, 0, 0, 0);
        if ((unsigned)row < (unsigned)HH && (unsigned)w < (unsigned)WW)
            v = *(const uint4*)&xb[(row * WW + w) * CIN + c0];
        *(uint4*)&Xs[r * (XPIX * XROW) + p * XROW + c0] = v;
    }
    __syncthreads();

    float acc[2][4];
    #pragma unroll
    for (int mi = 0; mi < 2; ++mi)
        #pragma unroll
        for (int r = 0; r < 4; ++r) acc[mi][r] = 0.f;

    #pragma unroll
    for (int t = 0; t < 9; ++t) {
        int ky = t / 3, kx = t % 3;
        #pragma unroll
        for (int ks = 0; ks < 4; ++ks) {
            int k0 = ks * 16;
            uint32_t a[2][4], b[2];
            #pragma unroll
            for (int mi = 0; mi < 2; ++mi) {
                const __half* ap = Aw + (mi * 16 + g) * AOP + t * 64 + k0 + 2 * tq;
                a[mi][0] = *(const uint32_t*)(ap);
                a[mi][1] = *(const uint32_t*)(ap + 8 * AOP);
                a[mi][2] = *(const uint32_t*)(ap + 8);
                a[mi][3] = *(const uint32_t*)(ap + 8 * AOP + 8);
            }
            const __half* bp = Xs + ky * (XPIX * XROW) + (nw + g + kx) * XROW + k0 + 2 * tq;
            b[0] = *(const uint32_t*)(bp);
            b[1] = *(const uint32_t*)(bp + 8);
            #pragma unroll
            for (int mi = 0; mi < 2; ++mi)
                mma_fp16(acc[mi], a[mi], b);
        }
    }

    int pix = nw + 2 * tq;
    #pragma unroll
    for (int mi = 0; mi < 2; ++mi) {
        int oa = mi * 16 + g;
        int ob = oa + 8;
        if (oa < NOFF) {
            float bb = __ldg(&b_off[oa]);
            *(float2*)&g_toff[((n * NOFF + oa) * HH + h) * WW + pix] =
                make_float2(acc[mi][0] + bb, acc[mi][1] + bb);
        }
        if (ob < NOFF) {
            float bb = __ldg(&b_off[ob]);
            *(float2*)&g_toff[((n * NOFF + ob) * HH + h) * WW + pix] =
                make_float2(acc[mi][2] + bb, acc[mi][3] + bb);
        }
    }
}

// ============================================================
// Fused deform-sample + fp16 GEMM.
// R11: A double-buffered (1 barrier/tap), 16B gather loads,
// gather pipelined across all 4 MMA k-steps, half2 combine.
// 256 threads, M=128 x N=64, 73.7KB smem -> 3 CTAs/SM.
// ============================================================
#define PADK 72
#define NPIX 64
#define BTILE (NPIX * PADK)                  // 4608 halfs = 9216 B per buf
#define SM_PAR 0                             // sWh 9216 + sO 9216 = 18432 B
#define SM_A 18432                           // 2 x 18432 B
#define SM_B (18432 + 36864)                 // 2 x 9216 B
#define SM_TOTAL (SM_B + 18432)              // 73728 B

__global__ void __launch_bounds__(256, 3) fused_mma(float* __restrict__ out) {
    extern __shared__ char sm[];
    __half2* sWh = (__half2*)(sm + SM_PAR);             // [4][576] broadcast weights
    int*     sO  = (int*)(sm + SM_PAR + 4 * 576 * 4);   // [4][576]
    __half* Bs = (__half*)(sm + SM_B);
    uint32_t smbA = smem_u32(sm + SM_A);
    uint32_t smbB = smem_u32(sm + SM_B);

    int tid = threadIdx.x, wid = tid >> 5, lid = tid & 31;
    int n  = blockIdx.x >> 8;
    int h  = (blockIdx.x >> 1) & 127;
    int w0 = (blockIdx.x & 1) * NPIX;
    int g = lid >> 2, tq = lid & 3;
    int m0 = (wid & 3) * 32;
    int n0 = (wid >> 2) * 32;

    uint32_t aBase = (uint32_t)(((m0 + (lid & 15)) * PADK + ((lid >> 4) << 3)) * 2);
    uint32_t bBase = (uint32_t)(((n0 + (lid & 7) + ((lid >> 4) << 3)) * PADK
                                 + (((lid >> 3) & 1) << 3)) * 2);

    // ---- bilinear params per (tap, pixel): 9*64 = 576 entries ----
    for (int i = tid; i < 9 * NPIX; i += 256) {
        int p = i >> 6, pix = i & 63;
        int w = w0 + pix;
        float dy = g_toff[((n * NOFF + 2 * p    ) * HH + h) * WW + w];
        float dx = g_toff[((n * NOFF + 2 * p + 1) * HH + h) * WW + w];
        float py = dy + (float)(h - 1 + p / 3);
        float px = dx + (float)(w - 1 + p % 3);
        float y0f = floorf(py), x0f = floorf(px);
        int y0 = (int)y0f, x0 = (int)x0f;
        float wy1 = py - y0f, wx1 = px - x0f;
        float wy0 = 1.f - wy1, wx0 = 1.f - wx1;
        bool vy0 = (unsigned)y0 < (unsigned)HH, vy1 = (unsigned)(y0 + 1) < (unsigned)HH;
        bool vx0 = (unsigned)x0 < (unsigned)WW, vx1 = (unsigned)(x0 + 1) < (unsigned)WW;
        int cy0 = min(max(y0, 0), HH - 1), cy1 = min(max(y0 + 1, 0), HH - 1);
        int cx0 = min(max(x0, 0), WW - 1), cx1 = min(max(x0 + 1, 0), WW - 1);
        float f00 = (vy0 && vx0) ? wy0 * wx0 : 0.f;
        float f01 = (vy0 && vx1) ? wy0 * wx1 : 0.f;
        float f10 = (vy1 && vx0) ? wy1 * wx0 : 0.f;
        float f11 = (vy1 && vx1) ? wy1 * wx1 : 0.f;
        sWh[0 * 576 + i] = __half2half2(__float2half_rn(f00));
        sWh[1 * 576 + i] = __half2half2(__float2half_rn(f01));
        sWh[2 * 576 + i] = __half2half2(__float2half_rn(f10));
        sWh[3 * 576 + i] = __half2half2(__float2half_rn(f11));
        sO[0 * 576 + i] = (cy0 * WW + cx0) * CIN;
        sO[1 * 576 + i] = (cy0 * WW + cx1) * CIN;
        sO[2 * 576 + i] = (cy1 * WW + cx0) * CIN;
        sO[3 * 576 + i] = (cy1 * WW + cx1) * CIN;
    }

    const __half* xb = g_xh + (size_t)n * (HH * WW * CIN);

    // ---- prologue: A(0) via cp.async into buf 0 ----
    #pragma unroll
    for (int m = 0; m < 4; ++m) {
        int j = tid + 256 * m;
        int row = j >> 3, seg = j & 7;
        cp_async16(smbA + (uint32_t)(row * 144 + seg * 16), g_Ah + j * 8);
    }
    cp_commit();
    __syncthreads();   // params visible

    // ---- prologue: B(0) gathered inline into buf 0 (tap 0) ----
    #pragma unroll
    for (int b = 0; b < 2; ++b) {
        int j = tid + 256 * b;
        int pix = j >> 3, c0 = (j & 7) * 8;
        int i = pix;   // tap 0
        uint4 q00 = *(const uint4*)&xb[sO[i] + c0];
        uint4 q01 = *(const uint4*)&xb[sO[576 + i] + c0];
        uint4 q10 = *(const uint4*)&xb[sO[2 * 576 + i] + c0];
        uint4 q11 = *(const uint4*)&xb[sO[3 * 576 + i] + c0];
        *(uint4*)&Bs[pix * PADK + c0] =
            comb8(q00, q01, q10, q11, sWh[i], sWh[576 + i], sWh[2 * 576 + i], sWh[3 * 576 + i]);
    }

    float acc[2][4][4];
    #pragma unroll
    for (int mi = 0; mi < 2; ++mi)
        #pragma unroll
        for (int nj = 0; nj < 4; ++nj)
            #pragma unroll
            for (int r = 0; r < 4; ++r) acc[mi][nj][r] = 0.f;

    for (int t = 0; t < NTAP; ++t) {
        cp_wait0();
        __syncthreads();   // single barrier per tap: A(t), B(t) ready
        bool pf = (t < 9);
        bool center = (t + 1 == 9);

        uint32_t aBuf = smbA + (uint32_t)((t & 1) * 18432) + aBase;
        uint32_t bBuf = smbB + (uint32_t)((t & 1) * 9216) + bBase;
        __half* Bnx = Bs + ((t + 1) & 1) * BTILE;

        // prefetch A(t+1) into the other buffer
        if (pf) {
            const __half* asrc = g_Ah + (t + 1) * 8192;
            uint32_t adst = smbA + (uint32_t)(((t + 1) & 1) * 18432);
            #pragma unroll
            for (int m = 0; m < 4; ++m) {
                int j = tid + 256 * m;
                int row = j >> 3, seg = j & 7;
                cp_async16(adst + (uint32_t)(row * 144 + seg * 16), asrc + j * 8);
            }
            cp_commit();
        }

        auto mma_step = [&](int sub) {
            uint32_t kOff = (uint32_t)(sub * 32);
            uint32_t a[2][4], bfr[2][4];
            #pragma unroll
            for (int mi = 0; mi < 2; ++mi)
                ldsm_x4(aBuf + (uint32_t)(mi * 16 * PADK * 2) + kOff, a[mi]);
            #pragma unroll
            for (int njp = 0; njp < 2; ++njp)
                ldsm_x4(bBuf + (uint32_t)(njp * 16 * PADK * 2) + kOff, bfr[njp]);
            #pragma unroll
            for (int mi = 0; mi < 2; ++mi)
                #pragma unroll
                for (int nj = 0; nj < 4; ++nj)
                    mma_fp16(acc[mi][nj], a[mi], bfr[nj >> 1] + (nj & 1) * 2);
        };

        uint4 q[2][4];
        int pix0 = tid >> 3, c00 = (tid & 7) * 8;
        int pix1 = pix0 + 32, c01 = c00;

        // sub0: issue gather batch0, then MMA k0
        if (pf) {
            if (center) {
                q[0][0] = *(const uint4*)&xb[(h * WW + w0 + pix0) * CIN + c00];
            } else {
                int i = (t + 1) * NPIX + pix0;
                q[0][0] = *(const uint4*)&xb[sO[i] + c00];
                q[0][1] = *(const uint4*)&xb[sO[576 + i] + c00];
                q[0][2] = *(const uint4*)&xb[sO[2 * 576 + i] + c00];
                q[0][3] = *(const uint4*)&xb[sO[3 * 576 + i] + c00];
            }
        }
        mma_step(0);

        // sub1: issue gather batch1, then MMA k1
        if (pf) {
            if (center) {
                q[1][0] = *(const uint4*)&xb[(h * WW + w0 + pix1) * CIN + c01];
            } else {
                int i = (t + 1) * NPIX + pix1;
                q[1][0] = *(const uint4*)&xb[sO[i] + c01];
                q[1][1] = *(const uint4*)&xb[sO[576 + i] + c01];
                q[1][2] = *(const uint4*)&xb[sO[2 * 576 + i] + c01];
                q[1][3] = *(const uint4*)&xb[sO[3 * 576 + i] + c01];
            }
        }
        mma_step(1);

        // sub2: MMA k2, then combine+STS batch0
        mma_step(2);
        if (pf) {
            uint4 r;
            if (center) {
                r = q[0][0];
            } else {
                int i = (t + 1) * NPIX + pix0;
                r = comb8(q[0][0], q[0][1], q[0][2], q[0][3],
                          sWh[i], sWh[576 + i], sWh[2 * 576 + i], sWh[3 * 576 + i]);
            }
            *(uint4*)&Bnx[pix0 * PADK + c00] = r;
        }

        // sub3: MMA k3, then combine+STS batch1
        mma_step(3);
        if (pf) {
            uint4 r;
            if (center) {
                r = q[1][0];
            } else {
                int i = (t + 1) * NPIX + pix1;
                r = comb8(q[1][0], q[1][1], q[1][2], q[1][3],
                          sWh[i], sWh[576 + i], sWh[2 * 576 + i], sWh[3 * 576 + i]);
            }
            *(uint4*)&Bnx[pix1 * PADK + c01] = r;
        }
    }

    // ---- epilogue: direct stores, NCHW ----
    #pragma unroll
    for (int mi = 0; mi < 2; ++mi) {
        #pragma unroll
        for (int nj = 0; nj < 4; ++nj) {
            int o = m0 + mi * 16 + g;
            int pix = w0 + n0 + nj * 8 + 2 * tq;
            float* op = out + (((size_t)n * COUT + o) * HH + h) * WW + pix;
            *(float2*)op = make_float2(acc[mi][nj][0], acc[mi][nj][1]);
            *(float2*)(op + 8 * HH * WW) = make_float2(acc[mi][nj][2], acc[mi][nj][3]);
        }
    }
}

// ============================================================
extern "C" void kernel_launch(void* const* d_in, const int* in_sizes, int n_in,
                              void* d_out, int out_size) {
    const float* x        = (const float*)d_in[0];
    const float* w_off    = (const float*)d_in[1];
    const float* b_off    = (const float*)d_in[2];
    const float* w_deform = (const float*)d_in[3];
    const float* w_pw     = (const float*)d_in[4];
    float* out = (float*)d_out;

    cudaFuncSetAttribute(off_mma,
                         cudaFuncAttributeMaxDynamicSharedMemorySize, OFF_SM_TOTAL);
    cudaFuncSetAttribute(fused_mma,
                         cudaFuncAttributeMaxDynamicSharedMemorySize, SM_TOTAL);

    prep_kernel<<<320, 256>>>(w_off, w_deform, w_pw);
    transpose_kernel<<<2048, 256>>>(x);
    off_mma<<<NB * HH, 512, OFF_SM_TOTAL>>>(b_off);
    fused_mma<<<NB * HH * 2, 256, SM_TOTAL>>>(out);
}

// round 12
// speedup vs baseline: 4.8061x; 1.0189x over previous
#include <cuda_runtime.h>
#include <cuda_fp16.h>
#include <cstdint>

#define NB 4
#define CIN 64
#define HH 128
#define WW 128
#define COUT 128
#define NTAP 10            // 9 deform taps + 1 center-correction tap
#define NOFF 18

// ---- scratch (no allocations allowed) ----
__device__ __half g_xh[NB * HH * WW * CIN];             // 8.4 MB, NHWC fp16
__device__ float g_toff[NB * NOFF * HH * WW];           // 4.7 MB, NCHW
__device__ __half g_Ah[NTAP * COUT * 64];               // fused GEMM A (fp16): [tap][o][c]
__device__ __half g_Aoffh[32 * 576];                    // offset-conv A (fp16): [o(32)][k]

// ============================================================
// helpers
// ============================================================
__device__ __forceinline__ void mma_fp16(float* c, const uint32_t* a, const uint32_t* b) {
    asm volatile(
        "mma.sync.aligned.m16n8k16.row.col.f32.f16.f16.f32 "
        "{%0,%1,%2,%3}, {%4,%5,%6,%7}, {%8,%9}, {%0,%1,%2,%3};"
        : "+f"(c[0]), "+f"(c[1]), "+f"(c[2]), "+f"(c[3])
        : "r"(a[0]), "r"(a[1]), "r"(a[2]), "r"(a[3]), "r"(b[0]), "r"(b[1]));
}
__device__ __forceinline__ void ldsm_x4(uint32_t addr, uint32_t* r) {
    asm volatile("ldmatrix.sync.aligned.m8n8.x4.shared.b16 {%0,%1,%2,%3}, [%4];"
                 : "=r"(r[0]), "=r"(r[1]), "=r"(r[2]), "=r"(r[3]) : "r"(addr));
}
__device__ __forceinline__ uint32_t smem_u32(const void* p) {
    uint32_t a;
    asm("{ .reg .u64 t; cvta.to.shared.u64 t, %1; cvt.u32.u64 %0, t; }" : "=r"(a) : "l"(p));
    return a;
}
__device__ __forceinline__ void cp_async16(uint32_t dst, const void* src) {
    asm volatile("cp.async.cg.shared.global [%0], [%1], 16;" :: "r"(dst), "l"(src) : "memory");
}
__device__ __forceinline__ void cp_commit() {
    asm volatile("cp.async.commit_group;" ::: "memory");
}
__device__ __forceinline__ void cp_wait0() {
    asm volatile("cp.async.wait_group 0;" ::: "memory");
}
// fp16x2 bilinear combine of 8 channels (4 half2 lanes)
__device__ __forceinline__ uint4 comb8(uint4 q00, uint4 q01, uint4 q10, uint4 q11,
                                       __half2 w00, __half2 w01, __half2 w10, __half2 w11) {
    const __half2* a = (const __half2*)&q00;
    const __half2* b = (const __half2*)&q01;
    const __half2* c = (const __half2*)&q10;
    const __half2* d = (const __half2*)&q11;
    uint4 r;
    __half2* rr = (__half2*)&r;
    #pragma unroll
    for (int k = 0; k < 4; ++k) {
        __half2 s = __hmul2(a[k], w00);
        s = __hfma2(b[k], w01, s);
        s = __hfma2(c[k], w10, s);
        s = __hfma2(d[k], w11, s);
        rr[k] = s;
    }
    return r;
}

// ============================================================
// Precompute: fused A (fp16) + offset-conv A (fp16)
// ============================================================
__global__ void prep_kernel(const float* __restrict__ w_off,
                            const float* __restrict__ w_deform,
                            const float* __restrict__ w_pw) {
    int tid = blockIdx.x * blockDim.x + threadIdx.x;
    int stride = gridDim.x * blockDim.x;

    for (int i = tid; i < NTAP * CIN * COUT; i += stride) {
        int o = i & 127;
        int k = i >> 7;
        int p = k >> 6;
        int c = k & 63;
        float acc = 0.f;
        if (p < 9) {
            #pragma unroll
            for (int d = 0; d < 4; ++d)
                acc += w_pw[o * 256 + c * 4 + d] * w_deform[(c * 4 + d) * 9 + p];
        } else {
            #pragma unroll
            for (int d = 0; d < 4; ++d) {
                float ws = 0.f;
                #pragma unroll
                for (int pp = 0; pp < 9; ++pp) ws += w_deform[(c * 4 + d) * 9 + pp];
                acc -= w_pw[o * 256 + c * 4 + d] * ws;
            }
        }
        g_Ah[p * 8192 + o * 64 + c] = __float2half_rn(acc);
    }

    for (int i = tid; i < 32 * 576; i += stride) {
        int k = i % 576;
        int o = i / 576;
        int t = k >> 6;
        int c = k & 63;
        float v = 0.f;
        if (o < NOFF) {
            const float* wp = w_off + (o * CIN + c) * 9;
            v = wp[t];
            if (t == 4) {
                float s = 0.f;
                #pragma unroll
                for (int tt = 0; tt < 9; ++tt) s += wp[tt];
                v -= s;
            }
        }
        g_Aoffh[o * 576 + k] = __float2half_rn(v);
    }
}

// ============================================================
// NCHW -> NHWC fp16 transpose of x
// ============================================================
__global__ void transpose_kernel(const float* __restrict__ x) {
    __shared__ float tile[CIN][33];
    int b = blockIdx.x;
    int wt = b & 3;
    int h  = (b >> 2) & 127;
    int n  = b >> 9;
    int w0 = wt * 32;

    for (int i = threadIdx.x; i < CIN * 32; i += 256) {
        int c = i >> 5, w = i & 31;
        tile[c][w] = x[((n * CIN + c) * HH + h) * WW + w0 + w];
    }
    __syncthreads();
    for (int i = threadIdx.x; i < 32 * 32; i += 256) {
        int w = i >> 5, cp = i & 31;
        __half2 hv = __float22half2_rn(make_float2(tile[2 * cp][w], tile[2 * cp + 1][w]));
        *(__half2*)&g_xh[((n * HH + h) * WW + w0 + w) * CIN + 2 * cp] = hv;
    }
}

// ============================================================
// Offset conv as fp16 tensor-core GEMM — R12: half-row blocks.
// Block = (n, h, half): M=32 (18 used), N=64 pixels, K=576.
// Staged window: 3 rows x 66 px (zero-padded). 66KB smem -> 3 CTAs/SM.
// ============================================================
#define OXROW 72
#define OXPIX 66
#define OXPLANE (3 * OXPIX * OXROW)            // 14256 halfs
#define OAOP 584
#define OFF_SM_A (OXPLANE * 2)                 // 28512 B
#define OFF_SM_TOTAL (OFF_SM_A + 32 * OAOP * 2)  // 65888 B

__global__ void __launch_bounds__(256, 3) off_mma(const float* __restrict__ b_off) {
    extern __shared__ char sm[];
    __half* Xs = (__half*)(sm);                 // [r3][px66][72]
    __half* Aw = (__half*)(sm + OFF_SM_A);      // [o32][584]

    int tid = threadIdx.x, wid = tid >> 5, lid = tid & 31;
    int g = lid >> 2, tq = lid & 3;
    int n  = blockIdx.x >> 8;
    int h  = (blockIdx.x >> 1) & 127;
    int w0 = (blockIdx.x & 1) * 64;
    int nw = wid * 8;

    // stage A (fp16, padded pitch): 32 rows x 72 chunks
    for (int j = tid; j < 2304; j += 256) {
        int o = j / 72, seg = j % 72;
        *(uint4*)&Aw[o * OAOP + seg * 8] = *(const uint4*)&g_Aoffh[o * 576 + seg * 8];
    }

    // stage X: 3 rows x 66 px (window origin w0-1), zero-padded
    const __half* xb = g_xh + (size_t)n * (HH * WW * CIN);
    for (int e = tid; e < 3 * OXPIX * 8; e += 256) {
        int r = e / (OXPIX * 8), rem = e % (OXPIX * 8);
        int p2 = rem >> 3, c0 = (rem & 7) * 8;
        int row = h - 1 + r, w = w0 - 1 + p2;
        uint4 v = make_uint4(0, 0, 0, 0);
        if ((unsigned)row < (unsigned)HH && (unsigned)w < (unsigned)WW)
            v = *(const uint4*)&xb[(row * WW + w) * CIN + c0];
        *(uint4*)&Xs[r * (OXPIX * OXROW) + p2 * OXROW + c0] = v;
    }
    __syncthreads();

    float acc[2][4];
    #pragma unroll
    for (int mi = 0; mi < 2; ++mi)
        #pragma unroll
        for (int r = 0; r < 4; ++r) acc[mi][r] = 0.f;

    #pragma unroll
    for (int t = 0; t < 9; ++t) {
        int ky = t / 3, kx = t % 3;
        #pragma unroll
        for (int ks = 0; ks < 4; ++ks) {
            int k0 = ks * 16;
            uint32_t a[2][4], b[2];
            #pragma unroll
            for (int mi = 0; mi < 2; ++mi) {
                const __half* ap = Aw + (mi * 16 + g) * OAOP + t * 64 + k0 + 2 * tq;
                a[mi][0] = *(const uint32_t*)(ap);
                a[mi][1] = *(const uint32_t*)(ap + 8 * OAOP);
                a[mi][2] = *(const uint32_t*)(ap + 8);
                a[mi][3] = *(const uint32_t*)(ap + 8 * OAOP + 8);
            }
            const __half* bp = Xs + ky * (OXPIX * OXROW) + (nw + g + kx) * OXROW + k0 + 2 * tq;
            b[0] = *(const uint32_t*)(bp);
            b[1] = *(const uint32_t*)(bp + 8);
            #pragma unroll
            for (int mi = 0; mi < 2; ++mi)
                mma_fp16(acc[mi], a[mi], b);
        }
    }

    int pix = w0 + nw + 2 * tq;
    #pragma unroll
    for (int mi = 0; mi < 2; ++mi) {
        int oa = mi * 16 + g;
        int ob = oa + 8;
        if (oa < NOFF) {
            float bb = __ldg(&b_off[oa]);
            *(float2*)&g_toff[((n * NOFF + oa) * HH + h) * WW + pix] =
                make_float2(acc[mi][0] + bb, acc[mi][1] + bb);
        }
        if (ob < NOFF) {
            float bb = __ldg(&b_off[ob]);
            *(float2*)&g_toff[((n * NOFF + ob) * HH + h) * WW + pix] =
                make_float2(acc[mi][2] + bb, acc[mi][3] + bb);
        }
    }
}

// ============================================================
// Fused deform-sample + fp16 GEMM (R12: gathers issue first).
// 256 threads, M=128 x N=64, 73.7KB smem -> 3 CTAs/SM.
// ============================================================
#define PADK 72
#define NPIX 64
#define BTILE (NPIX * PADK)                  // 4608 halfs = 9216 B per buf
#define SM_PAR 0                             // sWh 9216 + sO 9216 = 18432 B
#define SM_A 18432                           // 2 x 18432 B
#define SM_B (18432 + 36864)                 // 2 x 9216 B
#define SM_TOTAL (SM_B + 18432)              // 73728 B

__global__ void __launch_bounds__(256, 3) fused_mma(float* __restrict__ out) {
    extern __shared__ char sm[];
    __half2* sWh = (__half2*)(sm + SM_PAR);             // [4][576]
    int*     sO  = (int*)(sm + SM_PAR + 4 * 576 * 4);   // [4][576]
    __half* Bs = (__half*)(sm + SM_B);
    uint32_t smbA = smem_u32(sm + SM_A);
    uint32_t smbB = smem_u32(sm + SM_B);

    int tid = threadIdx.x, wid = tid >> 5, lid = tid & 31;
    int n  = blockIdx.x >> 8;
    int h  = (blockIdx.x >> 1) & 127;
    int w0 = (blockIdx.x & 1) * NPIX;
    int g = lid >> 2, tq = lid & 3;
    int m0 = (wid & 3) * 32;
    int n0 = (wid >> 2) * 32;

    uint32_t aBase = (uint32_t)(((m0 + (lid & 15)) * PADK + ((lid >> 4) << 3)) * 2);
    uint32_t bBase = (uint32_t)(((n0 + (lid & 7) + ((lid >> 4) << 3)) * PADK
                                 + (((lid >> 3) & 1) << 3)) * 2);

    // ---- bilinear params per (tap, pixel): 9*64 = 576 entries ----
    for (int i = tid; i < 9 * NPIX; i += 256) {
        int p = i >> 6, pix = i & 63;
        int w = w0 + pix;
        float dy = g_toff[((n * NOFF + 2 * p    ) * HH + h) * WW + w];
        float dx = g_toff[((n * NOFF + 2 * p + 1) * HH + h) * WW + w];
        float py = dy + (float)(h - 1 + p / 3);
        float px = dx + (float)(w - 1 + p % 3);
        float y0f = floorf(py), x0f = floorf(px);
        int y0 = (int)y0f, x0 = (int)x0f;
        float wy1 = py - y0f, wx1 = px - x0f;
        float wy0 = 1.f - wy1, wx0 = 1.f - wx1;
        bool vy0 = (unsigned)y0 < (unsigned)HH, vy1 = (unsigned)(y0 + 1) < (unsigned)HH;
        bool vx0 = (unsigned)x0 < (unsigned)WW, vx1 = (unsigned)(x0 + 1) < (unsigned)WW;
        int cy0 = min(max(y0, 0), HH - 1), cy1 = min(max(y0 + 1, 0), HH - 1);
        int cx0 = min(max(x0, 0), WW - 1), cx1 = min(max(x0 + 1, 0), WW - 1);
        float f00 = (vy0 && vx0) ? wy0 * wx0 : 0.f;
        float f01 = (vy0 && vx1) ? wy0 * wx1 : 0.f;
        float f10 = (vy1 && vx0) ? wy1 * wx0 : 0.f;
        float f11 = (vy1 && vx1) ? wy1 * wx1 : 0.f;
        sWh[0 * 576 + i] = __half2half2(__float2half_rn(f00));
        sWh[1 * 576 + i] = __half2half2(__float2half_rn(f01));
        sWh[2 * 576 + i] = __half2half2(__float2half_rn(f10));
        sWh[3 * 576 + i] = __half2half2(__float2half_rn(f11));
        sO[0 * 576 + i] = (cy0 * WW + cx0) * CIN;
        sO[1 * 576 + i] = (cy0 * WW + cx1) * CIN;
        sO[2 * 576 + i] = (cy1 * WW + cx0) * CIN;
        sO[3 * 576 + i] = (cy1 * WW + cx1) * CIN;
    }

    const __half* xb = g_xh + (size_t)n * (HH * WW * CIN);

    // ---- prologue: A(0) via cp.async into buf 0 ----
    #pragma unroll
    for (int m = 0; m < 4; ++m) {
        int j = tid + 256 * m;
        int row = j >> 3, seg = j & 7;
        cp_async16(smbA + (uint32_t)(row * 144 + seg * 16), g_Ah + j * 8);
    }
    cp_commit();
    __syncthreads();   // params visible

    // ---- prologue: B(0) gathered inline into buf 0 (tap 0) ----
    #pragma unroll
    for (int b = 0; b < 2; ++b) {
        int j = tid + 256 * b;
        int pix = j >> 3, c0 = (j & 7) * 8;
        int i = pix;   // tap 0
        uint4 q00 = *(const uint4*)&xb[sO[i] + c0];
        uint4 q01 = *(const uint4*)&xb[sO[576 + i] + c0];
        uint4 q10 = *(const uint4*)&xb[sO[2 * 576 + i] + c0];
        uint4 q11 = *(const uint4*)&xb[sO[3 * 576 + i] + c0];
        *(uint4*)&Bs[pix * PADK + c0] =
            comb8(q00, q01, q10, q11, sWh[i], sWh[576 + i], sWh[2 * 576 + i], sWh[3 * 576 + i]);
    }

    float acc[2][4][4];
    #pragma unroll
    for (int mi = 0; mi < 2; ++mi)
        #pragma unroll
        for (int nj = 0; nj < 4; ++nj)
            #pragma unroll
            for (int r = 0; r < 4; ++r) acc[mi][nj][r] = 0.f;

    for (int t = 0; t < NTAP; ++t) {
        cp_wait0();
        __syncthreads();   // single barrier per tap: A(t), B(t) ready
        bool pf = (t < 9);
        bool center = (t + 1 == 9);

        uint32_t aBuf = smbA + (uint32_t)((t & 1) * 18432) + aBase;
        uint32_t bBuf = smbB + (uint32_t)((t & 1) * 9216) + bBase;
        __half* Bnx = Bs + ((t + 1) & 1) * BTILE;

        uint4 q[2][4];
        int pix0 = tid >> 3, c00 = (tid & 7) * 8;
        int pix1 = pix0 + 32;

        // issue BOTH gather batches for tap t+1 immediately (max distance)
        if (pf) {
            if (center) {
                q[0][0] = *(const uint4*)&xb[(h * WW + w0 + pix0) * CIN + c00];
                q[1][0] = *(const uint4*)&xb[(h * WW + w0 + pix1) * CIN + c00];
            } else {
                int i0 = (t + 1) * NPIX + pix0;
                int i1 = (t + 1) * NPIX + pix1;
                q[0][0] = *(const uint4*)&xb[sO[i0] + c00];
                q[0][1] = *(const uint4*)&xb[sO[576 + i0] + c00];
                q[0][2] = *(const uint4*)&xb[sO[2 * 576 + i0] + c00];
                q[0][3] = *(const uint4*)&xb[sO[3 * 576 + i0] + c00];
                q[1][0] = *(const uint4*)&xb[sO[i1] + c00];
                q[1][1] = *(const uint4*)&xb[sO[576 + i1] + c00];
                q[1][2] = *(const uint4*)&xb[sO[2 * 576 + i1] + c00];
                q[1][3] = *(const uint4*)&xb[sO[3 * 576 + i1] + c00];
            }
        }

        // prefetch A(t+1)
        if (pf) {
            const __half* asrc = g_Ah + (t + 1) * 8192;
            uint32_t adst = smbA + (uint32_t)(((t + 1) & 1) * 18432);
            #pragma unroll
            for (int m = 0; m < 4; ++m) {
                int j = tid + 256 * m;
                int row = j >> 3, seg = j & 7;
                cp_async16(adst + (uint32_t)(row * 144 + seg * 16), asrc + j * 8);
            }
            cp_commit();
        }

        auto mma_step = [&](int sub) {
            uint32_t kOff = (uint32_t)(sub * 32);
            uint32_t a[2][4], bfr[2][4];
            #pragma unroll
            for (int mi = 0; mi < 2; ++mi)
                ldsm_x4(aBuf + (uint32_t)(mi * 16 * PADK * 2) + kOff, a[mi]);
            #pragma unroll
            for (int njp = 0; njp < 2; ++njp)
                ldsm_x4(bBuf + (uint32_t)(njp * 16 * PADK * 2) + kOff, bfr[njp]);
            #pragma unroll
            for (int mi = 0; mi < 2; ++mi)
                #pragma unroll
                for (int nj = 0; nj < 4; ++nj)
                    mma_fp16(acc[mi][nj], a[mi], bfr[nj >> 1] + (nj & 1) * 2);
        };

        mma_step(0);
        mma_step(1);
        mma_step(2);
        if (pf) {
            uint4 r;
            if (center) {
                r = q[0][0];
            } else {
                int i = (t + 1) * NPIX + pix0;
                r = comb8(q[0][0], q[0][1], q[0][2], q[0][3],
                          sWh[i], sWh[576 + i], sWh[2 * 576 + i], sWh[3 * 576 + i]);
            }
            *(uint4*)&Bnx[pix0 * PADK + c00] = r;
        }
        mma_step(3);
        if (pf) {
            uint4 r;
            if (center) {
                r = q[1][0];
            } else {
                int i = (t + 1) * NPIX + pix1;
                r = comb8(q[1][0], q[1][1], q[1][2], q[1][3],
                          sWh[i], sWh[576 + i], sWh[2 * 576 + i], sWh[3 * 576 + i]);
            }
            *(uint4*)&Bnx[pix1 * PADK + c00] = r;
        }
    }

    // ---- epilogue: direct stores, NCHW ----
    #pragma unroll
    for (int mi = 0; mi < 2; ++mi) {
        #pragma unroll
        for (int nj = 0; nj < 4; ++nj) {
            int o = m0 + mi * 16 + g;
            int pix = w0 + n0 + nj * 8 + 2 * tq;
            float* op = out + (((size_t)n * COUT + o) * HH + h) * WW + pix;
            *(float2*)op = make_float2(acc[mi][nj][0], acc[mi][nj][1]);
            *(float2*)(op + 8 * HH * WW) = make_float2(acc[mi][nj][2], acc[mi][nj][3]);
        }
    }
}

// ============================================================
extern "C" void kernel_launch(void* const* d_in, const int* in_sizes, int n_in,
                              void* d_out, int out_size) {
    const float* x        = (const float*)d_in[0];
    const float* w_off    = (const float*)d_in[1];
    const float* b_off    = (const float*)d_in[2];
    const float* w_deform = (const float*)d_in[3];
    const float* w_pw     = (const float*)d_in[4];
    float* out = (float*)d_out;

    cudaFuncSetAttribute(off_mma,
                         cudaFuncAttributeMaxDynamicSharedMemorySize, OFF_SM_TOTAL);
    cudaFuncSetAttribute(fused_mma,
                         cudaFuncAttributeMaxDynamicSharedMemorySize, SM_TOTAL);

    prep_kernel<<<320, 256>>>(w_off, w_deform, w_pw);
    transpose_kernel<<<2048, 256>>>(x);
    off_mma<<<NB * HH * 2, 256, OFF_SM_TOTAL>>>(b_off);
    fused_mma<<<NB * HH * 2, 256, SM_TOTAL>>>(out);
}

// round 13
// speedup vs baseline: 5.1588x; 1.0734x over previous
#include <cuda_runtime.h>
#include <cuda_fp16.h>
#include <cstdint>

#define NB 4
#define CIN 64
#define HH 128
#define WW 128
#define COUT 128
#define NTAP 10            // 9 deform taps + 1 center-correction tap
#define NOFF 18

// ---- scratch (no allocations allowed) ----
__device__ __half g_xh[NB * HH * WW * CIN];             // 8.4 MB, NHWC fp16
__device__ float g_toff[NB * NOFF * HH * WW];           // 4.7 MB, NCHW
__device__ __half g_Ah[NTAP * COUT * 64];               // fused GEMM A (fp16): [tap][o][c]
__device__ __half g_Aoffh[32 * 576];                    // offset-conv A (fp16): [o(32)][k]

// ============================================================
// helpers
// ============================================================
__device__ __forceinline__ void mma_fp16(float* c, const uint32_t* a, const uint32_t* b) {
    asm volatile(
        "mma.sync.aligned.m16n8k16.row.col.f32.f16.f16.f32 "
        "{%0,%1,%2,%3}, {%4,%5,%6,%7}, {%8,%9}, {%0,%1,%2,%3};"
        : "+f"(c[0]), "+f"(c[1]), "+f"(c[2]), "+f"(c[3])
        : "r"(a[0]), "r"(a[1]), "r"(a[2]), "r"(a[3]), "r"(b[0]), "r"(b[1]));
}
__device__ __forceinline__ void ldsm_x4(uint32_t addr, uint32_t* r) {
    asm volatile("ldmatrix.sync.aligned.m8n8.x4.shared.b16 {%0,%1,%2,%3}, [%4];"
                 : "=r"(r[0]), "=r"(r[1]), "=r"(r[2]), "=r"(r[3]) : "r"(addr));
}
__device__ __forceinline__ uint32_t smem_u32(const void* p) {
    uint32_t a;
    asm("{ .reg .u64 t; cvta.to.shared.u64 t, %1; cvt.u32.u64 %0, t; }" : "=r"(a) : "l"(p));
    return a;
}
__device__ __forceinline__ void cp_async16(uint32_t dst, const void* src) {
    asm volatile("cp.async.cg.shared.global [%0], [%1], 16;" :: "r"(dst), "l"(src) : "memory");
}
__device__ __forceinline__ void cp_commit() {
    asm volatile("cp.async.commit_group;" ::: "memory");
}
__device__ __forceinline__ void cp_wait0() {
    asm volatile("cp.async.wait_group 0;" ::: "memory");
}
// fp16x2 bilinear combine of 8 channels (4 half2 lanes)
__device__ __forceinline__ uint4 comb8(uint4 q00, uint4 q01, uint4 q10, uint4 q11,
                                       __half2 w00, __half2 w01, __half2 w10, __half2 w11) {
    const __half2* a = (const __half2*)&q00;
    const __half2* b = (const __half2*)&q01;
    const __half2* c = (const __half2*)&q10;
    const __half2* d = (const __half2*)&q11;
    uint4 r;
    __half2* rr = (__half2*)&r;
    #pragma unroll
    for (int k = 0; k < 4; ++k) {
        __half2 s = __hmul2(a[k], w00);
        s = __hfma2(b[k], w01, s);
        s = __hfma2(c[k], w10, s);
        s = __hfma2(d[k], w11, s);
        rr[k] = s;
    }
    return r;
}

// ============================================================
// Transpose (NCHW -> NHWC fp16) + fused weight prep in one launch.
// 2048 blocks x 256 threads; prep work strided over the whole grid.
// ============================================================
__global__ void transpose_prep_kernel(const float* __restrict__ x,
                                      const float* __restrict__ w_off,
                                      const float* __restrict__ w_deform,
                                      const float* __restrict__ w_pw) {
    __shared__ float tile[CIN][33];
    int b = blockIdx.x;
    int wt = b & 3;
    int h  = (b >> 2) & 127;
    int n  = b >> 9;
    int w0 = wt * 32;

    for (int i = threadIdx.x; i < CIN * 32; i += 256) {
        int c = i >> 5, w = i & 31;
        tile[c][w] = x[((n * CIN + c) * HH + h) * WW + w0 + w];
    }

    // ---- prep work (independent of the transpose tile) ----
    int gtid = blockIdx.x * 256 + threadIdx.x;
    int gstride = gridDim.x * 256;
    for (int i = gtid; i < NTAP * CIN * COUT; i += gstride) {
        int o = i & 127;
        int k = i >> 7;
        int p = k >> 6;
        int c = k & 63;
        float acc = 0.f;
        if (p < 9) {
            #pragma unroll
            for (int d = 0; d < 4; ++d)
                acc += w_pw[o * 256 + c * 4 + d] * w_deform[(c * 4 + d) * 9 + p];
        } else {
            #pragma unroll
            for (int d = 0; d < 4; ++d) {
                float ws = 0.f;
                #pragma unroll
                for (int pp = 0; pp < 9; ++pp) ws += w_deform[(c * 4 + d) * 9 + pp];
                acc -= w_pw[o * 256 + c * 4 + d] * ws;
            }
        }
        g_Ah[p * 8192 + o * 64 + c] = __float2half_rn(acc);
    }
    for (int i = gtid; i < 32 * 576; i += gstride) {
        int k = i % 576;
        int o = i / 576;
        int t = k >> 6;
        int c = k & 63;
        float v = 0.f;
        if (o < NOFF) {
            const float* wp = w_off + (o * CIN + c) * 9;
            v = wp[t];
            if (t == 4) {
                float s = 0.f;
                #pragma unroll
                for (int tt = 0; tt < 9; ++tt) s += wp[tt];
                v -= s;
            }
        }
        g_Aoffh[o * 576 + k] = __float2half_rn(v);
    }

    __syncthreads();
    for (int i = threadIdx.x; i < 32 * 32; i += 256) {
        int w = i >> 5, cp = i & 31;
        __half2 hv = __float22half2_rn(make_float2(tile[2 * cp][w], tile[2 * cp + 1][w]));
        *(__half2*)&g_xh[((n * HH + h) * WW + w0 + w) * CIN + 2 * cp] = hv;
    }
}

// ============================================================
// Offset conv as single-pass fp16 tensor-core GEMM.
// R13: reverted to the R11-proven full-row form (512 blocks x 512 thr).
// M=32 (18 used), N=128 pixels, K=576; staged window 3 x 130 px.
// ============================================================
#define XROW 72
#define XPIX 130
#define XPLANE (3 * XPIX * XROW)
#define AOP 584
#define OFF_SM_X 0
#define OFF_SM_A (XPLANE * 2)
#define OFF_SM_TOTAL (OFF_SM_A + 32 * AOP * 2)

__global__ void __launch_bounds__(512, 1) off_mma(const float* __restrict__ b_off) {
    extern __shared__ char sm[];
    __half* Xs = (__half*)(sm + OFF_SM_X);
    __half* Aw = (__half*)(sm + OFF_SM_A);

    int tid = threadIdx.x, wid = tid >> 5, lid = tid & 31;
    int g = lid >> 2, tq = lid & 3;
    int n = blockIdx.x >> 7, h = blockIdx.x & 127;
    int nw = wid * 8;

    for (int j = tid; j < 2304; j += 512) {
        int o = j / 72, seg = j % 72;
        *(uint4*)&Aw[o * AOP + seg * 8] = *(const uint4*)&g_Aoffh[o * 576 + seg * 8];
    }

    const __half* xb = g_xh + (size_t)n * (HH * WW * CIN);
    for (int e = tid; e < 3120; e += 512) {
        int r = e / 1040, rem = e % 1040;
        int p = rem >> 3, seg = rem & 7;
        int c0 = seg * 8;
        int row = h - 1 + r, w = p - 1;
        uint4 v = make_uint4(0, 0, 0, 0);
        if ((unsigned)row < (unsigned)HH && (unsigned)w < (unsigned)WW)
            v = *(const uint4*)&xb[(row * WW + w) * CIN + c0];
        *(uint4*)&Xs[r * (XPIX * XROW) + p * XROW + c0] = v;
    }
    __syncthreads();

    float acc[2][4];
    #pragma unroll
    for (int mi = 0; mi < 2; ++mi)
        #pragma unroll
        for (int r = 0; r < 4; ++r) acc[mi][r] = 0.f;

    #pragma unroll
    for (int t = 0; t < 9; ++t) {
        int ky = t / 3, kx = t % 3;
        #pragma unroll
        for (int ks = 0; ks < 4; ++ks) {
            int k0 = ks * 16;
            uint32_t a[2][4], b[2];
            #pragma unroll
            for (int mi = 0; mi < 2; ++mi) {
                const __half* ap = Aw + (mi * 16 + g) * AOP + t * 64 + k0 + 2 * tq;
                a[mi][0] = *(const uint32_t*)(ap);
                a[mi][1] = *(const uint32_t*)(ap + 8 * AOP);
                a[mi][2] = *(const uint32_t*)(ap + 8);
                a[mi][3] = *(const uint32_t*)(ap + 8 * AOP + 8);
            }
            const __half* bp = Xs + ky * (XPIX * XROW) + (nw + g + kx) * XROW + k0 + 2 * tq;
            b[0] = *(const uint32_t*)(bp);
            b[1] = *(const uint32_t*)(bp + 8);
            #pragma unroll
            for (int mi = 0; mi < 2; ++mi)
                mma_fp16(acc[mi], a[mi], b);
        }
    }

    int pix = nw + 2 * tq;
    #pragma unroll
    for (int mi = 0; mi < 2; ++mi) {
        int oa = mi * 16 + g;
        int ob = oa + 8;
        if (oa < NOFF) {
            float bb = __ldg(&b_off[oa]);
            *(float2*)&g_toff[((n * NOFF + oa) * HH + h) * WW + pix] =
                make_float2(acc[mi][0] + bb, acc[mi][1] + bb);
        }
        if (ob < NOFF) {
            float bb = __ldg(&b_off[ob]);
            *(float2*)&g_toff[((n * NOFF + ob) * HH + h) * WW + pix] =
                make_float2(acc[mi][2] + bb, acc[mi][3] + bb);
        }
    }
}

// ============================================================
// Fused deform-sample + fp16 GEMM (R12 body, proven at 79.3us).
// 256 threads, M=128 x N=64, 73.7KB smem -> 3 CTAs/SM.
// ============================================================
#define PADK 72
#define NPIX 64
#define BTILE (NPIX * PADK)                  // 4608 halfs = 9216 B per buf
#define SM_PAR 0                             // sWh 9216 + sO 9216 = 18432 B
#define SM_A 18432                           // 2 x 18432 B
#define SM_B (18432 + 36864)                 // 2 x 9216 B
#define SM_TOTAL (SM_B + 18432)              // 73728 B

__global__ void __launch_bounds__(256, 3) fused_mma(float* __restrict__ out) {
    extern __shared__ char sm[];
    __half2* sWh = (__half2*)(sm + SM_PAR);             // [4][576]
    int*     sO  = (int*)(sm + SM_PAR + 4 * 576 * 4);   // [4][576]
    __half* Bs = (__half*)(sm + SM_B);
    uint32_t smbA = smem_u32(sm + SM_A);
    uint32_t smbB = smem_u32(sm + SM_B);

    int tid = threadIdx.x, wid = tid >> 5, lid = tid & 31;
    int n  = blockIdx.x >> 8;
    int h  = (blockIdx.x >> 1) & 127;
    int w0 = (blockIdx.x & 1) * NPIX;
    int g = lid >> 2, tq = lid & 3;
    int m0 = (wid & 3) * 32;
    int n0 = (wid >> 2) * 32;

    uint32_t aBase = (uint32_t)(((m0 + (lid & 15)) * PADK + ((lid >> 4) << 3)) * 2);
    uint32_t bBase = (uint32_t)(((n0 + (lid & 7) + ((lid >> 4) << 3)) * PADK
                                 + (((lid >> 3) & 1) << 3)) * 2);

    // ---- bilinear params per (tap, pixel): 9*64 = 576 entries ----
    for (int i = tid; i < 9 * NPIX; i += 256) {
        int p = i >> 6, pix = i & 63;
        int w = w0 + pix;
        float dy = g_toff[((n * NOFF + 2 * p    ) * HH + h) * WW + w];
        float dx = g_toff[((n * NOFF + 2 * p + 1) * HH + h) * WW + w];
        float py = dy + (float)(h - 1 + p / 3);
        float px = dx + (float)(w - 1 + p % 3);
        float y0f = floorf(py), x0f = floorf(px);
        int y0 = (int)y0f, x0 = (int)x0f;
        float wy1 = py - y0f, wx1 = px - x0f;
        float wy0 = 1.f - wy1, wx0 = 1.f - wx1;
        bool vy0 = (unsigned)y0 < (unsigned)HH, vy1 = (unsigned)(y0 + 1) < (unsigned)HH;
        bool vx0 = (unsigned)x0 < (unsigned)WW, vx1 = (unsigned)(x0 + 1) < (unsigned)WW;
        int cy0 = min(max(y0, 0), HH - 1), cy1 = min(max(y0 + 1, 0), HH - 1);
        int cx0 = min(max(x0, 0), WW - 1), cx1 = min(max(x0 + 1, 0), WW - 1);
        float f00 = (vy0 && vx0) ? wy0 * wx0 : 0.f;
        float f01 = (vy0 && vx1) ? wy0 * wx1 : 0.f;
        float f10 = (vy1 && vx0) ? wy1 * wx0 : 0.f;
        float f11 = (vy1 && vx1) ? wy1 * wx1 : 0.f;
        sWh[0 * 576 + i] = __half2half2(__float2half_rn(f00));
        sWh[1 * 576 + i] = __half2half2(__float2half_rn(f01));
        sWh[2 * 576 + i] = __half2half2(__float2half_rn(f10));
        sWh[3 * 576 + i] = __half2half2(__float2half_rn(f11));
        sO[0 * 576 + i] = (cy0 * WW + cx0) * CIN;
        sO[1 * 576 + i] = (cy0 * WW + cx1) * CIN;
        sO[2 * 576 + i] = (cy1 * WW + cx0) * CIN;
        sO[3 * 576 + i] = (cy1 * WW + cx1) * CIN;
    }

    const __half* xb = g_xh + (size_t)n * (HH * WW * CIN);

    // ---- prologue: A(0) via cp.async into buf 0 ----
    #pragma unroll
    for (int m = 0; m < 4; ++m) {
        int j = tid + 256 * m;
        int row = j >> 3, seg = j & 7;
        cp_async16(smbA + (uint32_t)(row * 144 + seg * 16), g_Ah + j * 8);
    }
    cp_commit();
    __syncthreads();   // params visible

    // ---- prologue: B(0) gathered inline into buf 0 (tap 0) ----
    #pragma unroll
    for (int b = 0; b < 2; ++b) {
        int j = tid + 256 * b;
        int pix = j >> 3, c0 = (j & 7) * 8;
        int i = pix;   // tap 0
        uint4 q00 = *(const uint4*)&xb[sO[i] + c0];
        uint4 q01 = *(const uint4*)&xb[sO[576 + i] + c0];
        uint4 q10 = *(const uint4*)&xb[sO[2 * 576 + i] + c0];
        uint4 q11 = *(const uint4*)&xb[sO[3 * 576 + i] + c0];
        *(uint4*)&Bs[pix * PADK + c0] =
            comb8(q00, q01, q10, q11, sWh[i], sWh[576 + i], sWh[2 * 576 + i], sWh[3 * 576 + i]);
    }

    float acc[2][4][4];
    #pragma unroll
    for (int mi = 0; mi < 2; ++mi)
        #pragma unroll
        for (int nj = 0; nj < 4; ++nj)
            #pragma unroll
            for (int r = 0; r < 4; ++r) acc[mi][nj][r] = 0.f;

    for (int t = 0; t < NTAP; ++t) {
        cp_wait0();
        __syncthreads();   // single barrier per tap: A(t), B(t) ready
        bool pf = (t < 9);
        bool center = (t + 1 == 9);

        uint32_t aBuf = smbA + (uint32_t)((t & 1) * 18432) + aBase;
        uint32_t bBuf = smbB + (uint32_t)((t & 1) * 9216) + bBase;
        __half* Bnx = Bs + ((t + 1) & 1) * BTILE;

        uint4 q[2][4];
        int pix0 = tid >> 3, c00 = (tid & 7) * 8;
        int pix1 = pix0 + 32;

        // issue BOTH gather batches for tap t+1 immediately (max distance)
        if (pf) {
            if (center) {
                q[0][0] = *(const uint4*)&xb[(h * WW + w0 + pix0) * CIN + c00];
                q[1][0] = *(const uint4*)&xb[(h * WW + w0 + pix1) * CIN + c00];
            } else {
                int i0 = (t + 1) * NPIX + pix0;
                int i1 = (t + 1) * NPIX + pix1;
                q[0][0] = *(const uint4*)&xb[sO[i0] + c00];
                q[0][1] = *(const uint4*)&xb[sO[576 + i0] + c00];
                q[0][2] = *(const uint4*)&xb[sO[2 * 576 + i0] + c00];
                q[0][3] = *(const uint4*)&xb[sO[3 * 576 + i0] + c00];
                q[1][0] = *(const uint4*)&xb[sO[i1] + c00];
                q[1][1] = *(const uint4*)&xb[sO[576 + i1] + c00];
                q[1][2] = *(const uint4*)&xb[sO[2 * 576 + i1] + c00];
                q[1][3] = *(const uint4*)&xb[sO[3 * 576 + i1] + c00];
            }
        }

        // prefetch A(t+1)
        if (pf) {
            const __half* asrc = g_Ah + (t + 1) * 8192;
            uint32_t adst = smbA + (uint32_t)(((t + 1) & 1) * 18432);
            #pragma unroll
            for (int m = 0; m < 4; ++m) {
                int j = tid + 256 * m;
                int row = j >> 3, seg = j & 7;
                cp_async16(adst + (uint32_t)(row * 144 + seg * 16), asrc + j * 8);
            }
            cp_commit();
        }

        auto mma_step = [&](int sub) {
            uint32_t kOff = (uint32_t)(sub * 32);
            uint32_t a[2][4], bfr[2][4];
            #pragma unroll
            for (int mi = 0; mi < 2; ++mi)
                ldsm_x4(aBuf + (uint32_t)(mi * 16 * PADK * 2) + kOff, a[mi]);
            #pragma unroll
            for (int njp = 0; njp < 2; ++njp)
                ldsm_x4(bBuf + (uint32_t)(njp * 16 * PADK * 2) + kOff, bfr[njp]);
            #pragma unroll
            for (int mi = 0; mi < 2; ++mi)
                #pragma unroll
                for (int nj = 0; nj < 4; ++nj)
                    mma_fp16(acc[mi][nj], a[mi], bfr[nj >> 1] + (nj & 1) * 2);
        };

        mma_step(0);
        mma_step(1);
        mma_step(2);
        if (pf) {
            uint4 r;
            if (center) {
                r = q[0][0];
            } else {
                int i = (t + 1) * NPIX + pix0;
                r = comb8(q[0][0], q[0][1], q[0][2], q[0][3],
                          sWh[i], sWh[576 + i], sWh[2 * 576 + i], sWh[3 * 576 + i]);
            }
            *(uint4*)&Bnx[pix0 * PADK + c00] = r;
        }
        mma_step(3);
        if (pf) {
            uint4 r;
            if (center) {
                r = q[1][0];
            } else {
                int i = (t + 1) * NPIX + pix1;
                r = comb8(q[1][0], q[1][1], q[1][2], q[1][3],
                          sWh[i], sWh[576 + i], sWh[2 * 576 + i], sWh[3 * 576 + i]);
            }
            *(uint4*)&Bnx[pix1 * PADK + c00] = r;
        }
    }

    // ---- epilogue: direct stores, NCHW ----
    #pragma unroll
    for (int mi = 0; mi < 2; ++mi) {
        #pragma unroll
        for (int nj = 0; nj < 4; ++nj) {
            int o = m0 + mi * 16 + g;
            int pix = w0 + n0 + nj * 8 + 2 * tq;
            float* op = out + (((size_t)n * COUT + o) * HH + h) * WW + pix;
            *(float2*)op = make_float2(acc[mi][nj][0], acc[mi][nj][1]);
            *(float2*)(op + 8 * HH * WW) = make_float2(acc[mi][nj][2], acc[mi][nj][3]);
        }
    }
}

// ============================================================
extern "C" void kernel_launch(void* const* d_in, const int* in_sizes, int n_in,
                              void* d_out, int out_size) {
    const float* x        = (const float*)d_in[0];
    const float* w_off    = (const float*)d_in[1];
    const float* b_off    = (const float*)d_in[2];
    const float* w_deform = (const float*)d_in[3];
    const float* w_pw     = (const float*)d_in[4];
    float* out = (float*)d_out;

    cudaFuncSetAttribute(off_mma,
                         cudaFuncAttributeMaxDynamicSharedMemorySize, OFF_SM_TOTAL);
    cudaFuncSetAttribute(fused_mma,
                         cudaFuncAttributeMaxDynamicSharedMemorySize, SM_TOTAL);

    transpose_prep_kernel<<<2048, 256>>>(x, w_off, w_deform, w_pw);
    off_mma<<<NB * HH, 512, OFF_SM_TOTAL>>>(b_off);
    fused_mma<<<NB * HH * 2, 256, SM_TOTAL>>>(out);
}

// round 14
// speedup vs baseline: 5.1983x; 1.0077x over previous
#include <cuda_runtime.h>
#include <cuda_fp16.h>
#include <cstdint>

#define NB 4
#define CIN 64
#define HH 128
#define WW 128
#define COUT 128
#define NTAP 10            // 9 deform taps + 1 center-correction tap
#define NOFF 18

// ---- scratch (no allocations allowed) ----
__device__ __half g_xh[NB * HH * WW * CIN];             // 8.4 MB, NHWC fp16
__device__ float g_toff[NB * NOFF * HH * WW];           // 4.7 MB, NCHW
__device__ __half g_Ah[NTAP * COUT * 64];               // fused GEMM A (fp16): [tap][o][c]
__device__ __half g_Aoffh[32 * 576];                    // offset-conv A (fp16): [o(32)][k]

// ============================================================
// helpers
// ============================================================
__device__ __forceinline__ void mma_fp16(float* c, const uint32_t* a, const uint32_t* b) {
    asm volatile(
        "mma.sync.aligned.m16n8k16.row.col.f32.f16.f16.f32 "
        "{%0,%1,%2,%3}, {%4,%5,%6,%7}, {%8,%9}, {%0,%1,%2,%3};"
        : "+f"(c[0]), "+f"(c[1]), "+f"(c[2]), "+f"(c[3])
        : "r"(a[0]), "r"(a[1]), "r"(a[2]), "r"(a[3]), "r"(b[0]), "r"(b[1]));
}
__device__ __forceinline__ void ldsm_x4(uint32_t addr, uint32_t* r) {
    asm volatile("ldmatrix.sync.aligned.m8n8.x4.shared.b16 {%0,%1,%2,%3}, [%4];"
                 : "=r"(r[0]), "=r"(r[1]), "=r"(r[2]), "=r"(r[3]) : "r"(addr));
}
__device__ __forceinline__ uint32_t smem_u32(const void* p) {
    uint32_t a;
    asm("{ .reg .u64 t; cvta.to.shared.u64 t, %1; cvt.u32.u64 %0, t; }" : "=r"(a) : "l"(p));
    return a;
}
__device__ __forceinline__ void cp_async16(uint32_t dst, const void* src) {
    asm volatile("cp.async.cg.shared.global [%0], [%1], 16;" :: "r"(dst), "l"(src) : "memory");
}
__device__ __forceinline__ void cp_commit() {
    asm volatile("cp.async.commit_group;" ::: "memory");
}
__device__ __forceinline__ void cp_wait0() {
    asm volatile("cp.async.wait_group 0;" ::: "memory");
}
// fp16x2 bilinear combine of 8 channels (4 half2 lanes)
__device__ __forceinline__ uint4 comb8(uint4 q00, uint4 q01, uint4 q10, uint4 q11,
                                       __half2 w00, __half2 w01, __half2 w10, __half2 w11) {
    const __half2* a = (const __half2*)&q00;
    const __half2* b = (const __half2*)&q01;
    const __half2* c = (const __half2*)&q10;
    const __half2* d = (const __half2*)&q11;
    uint4 r;
    __half2* rr = (__half2*)&r;
    #pragma unroll
    for (int k = 0; k < 4; ++k) {
        __half2 s = __hmul2(a[k], w00);
        s = __hfma2(b[k], w01, s);
        s = __hfma2(c[k], w10, s);
        s = __hfma2(d[k], w11, s);
        rr[k] = s;
    }
    return r;
}

// ============================================================
// Transpose (NCHW -> NHWC fp16) + fused weight prep in one launch.
// R14: two-phase register staging for explicit MLP=8.
// ============================================================
__global__ void transpose_prep_kernel(const float* __restrict__ x,
                                      const float* __restrict__ w_off,
                                      const float* __restrict__ w_deform,
                                      const float* __restrict__ w_pw) {
    __shared__ float tile[CIN][33];
    int b = blockIdx.x;
    int wt = b & 3;
    int h  = (b >> 2) & 127;
    int n  = b >> 9;
    int w0 = wt * 32;

    // phase 1: issue all 8 loads
    float v[8];
    #pragma unroll
    for (int k = 0; k < 8; ++k) {
        int i = threadIdx.x + k * 256;
        int c = i >> 5, w = i & 31;
        v[k] = x[((n * CIN + c) * HH + h) * WW + w0 + w];
    }

    // ---- prep work (independent; overlaps load latency) ----
    int gtid = blockIdx.x * 256 + threadIdx.x;
    int gstride = gridDim.x * 256;
    for (int i = gtid; i < NTAP * CIN * COUT; i += gstride) {
        int o = i & 127;
        int k = i >> 7;
        int p = k >> 6;
        int c = k & 63;
        float acc = 0.f;
        if (p < 9) {
            #pragma unroll
            for (int d = 0; d < 4; ++d)
                acc += w_pw[o * 256 + c * 4 + d] * w_deform[(c * 4 + d) * 9 + p];
        } else {
            #pragma unroll
            for (int d = 0; d < 4; ++d) {
                float ws = 0.f;
                #pragma unroll
                for (int pp = 0; pp < 9; ++pp) ws += w_deform[(c * 4 + d) * 9 + pp];
                acc -= w_pw[o * 256 + c * 4 + d] * ws;
            }
        }
        g_Ah[p * 8192 + o * 64 + c] = __float2half_rn(acc);
    }
    for (int i = gtid; i < 32 * 576; i += gstride) {
        int k = i % 576;
        int o = i / 576;
        int t = k >> 6;
        int c = k & 63;
        float vv = 0.f;
        if (o < NOFF) {
            const float* wp = w_off + (o * CIN + c) * 9;
            vv = wp[t];
            if (t == 4) {
                float s = 0.f;
                #pragma unroll
                for (int tt = 0; tt < 9; ++tt) s += wp[tt];
                vv -= s;
            }
        }
        g_Aoffh[o * 576 + k] = __float2half_rn(vv);
    }

    // phase 2: store staged values
    #pragma unroll
    for (int k = 0; k < 8; ++k) {
        int i = threadIdx.x + k * 256;
        int c = i >> 5, w = i & 31;
        tile[c][w] = v[k];
    }
    __syncthreads();
    for (int i = threadIdx.x; i < 32 * 32; i += 256) {
        int w = i >> 5, cp = i & 31;
        __half2 hv = __float22half2_rn(make_float2(tile[2 * cp][w], tile[2 * cp + 1][w]));
        *(__half2*)&g_xh[((n * HH + h) * WW + w0 + w) * CIN + 2 * cp] = hv;
    }
}

// ============================================================
// Offset conv as single-pass fp16 tensor-core GEMM (proven form).
// ============================================================
#define XROW 72
#define XPIX 130
#define XPLANE (3 * XPIX * XROW)
#define AOP 584
#define OFF_SM_X 0
#define OFF_SM_A (XPLANE * 2)
#define OFF_SM_TOTAL (OFF_SM_A + 32 * AOP * 2)

__global__ void __launch_bounds__(512, 1) off_mma(const float* __restrict__ b_off) {
    extern __shared__ char sm[];
    __half* Xs = (__half*)(sm + OFF_SM_X);
    __half* Aw = (__half*)(sm + OFF_SM_A);

    int tid = threadIdx.x, wid = tid >> 5, lid = tid & 31;
    int g = lid >> 2, tq = lid & 3;
    int n = blockIdx.x >> 7, h = blockIdx.x & 127;
    int nw = wid * 8;

    for (int j = tid; j < 2304; j += 512) {
        int o = j / 72, seg = j % 72;
        *(uint4*)&Aw[o * AOP + seg * 8] = *(const uint4*)&g_Aoffh[o * 576 + seg * 8];
    }

    const __half* xb = g_xh + (size_t)n * (HH * WW * CIN);
    for (int e = tid; e < 3120; e += 512) {
        int r = e / 1040, rem = e % 1040;
        int p = rem >> 3, seg = rem & 7;
        int c0 = seg * 8;
        int row = h - 1 + r, w = p - 1;
        uint4 v = make_uint4(0, 0, 0, 0);
        if ((unsigned)row < (unsigned)HH && (unsigned)w < (unsigned)WW)
            v = *(const uint4*)&xb[(row * WW + w) * CIN + c0];
        *(uint4*)&Xs[r * (XPIX * XROW) + p * XROW + c0] = v;
    }
    __syncthreads();

    float acc[2][4];
    #pragma unroll
    for (int mi = 0; mi < 2; ++mi)
        #pragma unroll
        for (int r = 0; r < 4; ++r) acc[mi][r] = 0.f;

    #pragma unroll
    for (int t = 0; t < 9; ++t) {
        int ky = t / 3, kx = t % 3;
        #pragma unroll
        for (int ks = 0; ks < 4; ++ks) {
            int k0 = ks * 16;
            uint32_t a[2][4], b[2];
            #pragma unroll
            for (int mi = 0; mi < 2; ++mi) {
                const __half* ap = Aw + (mi * 16 + g) * AOP + t * 64 + k0 + 2 * tq;
                a[mi][0] = *(const uint32_t*)(ap);
                a[mi][1] = *(const uint32_t*)(ap + 8 * AOP);
                a[mi][2] = *(const uint32_t*)(ap + 8);
                a[mi][3] = *(const uint32_t*)(ap + 8 * AOP + 8);
            }
            const __half* bp = Xs + ky * (XPIX * XROW) + (nw + g + kx) * XROW + k0 + 2 * tq;
            b[0] = *(const uint32_t*)(bp);
            b[1] = *(const uint32_t*)(bp + 8);
            #pragma unroll
            for (int mi = 0; mi < 2; ++mi)
                mma_fp16(acc[mi], a[mi], b);
        }
    }

    int pix = nw + 2 * tq;
    #pragma unroll
    for (int mi = 0; mi < 2; ++mi) {
        int oa = mi * 16 + g;
        int ob = oa + 8;
        if (oa < NOFF) {
            float bb = __ldg(&b_off[oa]);
            *(float2*)&g_toff[((n * NOFF + oa) * HH + h) * WW + pix] =
                make_float2(acc[mi][0] + bb, acc[mi][1] + bb);
        }
        if (ob < NOFF) {
            float bb = __ldg(&b_off[ob]);
            *(float2*)&g_toff[((n * NOFF + ob) * HH + h) * WW + pix] =
                make_float2(acc[mi][2] + bb, acc[mi][3] + bb);
        }
    }
}

// ============================================================
// Fused deform-sample + fp16 GEMM.
// R14: params packed (ushort pixel idx + scalar half weights) ->
// smem 64.5KB/CTA -> ~34KB L1D reappears for the gather working set.
// ============================================================
#define PADK 72
#define NPIX 64
#define BTILE (NPIX * PADK)                  // 4608 halfs = 9216 B per buf
#define SM_PAR 0                             // sWhs 4608 + sOp 4608 = 9216 B
#define SM_A 9216                            // 2 x 18432 B
#define SM_B (9216 + 36864)                  // 2 x 9216 B
#define SM_TOTAL (SM_B + 18432)              // 64512 B

__global__ void __launch_bounds__(256, 3) fused_mma(float* __restrict__ out) {
    extern __shared__ char sm[];
    __half*   sWhs = (__half*)(sm + SM_PAR);               // [4][576] scalar weights
    uint16_t* sOp  = (uint16_t*)(sm + SM_PAR + 4 * 576 * 2); // [4][576] pixel indices
    __half* Bs = (__half*)(sm + SM_B);
    uint32_t smbA = smem_u32(sm + SM_A);
    uint32_t smbB = smem_u32(sm + SM_B);

    int tid = threadIdx.x, wid = tid >> 5, lid = tid & 31;
    int n  = blockIdx.x >> 8;
    int h  = (blockIdx.x >> 1) & 127;
    int w0 = (blockIdx.x & 1) * NPIX;
    int g = lid >> 2, tq = lid & 3;
    int m0 = (wid & 3) * 32;
    int n0 = (wid >> 2) * 32;

    uint32_t aBase = (uint32_t)(((m0 + (lid & 15)) * PADK + ((lid >> 4) << 3)) * 2);
    uint32_t bBase = (uint32_t)(((n0 + (lid & 7) + ((lid >> 4) << 3)) * PADK
                                 + (((lid >> 3) & 1) << 3)) * 2);

    // ---- bilinear params per (tap, pixel): 9*64 = 576 entries ----
    for (int i = tid; i < 9 * NPIX; i += 256) {
        int p = i >> 6, pix = i & 63;
        int w = w0 + pix;
        float dy = g_toff[((n * NOFF + 2 * p    ) * HH + h) * WW + w];
        float dx = g_toff[((n * NOFF + 2 * p + 1) * HH + h) * WW + w];
        float py = dy + (float)(h - 1 + p / 3);
        float px = dx + (float)(w - 1 + p % 3);
        float y0f = floorf(py), x0f = floorf(px);
        int y0 = (int)y0f, x0 = (int)x0f;
        float wy1 = py - y0f, wx1 = px - x0f;
        float wy0 = 1.f - wy1, wx0 = 1.f - wx1;
        bool vy0 = (unsigned)y0 < (unsigned)HH, vy1 = (unsigned)(y0 + 1) < (unsigned)HH;
        bool vx0 = (unsigned)x0 < (unsigned)WW, vx1 = (unsigned)(x0 + 1) < (unsigned)WW;
        int cy0 = min(max(y0, 0), HH - 1), cy1 = min(max(y0 + 1, 0), HH - 1);
        int cx0 = min(max(x0, 0), WW - 1), cx1 = min(max(x0 + 1, 0), WW - 1);
        float f00 = (vy0 && vx0) ? wy0 * wx0 : 0.f;
        float f01 = (vy0 && vx1) ? wy0 * wx1 : 0.f;
        float f10 = (vy1 && vx0) ? wy1 * wx0 : 0.f;
        float f11 = (vy1 && vx1) ? wy1 * wx1 : 0.f;
        sWhs[0 * 576 + i] = __float2half_rn(f00);
        sWhs[1 * 576 + i] = __float2half_rn(f01);
        sWhs[2 * 576 + i] = __float2half_rn(f10);
        sWhs[3 * 576 + i] = __float2half_rn(f11);
        sOp[0 * 576 + i] = (uint16_t)(cy0 * WW + cx0);
        sOp[1 * 576 + i] = (uint16_t)(cy0 * WW + cx1);
        sOp[2 * 576 + i] = (uint16_t)(cy1 * WW + cx0);
        sOp[3 * 576 + i] = (uint16_t)(cy1 * WW + cx1);
    }

    const __half* xb = g_xh + (size_t)n * (HH * WW * CIN);

    // ---- prologue: A(0) via cp.async into buf 0 ----
    #pragma unroll
    for (int m = 0; m < 4; ++m) {
        int j = tid + 256 * m;
        int row = j >> 3, seg = j & 7;
        cp_async16(smbA + (uint32_t)(row * 144 + seg * 16), g_Ah + j * 8);
    }
    cp_commit();
    __syncthreads();   // params visible

    // ---- prologue: B(0) gathered inline into buf 0 (tap 0) ----
    #pragma unroll
    for (int b = 0; b < 2; ++b) {
        int j = tid + 256 * b;
        int pix = j >> 3, c0 = (j & 7) * 8;
        int i = pix;   // tap 0
        uint4 q00 = *(const uint4*)&xb[(int)sOp[i] * CIN + c0];
        uint4 q01 = *(const uint4*)&xb[(int)sOp[576 + i] * CIN + c0];
        uint4 q10 = *(const uint4*)&xb[(int)sOp[2 * 576 + i] * CIN + c0];
        uint4 q11 = *(const uint4*)&xb[(int)sOp[3 * 576 + i] * CIN + c0];
        *(uint4*)&Bs[pix * PADK + c0] =
            comb8(q00, q01, q10, q11,
                  __half2half2(sWhs[i]), __half2half2(sWhs[576 + i]),
                  __half2half2(sWhs[2 * 576 + i]), __half2half2(sWhs[3 * 576 + i]));
    }

    float acc[2][4][4];
    #pragma unroll
    for (int mi = 0; mi < 2; ++mi)
        #pragma unroll
        for (int nj = 0; nj < 4; ++nj)
            #pragma unroll
            for (int r = 0; r < 4; ++r) acc[mi][nj][r] = 0.f;

    for (int t = 0; t < NTAP; ++t) {
        cp_wait0();
        __syncthreads();   // single barrier per tap: A(t), B(t) ready
        bool pf = (t < 9);
        bool center = (t + 1 == 9);

        uint32_t aBuf = smbA + (uint32_t)((t & 1) * 18432) + aBase;
        uint32_t bBuf = smbB + (uint32_t)((t & 1) * 9216) + bBase;
        __half* Bnx = Bs + ((t + 1) & 1) * BTILE;

        uint4 q[2][4];
        int pix0 = tid >> 3, c00 = (tid & 7) * 8;
        int pix1 = pix0 + 32;

        // issue BOTH gather batches for tap t+1 immediately (max distance)
        if (pf) {
            if (center) {
                q[0][0] = *(const uint4*)&xb[(h * WW + w0 + pix0) * CIN + c00];
                q[1][0] = *(const uint4*)&xb[(h * WW + w0 + pix1) * CIN + c00];
            } else {
                int i0 = (t + 1) * NPIX + pix0;
                int i1 = (t + 1) * NPIX + pix1;
                q[0][0] = *(const uint4*)&xb[(int)sOp[i0] * CIN + c00];
                q[0][1] = *(const uint4*)&xb[(int)sOp[576 + i0] * CIN + c00];
                q[0][2] = *(const uint4*)&xb[(int)sOp[2 * 576 + i0] * CIN + c00];
                q[0][3] = *(const uint4*)&xb[(int)sOp[3 * 576 + i0] * CIN + c00];
                q[1][0] = *(const uint4*)&xb[(int)sOp[i1] * CIN + c00];
                q[1][1] = *(const uint4*)&xb[(int)sOp[576 + i1] * CIN + c00];
                q[1][2] = *(const uint4*)&xb[(int)sOp[2 * 576 + i1] * CIN + c00];
                q[1][3] = *(const uint4*)&xb[(int)sOp[3 * 576 + i1] * CIN + c00];
            }
        }

        // prefetch A(t+1)
        if (pf) {
            const __half* asrc = g_Ah + (t + 1) * 8192;
            uint32_t adst = smbA + (uint32_t)(((t + 1) & 1) * 18432);
            #pragma unroll
            for (int m = 0; m < 4; ++m) {
                int j = tid + 256 * m;
                int row = j >> 3, seg = j & 7;
                cp_async16(adst + (uint32_t)(row * 144 + seg * 16), asrc + j * 8);
            }
            cp_commit();
        }

        auto mma_step = [&](int sub) {
            uint32_t kOff = (uint32_t)(sub * 32);
            uint32_t a[2][4], bfr[2][4];
            #pragma unroll
            for (int mi = 0; mi < 2; ++mi)
                ldsm_x4(aBuf + (uint32_t)(mi * 16 * PADK * 2) + kOff, a[mi]);
            #pragma unroll
            for (int njp = 0; njp < 2; ++njp)
                ldsm_x4(bBuf + (uint32_t)(njp * 16 * PADK * 2) + kOff, bfr[njp]);
            #pragma unroll
            for (int mi = 0; mi < 2; ++mi)
                #pragma unroll
                for (int nj = 0; nj < 4; ++nj)
                    mma_fp16(acc[mi][nj], a[mi], bfr[nj >> 1] + (nj & 1) * 2);
        };

        mma_step(0);
        mma_step(1);
        mma_step(2);
        if (pf) {
            uint4 r;
            if (center) {
                r = q[0][0];
            } else {
                int i = (t + 1) * NPIX + pix0;
                r = comb8(q[0][0], q[0][1], q[0][2], q[0][3],
                          __half2half2(sWhs[i]), __half2half2(sWhs[576 + i]),
                          __half2half2(sWhs[2 * 576 + i]), __half2half2(sWhs[3 * 576 + i]));
            }
            *(uint4*)&Bnx[pix0 * PADK + c00] = r;
        }
        mma_step(3);
        if (pf) {
            uint4 r;
            if (center) {
                r = q[1][0];
            } else {
                int i = (t + 1) * NPIX + pix1;
                r = comb8(q[1][0], q[1][1], q[1][2], q[1][3],
                          __half2half2(sWhs[i]), __half2half2(sWhs[576 + i]),
                          __half2half2(sWhs[2 * 576 + i]), __half2half2(sWhs[3 * 576 + i]));
            }
            *(uint4*)&Bnx[pix1 * PADK + c00] = r;
        }
    }

    // ---- epilogue: direct stores, NCHW ----
    #pragma unroll
    for (int mi = 0; mi < 2; ++mi) {
        #pragma unroll
        for (int nj = 0; nj < 4; ++nj) {
            int o = m0 + mi * 16 + g;
            int pix = w0 + n0 + nj * 8 + 2 * tq;
            float* op = out + (((size_t)n * COUT + o) * HH + h) * WW + pix;
            *(float2*)op = make_float2(acc[mi][nj][0], acc[mi][nj][1]);
            *(float2*)(op + 8 * HH * WW) = make_float2(acc[mi][nj][2], acc[mi][nj][3]);
        }
    }
}

// ============================================================
extern "C" void kernel_launch(void* const* d_in, const int* in_sizes, int n_in,
                              void* d_out, int out_size) {
    const float* x        = (const float*)d_in[0];
    const float* w_off    = (const float*)d_in[1];
    const float* b_off    = (const float*)d_in[2];
    const float* w_deform = (const float*)d_in[3];
    const float* w_pw     = (const float*)d_in[4];
    float* out = (float*)d_out;

    cudaFuncSetAttribute(off_mma,
                         cudaFuncAttributeMaxDynamicSharedMemorySize, OFF_SM_TOTAL);
    cudaFuncSetAttribute(fused_mma,
                         cudaFuncAttributeMaxDynamicSharedMemorySize, SM_TOTAL);

    transpose_prep_kernel<<<2048, 256>>>(x, w_off, w_deform, w_pw);
    off_mma<<<NB * HH, 512, OFF_SM_TOTAL>>>(b_off);
    fused_mma<<<NB * HH * 2, 256, SM_TOTAL>>>(out);
}